// round 3
// baseline (speedup 1.0000x reference)
#include <cuda_runtime.h>
#include <cuda_fp16.h>
#include <math.h>
#include <float.h>

#define NN   20000
#define EE   340000
#define DD   128
#define CC1  256
#define NB   157      // ceil(NN/128)

// ---- output layout (element offsets into float* d_out) ----
#define OFF_S1  0
#define OFF_S2  (NN*CC1)
#define OFF_A1  (OFF_S2 + 256*32)
#define OFF_E3  (OFF_A1 + 32)
#define OFF_X1  (OFF_E3 + NN*DD)
#define OFF_X2  (OFF_X1 + 256*128)
#define OFF_E0  (OFF_X2 + 32*128)

// ---- scratch ----
__device__ __align__(16) __half g_zfh[NN*DD];
__device__ __align__(16) __half g_xh[NN*DD];
__device__ __align__(16) __half g_m2h[NN*DD];
__device__ float g_m2[NN*DD];
__device__ float g_magg[NN*DD];
__device__ float g_asrc[NN];
__device__ float g_adst[NN];
__device__ int   g_deg[NN];
__device__ int   g_off[NN+1];
__device__ int   g_cur[NN];
__device__ int   g_csrc[EE];
__device__ int   g_bsum[NB];
__device__ int   g_boff[NB];
__device__ float g_Wcomb[DD*CC1];        // 128x256
__device__ float g_bcomb[CC1];
__device__ float g_us[DD];
__device__ float g_ud[DD];
__device__ float g_cs[2];
__device__ float g_Tbuf[CC1*DD + CC1];   // [0,32768): T = s1^T@m2 ; [32768,+256): colsum(s1)

// ---- half helpers ----
__device__ __forceinline__ float4 ld_h4(const __half* p) {
    uint2 u = *(const uint2*)p;
    __half2 a = *reinterpret_cast<const __half2*>(&u.x);
    __half2 b = *reinterpret_cast<const __half2*>(&u.y);
    float2 fa = __half22float2(a), fb = __half22float2(b);
    return make_float4(fa.x, fa.y, fb.x, fb.y);
}
__device__ __forceinline__ void st_h4(__half* p, float4 v) {
    __half2 a = __floats2half2_rn(v.x, v.y);
    __half2 b = __floats2half2_rn(v.z, v.w);
    uint2 u;
    u.x = *reinterpret_cast<unsigned*>(&a);
    u.y = *reinterpret_cast<unsigned*>(&b);
    *(uint2*)p = u;
}

// ============================ graph build ============================
__global__ void k_count(const int* __restrict__ dst) {
    int e = blockIdx.x*blockDim.x + threadIdx.x;
    if (e < EE) atomicAdd(&g_deg[dst[e]], 1);
}

__global__ void k_scan1() {   // NB blocks x 128
    __shared__ int sh[128];
    int t = threadIdx.x;
    int i = blockIdx.x*128 + t;
    sh[t] = (i < NN) ? g_deg[i] : 0;
    __syncthreads();
    #pragma unroll
    for (int st = 64; st > 0; st >>= 1) {
        if (t < st) sh[t] += sh[t+st];
        __syncthreads();
    }
    if (t == 0) g_bsum[blockIdx.x] = sh[0];
}

__global__ void k_scan2() {   // 1 block x 256
    __shared__ int sh[256];
    int t = threadIdx.x;
    sh[t] = (t < NB) ? g_bsum[t] : 0;
    __syncthreads();
    #pragma unroll
    for (int off = 1; off < 256; off <<= 1) {
        int v = (t >= off) ? sh[t-off] : 0;
        __syncthreads();
        sh[t] += v;
        __syncthreads();
    }
    if (t < NB) g_boff[t] = (t == 0) ? 0 : sh[t-1];
}

__global__ void k_scan3() {   // NB blocks x 128
    __shared__ int sh[128];
    int t = threadIdx.x;
    int i = blockIdx.x*128 + t;
    int d = (i < NN) ? g_deg[i] : 0;
    sh[t] = d;
    __syncthreads();
    #pragma unroll
    for (int off = 1; off < 128; off <<= 1) {
        int v = (t >= off) ? sh[t-off] : 0;
        __syncthreads();
        sh[t] += v;
        __syncthreads();
    }
    int excl = g_boff[blockIdx.x] + sh[t] - d;
    if (i < NN) { g_off[i] = excl; g_cur[i] = excl; }
    if (i == 0) g_off[NN] = EE;
}

__global__ void k_fill(const int* __restrict__ src, const int* __restrict__ dst) {
    int e = blockIdx.x*blockDim.x + threadIdx.x;
    if (e < EE) {
        int p = atomicAdd(&g_cur[dst[e]], 1);
        g_csrc[p] = src[e];
    }
}

// ============================ weight folding ============================
__global__ __launch_bounds__(256) void k_fold(
    const float* __restrict__ We1, const float* __restrict__ be1,
    const float* __restrict__ Wa1, const float* __restrict__ ba1,
    const float* __restrict__ attW)
{
    int b = blockIdx.x, t = threadIdx.x;
    if (b < 128) {
        __shared__ float sWe[128];
        if (t < 128) sWe[t] = We1[b*128 + t];
        __syncthreads();
        float acc = 0.f;
        #pragma unroll 8
        for (int k = 0; k < 128; k++) acc = fmaf(sWe[k], Wa1[k*256 + t], acc);
        g_Wcomb[b*256 + t] = acc;
    } else {
        __shared__ float ts[128], td[128], bc[256];
        if (t < 128) {
            float s1v = 0.f, s2v = 0.f;
            for (int c = 0; c < 256; c++) {
                float w = Wa1[t*256 + c];
                s1v = fmaf(w, attW[c], s1v);
                s2v = fmaf(w, attW[256 + c], s2v);
            }
            ts[t] = s1v; td[t] = s2v;
        }
        {
            float s = 0.f;
            for (int e = 0; e < 128; e++) s = fmaf(be1[e], Wa1[e*256 + t], s);
            bc[t] = s + ba1[t];
            g_bcomb[t] = bc[t];
        }
        __syncthreads();
        if (t < 128) {
            float u1 = 0.f, u2 = 0.f;
            for (int e = 0; e < 128; e++) {
                float w = We1[t*128 + e];
                u1 = fmaf(w, ts[e], u1);
                u2 = fmaf(w, td[e], u2);
            }
            g_us[t] = u1; g_ud[t] = u2;
        }
        if (t == 0) {
            float c1v = 0.f, c2v = 0.f;
            for (int c = 0; c < 256; c++) {
                c1v = fmaf(bc[c], attW[c], c1v);
                c2v = fmaf(bc[c], attW[256 + c], c2v);
            }
            g_cs[0] = c1v; g_cs[1] = c2v;
        }
    }
}

// ============================ GEMM 128x128 -> fp16 out ============================
// zfh = half(feature @ Wf + bf)
__global__ __launch_bounds__(256) void k_gemm_zf(
    const float* __restrict__ A, const float* __restrict__ B,
    const float* __restrict__ bias, __half* __restrict__ Ch)
{
    __shared__ float As[8][128];
    __shared__ float Bs[8][128];
    int tid = threadIdx.x;
    int row0 = blockIdx.x*128;
    int tr = tid/16, tc = tid%16;
    float acc[8][8];
    #pragma unroll
    for (int i = 0; i < 8; i++)
        #pragma unroll
        for (int jj = 0; jj < 8; jj++) acc[i][jj] = 0.0f;

    int aRow = tid/2, aCol = (tid%2)*4;
    int bRow = tid/32, bCol = (tid%32)*4;

    for (int k0 = 0; k0 < 128; k0 += 8) {
        float4 av = make_float4(0.f,0.f,0.f,0.f);
        int gr = row0 + aRow;
        if (gr < NN) av = *(const float4*)(A + (size_t)gr*128 + k0 + aCol);
        As[aCol+0][aRow] = av.x; As[aCol+1][aRow] = av.y;
        As[aCol+2][aRow] = av.z; As[aCol+3][aRow] = av.w;
        *(float4*)&Bs[bRow][bCol] = *(const float4*)(B + (size_t)(k0+bRow)*128 + bCol);
        __syncthreads();
        #pragma unroll
        for (int kk = 0; kk < 8; kk++) {
            float ra[8], rb[8];
            *(float4*)(ra)   = *(float4*)&As[kk][tr*8];
            *(float4*)(ra+4) = *(float4*)&As[kk][tr*8+4];
            *(float4*)(rb)   = *(float4*)&Bs[kk][tc*8];
            *(float4*)(rb+4) = *(float4*)&Bs[kk][tc*8+4];
            #pragma unroll
            for (int i = 0; i < 8; i++)
                #pragma unroll
                for (int jj = 0; jj < 8; jj++)
                    acc[i][jj] = fmaf(ra[i], rb[jj], acc[i][jj]);
        }
        __syncthreads();
    }
    float bb[8];
    #pragma unroll
    for (int jj = 0; jj < 8; jj++) bb[jj] = bias[tc*8 + jj];
    #pragma unroll
    for (int i = 0; i < 8; i++) {
        int gr = row0 + tr*8 + i;
        if (gr >= NN) continue;
        float4 lo = make_float4(acc[i][0]+bb[0], acc[i][1]+bb[1], acc[i][2]+bb[2], acc[i][3]+bb[3]);
        float4 hi = make_float4(acc[i][4]+bb[4], acc[i][5]+bb[5], acc[i][6]+bb[6], acc[i][7]+bb[7]);
        st_h4(Ch + (size_t)gr*DD + tc*8,     lo);
        st_h4(Ch + (size_t)gr*DD + tc*8 + 4, hi);
    }
}

// ============================ segment mean (warp/node, fp16 gather) ============================
// NORM: L2-normalize row; DOTS: emit a_src/a_dst via folded attention vectors.
// outf: fp32 row output (may be null), outh: fp16 row output (may be null)
template<bool NORM, bool DOTS>
__global__ __launch_bounds__(256) void k_segmean(
    const __half* __restrict__ zin, float* __restrict__ outf,
    __half* __restrict__ outh)
{
    int node = blockIdx.x*8 + (threadIdx.x >> 5);
    if (node >= NN) return;
    int lane = threadIdx.x & 31;
    int e0 = g_off[node], e1 = g_off[node+1];
    float4 acc = make_float4(0.f,0.f,0.f,0.f);
    int j = e0;
    for (; j + 4 <= e1; j += 4) {
        int s0 = g_csrc[j],   s1i = g_csrc[j+1];
        int s2 = g_csrc[j+2], s3i = g_csrc[j+3];
        float4 v0 = ld_h4(zin + (size_t)s0*DD  + lane*4);
        float4 v1 = ld_h4(zin + (size_t)s1i*DD + lane*4);
        float4 v2 = ld_h4(zin + (size_t)s2*DD  + lane*4);
        float4 v3 = ld_h4(zin + (size_t)s3i*DD + lane*4);
        acc.x += (v0.x+v1.x) + (v2.x+v3.x);
        acc.y += (v0.y+v1.y) + (v2.y+v3.y);
        acc.z += (v0.z+v1.z) + (v2.z+v3.z);
        acc.w += (v0.w+v1.w) + (v2.w+v3.w);
    }
    for (; j < e1; j++) {
        int s0 = g_csrc[j];
        float4 v0 = ld_h4(zin + (size_t)s0*DD + lane*4);
        acc.x += v0.x; acc.y += v0.y; acc.z += v0.z; acc.w += v0.w;
    }
    float inv = 1.0f / (float)(e1 - e0);
    acc.x *= inv; acc.y *= inv; acc.z *= inv; acc.w *= inv;
    if (NORM) {
        float ss = acc.x*acc.x + acc.y*acc.y + acc.z*acc.z + acc.w*acc.w;
        #pragma unroll
        for (int o = 16; o > 0; o >>= 1) ss += __shfl_xor_sync(0xffffffffu, ss, o);
        float r = 1.0f / fmaxf(sqrtf(ss), 1e-12f);
        acc.x *= r; acc.y *= r; acc.z *= r; acc.w *= r;
    }
    if (outf) *(float4*)(outf + (size_t)node*DD + lane*4) = acc;
    if (outh) st_h4(outh + (size_t)node*DD + lane*4, acc);
    if (DOTS) {
        float4 us4 = *(const float4*)(g_us + lane*4);
        float4 ud4 = *(const float4*)(g_ud + lane*4);
        float as = acc.x*us4.x + acc.y*us4.y + acc.z*us4.z + acc.w*us4.w;
        float ad = acc.x*ud4.x + acc.y*ud4.y + acc.z*ud4.z + acc.w*ud4.w;
        #pragma unroll
        for (int o = 16; o > 0; o >>= 1) {
            as += __shfl_xor_sync(0xffffffffu, as, o);
            ad += __shfl_xor_sync(0xffffffffu, ad, o);
        }
        if (lane == 0) { g_asrc[node] = as + g_cs[0]; g_adst[node] = ad + g_cs[1]; }
    }
}

// ============================ GAT aggregation (warp/node, fp16 gather) ============================
__global__ __launch_bounds__(256) void k_gatagg(const float* __restrict__ attb)
{
    int node = blockIdx.x*8 + (threadIdx.x >> 5);
    if (node >= NN) return;
    int lane = threadIdx.x & 31;
    int e0 = g_off[node], e1 = g_off[node+1];
    float adb = g_adst[node] + attb[0];

    float mx = -FLT_MAX;
    for (int j = e0 + lane; j < e1; j += 32) {
        float e = g_asrc[g_csrc[j]] + adb;
        e = (e > 0.f) ? e : 0.01f*e;
        mx = fmaxf(mx, e);
    }
    #pragma unroll
    for (int o = 16; o > 0; o >>= 1) mx = fmaxf(mx, __shfl_xor_sync(0xffffffffu, mx, o));

    float4 acc = make_float4(0.f,0.f,0.f,0.f);
    float denom = 0.f;
    for (int base = e0; base < e1; base += 32) {
        int j = base + lane;
        int s = 0; float a = 0.f;
        if (j < e1) {
            s = g_csrc[j];
            float e = g_asrc[s] + adb;
            e = (e > 0.f) ? e : 0.01f*e;
            a = __expf(e - mx);
            denom += a;
        }
        int cnt = min(32, e1 - base);
        #pragma unroll 4
        for (int t = 0; t < cnt; t++) {
            float ab = __shfl_sync(0xffffffffu, a, t);
            int   sb = __shfl_sync(0xffffffffu, s, t);
            float4 v = ld_h4(g_m2h + (size_t)sb*DD + lane*4);
            acc.x = fmaf(ab, v.x, acc.x); acc.y = fmaf(ab, v.y, acc.y);
            acc.z = fmaf(ab, v.z, acc.z); acc.w = fmaf(ab, v.w, acc.w);
        }
    }
    #pragma unroll
    for (int o = 16; o > 0; o >>= 1) denom += __shfl_xor_sync(0xffffffffu, denom, o);
    float r = 1.0f / denom;
    acc.x *= r; acc.y *= r; acc.z *= r; acc.w *= r;
    *(float4*)(g_magg + (size_t)node*DD + lane*4) = acc;
}

// ============================ GEMM 64x256 + row-softmax -> s1 ============================
__global__ __launch_bounds__(256) void k_gemm_s1(float* __restrict__ s1out)
{
    __shared__ float As[8][64];
    __shared__ float Bs[8][256];
    __shared__ float red[64][16];
    int tid = threadIdx.x;
    int row0 = blockIdx.x*64;
    int tr = tid/16, tc = tid%16;
    float acc[4][16];
    #pragma unroll
    for (int i = 0; i < 4; i++)
        #pragma unroll
        for (int jj = 0; jj < 16; jj++) acc[i][jj] = 0.f;

    int aRow = tid/4, aCol = (tid%4)*2;
    int bRow = tid/32, bCol = (tid%32)*8;

    for (int k0 = 0; k0 < 128; k0 += 8) {
        float2 av = make_float2(0.f,0.f);
        int gr = row0 + aRow;
        if (gr < NN) av = *(const float2*)(g_magg + (size_t)gr*128 + k0 + aCol);
        As[aCol+0][aRow] = av.x; As[aCol+1][aRow] = av.y;
        *(float4*)&Bs[bRow][bCol]   = *(const float4*)(g_Wcomb + (size_t)(k0+bRow)*256 + bCol);
        *(float4*)&Bs[bRow][bCol+4] = *(const float4*)(g_Wcomb + (size_t)(k0+bRow)*256 + bCol + 4);
        __syncthreads();
        #pragma unroll
        for (int kk = 0; kk < 8; kk++) {
            float ra[4], rb[16];
            *(float4*)(ra)    = *(float4*)&As[kk][tr*4];
            *(float4*)(rb)    = *(float4*)&Bs[kk][tc*16];
            *(float4*)(rb+4)  = *(float4*)&Bs[kk][tc*16+4];
            *(float4*)(rb+8)  = *(float4*)&Bs[kk][tc*16+8];
            *(float4*)(rb+12) = *(float4*)&Bs[kk][tc*16+12];
            #pragma unroll
            for (int i = 0; i < 4; i++)
                #pragma unroll
                for (int jj = 0; jj < 16; jj++)
                    acc[i][jj] = fmaf(ra[i], rb[jj], acc[i][jj]);
        }
        __syncthreads();
    }
    float bb[16];
    #pragma unroll
    for (int jj = 0; jj < 16; jj++) bb[jj] = g_bcomb[tc*16 + jj];
    #pragma unroll
    for (int i = 0; i < 4; i++) {
        float lm = -FLT_MAX;
        #pragma unroll
        for (int jj = 0; jj < 16; jj++) {
            acc[i][jj] += bb[jj];
            lm = fmaxf(lm, acc[i][jj]);
        }
        red[tr*4+i][tc] = lm;
    }
    __syncthreads();
    float rowmax[4];
    #pragma unroll
    for (int i = 0; i < 4; i++) {
        float m = -FLT_MAX;
        #pragma unroll
        for (int t = 0; t < 16; t++) m = fmaxf(m, red[tr*4+i][t]);
        rowmax[i] = m;
    }
    __syncthreads();
    #pragma unroll
    for (int i = 0; i < 4; i++) {
        float ls = 0.f;
        #pragma unroll
        for (int jj = 0; jj < 16; jj++) {
            acc[i][jj] = __expf(acc[i][jj] - rowmax[i]);
            ls += acc[i][jj];
        }
        red[tr*4+i][tc] = ls;
    }
    __syncthreads();
    #pragma unroll
    for (int i = 0; i < 4; i++) {
        int gr = row0 + tr*4 + i;
        if (gr >= NN) continue;
        float s = 0.f;
        #pragma unroll
        for (int t = 0; t < 16; t++) s += red[tr*4+i][t];
        float rinv = 1.0f / s;
        #pragma unroll
        for (int jj = 0; jj < 16; jj += 4) {
            float4 o;
            o.x = acc[i][jj]*rinv;   o.y = acc[i][jj+1]*rinv;
            o.z = acc[i][jj+2]*rinv; o.w = acc[i][jj+3]*rinv;
            *(float4*)(s1out + (size_t)gr*256 + tc*16 + jj) = o;
        }
    }
}

// ============================ T = s1^T @ m2 + colsum(s1) ============================
#define SPLITS 80
__global__ __launch_bounds__(256) void k_at_b(const float* __restrict__ S)
{
    __shared__ float sS[16][64];
    __shared__ float sZ[16][128];
    int chunk = blockIdx.x;
    int k_begin = (int)((long long)NN * chunk / SPLITS);
    int k_end   = (int)((long long)NN * (chunk+1) / SPLITS);
    int m0 = blockIdx.y * 64;
    int tid = threadIdx.x;
    int tr = tid/16, tc = tid%16;
    float acc[4][8];
    #pragma unroll
    for (int i = 0; i < 4; i++)
        #pragma unroll
        for (int jj = 0; jj < 8; jj++) acc[i][jj] = 0.f;
    float colacc = 0.f;

    for (int k0 = k_begin; k0 < k_end; k0 += 16) {
        int kc = min(16, k_end - k0);
        {
            int r = tid/16, c4 = (tid%16)*4;
            float4 v = make_float4(0.f,0.f,0.f,0.f);
            if (r < kc) v = *(const float4*)(S + (size_t)(k0+r)*CC1 + m0 + c4);
            *(float4*)&sS[r][c4] = v;
        }
        #pragma unroll
        for (int half = 0; half < 2; half++) {
            int r = tid/32 + half*8, c4 = (tid%32)*4;
            float4 v = make_float4(0.f,0.f,0.f,0.f);
            if (r < kc) v = *(const float4*)(g_m2 + (size_t)(k0+r)*DD + c4);
            *(float4*)&sZ[r][c4] = v;
        }
        __syncthreads();
        if (tid < 64) {
            #pragma unroll
            for (int r = 0; r < 16; r++) colacc += sS[r][tid];
        }
        #pragma unroll
        for (int kk = 0; kk < 16; kk++) {
            float ra[4], rb[8];
            *(float4*)(ra)   = *(float4*)&sS[kk][tr*4];
            *(float4*)(rb)   = *(float4*)&sZ[kk][tc*8];
            *(float4*)(rb+4) = *(float4*)&sZ[kk][tc*8+4];
            #pragma unroll
            for (int i = 0; i < 4; i++)
                #pragma unroll
                for (int jj = 0; jj < 8; jj++)
                    acc[i][jj] = fmaf(ra[i], rb[jj], acc[i][jj]);
        }
        __syncthreads();
    }
    #pragma unroll
    for (int i = 0; i < 4; i++)
        #pragma unroll
        for (int jj = 0; jj < 8; jj++)
            atomicAdd(&g_Tbuf[(m0 + tr*4 + i)*DD + tc*8 + jj], acc[i][jj]);
    if (tid < 64) atomicAdd(&g_Tbuf[CC1*DD + m0 + tid], colacc);
}

// ============================ x1 = T@We1 + colsum (x) be1 ============================
__global__ __launch_bounds__(256) void k_x1(
    const float* __restrict__ We1, const float* __restrict__ be1,
    float* __restrict__ out)
{
    int elem = blockIdx.x*256 + threadIdx.x;
    int k = elem >> 7, d = elem & 127;
    float s = 0.f;
    #pragma unroll 8
    for (int e = 0; e < 128; e++) s = fmaf(g_Tbuf[k*128 + e], We1[e*128 + d], s);
    out[OFF_X1 + elem] = s + g_Tbuf[CC1*DD + k]*be1[d];
}

// ============================ analytic coarse tail ============================
__global__ __launch_bounds__(256) void k_tail(
    const float* __restrict__ We1, const float* __restrict__ be1,
    const float* __restrict__ We2, const float* __restrict__ be2,
    const float* __restrict__ Wa2, const float* __restrict__ ba2,
    float* __restrict__ out)
{
    __shared__ float sumT[128];
    __shared__ float meanx1[128];
    __shared__ float meanvec[128];
    __shared__ float s2row[32];
    __shared__ float sc[256];
    int t = threadIdx.x;

    if (t < 128) {
        float s = 0.f;
        for (int k = 0; k < 256; k++) s += g_Tbuf[k*128 + t];
        sumT[t] = s;
    }
    sc[t] = g_Tbuf[CC1*DD + t];
    __syncthreads();
    #pragma unroll
    for (int st = 128; st > 0; st >>= 1) {
        if (t < st) sc[t] += sc[t+st];
        __syncthreads();
    }
    float sumcol = sc[0];
    if (t < 128) {
        float s = 0.f;
        for (int e = 0; e < 128; e++) s = fmaf(sumT[e], We1[e*128 + t], s);
        meanx1[t] = (s + sumcol*be1[t]) * (1.0f/256.0f);
    }
    __syncthreads();
    if (t < 128) {
        float s = 0.f;
        for (int e = 0; e < 128; e++) s = fmaf(meanx1[e], We2[e*128 + t], s);
        meanvec[t] = s + be2[t];
    }
    __syncthreads();
    if (t < 32) {
        float s = 0.f;
        for (int d = 0; d < 128; d++) s = fmaf(meanvec[d], Wa2[d*32 + t], s);
        float v = s + ba2[t];
        float mx = v;
        #pragma unroll
        for (int o = 16; o > 0; o >>= 1) mx = fmaxf(mx, __shfl_xor_sync(0xffffffffu, mx, o));
        float ex = __expf(v - mx);
        float sm = ex;
        #pragma unroll
        for (int o = 16; o > 0; o >>= 1) sm += __shfl_xor_sync(0xffffffffu, sm, o);
        s2row[t] = ex / sm;
    }
    __syncthreads();
    for (int i = t; i < 256*32; i += 256) out[OFF_S2 + i] = s2row[i & 31];
    if (t < 32) out[OFF_A1 + t] = 1.0f;
    for (int i = t; i < 32*128; i += 256)
        out[OFF_X2 + i] = 256.0f * s2row[i >> 7] * meanvec[i & 127];
    if (t == 0) {
        float s = 0.f;
        for (int d = 0; d < 128; d++) s += meanvec[d];
        out[OFF_E0] = s * (1.0f/16.0f);
    }
}

// ============================ launch ============================
extern "C" void kernel_launch(void* const* d_in, const int* in_sizes, int n_in,
                              void* d_out, int out_size)
{
    const float* feature = (const float*)d_in[0];
    const int*   eidx    = (const int*)d_in[1];
    const int*   src     = eidx;
    const int*   dst     = eidx + EE;
    const float* Wf   = (const float*)d_in[2];
    const float* bf   = (const float*)d_in[3];
    const float* We1  = (const float*)d_in[4];
    const float* be1  = (const float*)d_in[5];
    const float* Wa1  = (const float*)d_in[6];
    const float* ba1  = (const float*)d_in[7];
    const float* attW1 = (const float*)d_in[8];
    const float* attb1 = (const float*)d_in[9];
    const float* We2  = (const float*)d_in[10];
    const float* be2  = (const float*)d_in[11];
    const float* Wa2  = (const float*)d_in[12];
    const float* ba2  = (const float*)d_in[13];
    float* out = (float*)d_out;

    void *deg_p, *tbuf_p;
    __half *zfh_p, *xh_p;
    cudaGetSymbolAddress(&deg_p,  g_deg);
    cudaGetSymbolAddress(&tbuf_p, g_Tbuf);
    cudaGetSymbolAddress((void**)&zfh_p, g_zfh);
    cudaGetSymbolAddress((void**)&xh_p,  g_xh);
    __half* m2h_p; float* m2_p;
    cudaGetSymbolAddress((void**)&m2h_p, g_m2h);
    cudaGetSymbolAddress((void**)&m2_p,  g_m2);

    // zero accumulators / degree counters
    cudaMemsetAsync(deg_p,  0, NN*sizeof(int));
    cudaMemsetAsync(tbuf_p, 0, (CC1*DD + CC1)*sizeof(float));

    // graph build (+ independent weight folding and feature GEMM interleaved)
    k_count<<<(EE + 255)/256, 256>>>(dst);
    k_fold<<<129, 256>>>(We1, be1, Wa1, ba1, attW1);
    k_gemm_zf<<<(NN+127)/128, 256>>>(feature, Wf, bf, zfh_p);
    k_scan1<<<NB, 128>>>();
    k_scan2<<<1, 256>>>();
    k_scan3<<<NB, 128>>>();
    k_fill<<<(EE + 255)/256, 256>>>(src, dst);

    // x = normalize(segmean(zf)); embed3 = x (fp32 out), fp16 copy for next gather
    k_segmean<true,false><<<(NN+7)/8, 256>>>(zfh_p, out + OFF_E3, xh_p);
    // m2 = segmean(x) + fused a_src/a_dst; fp32 (for at_b) + fp16 (for gatagg)
    k_segmean<false,true><<<(NN+7)/8, 256>>>(xh_p, m2_p, m2h_p);
    // GAT aggregation (fp16 gathers)
    k_gatagg<<<(NN+7)/8, 256>>>(attb1);
    // s1 = softmax(magg@W_comb + b_comb)
    k_gemm_s1<<<(NN+63)/64, 256>>>(out + OFF_S1);
    // T = s1^T @ m2, colsum(s1)
    k_at_b<<<dim3(SPLITS, 4), 256>>>(out + OFF_S1);
    // x1 = T@We1 + colsum (x) be1
    k_x1<<<128, 256>>>(We1, be1, out);
    // analytic coarse level
    k_tail<<<1, 256>>>(We1, be1, We2, be2, Wa2, ba2, out);
}

// round 4
// speedup vs baseline: 1.4828x; 1.4828x over previous
#include <cuda_runtime.h>
#include <math.h>
#include <float.h>

#define NN   20000
#define EE   340000
#define DD   128
#define CC1  256
#define NB   157      // ceil(NN/128)

// ---- output layout (element offsets into float* d_out) ----
#define OFF_S1  0
#define OFF_S2  (NN*CC1)
#define OFF_A1  (OFF_S2 + 256*32)
#define OFF_E3  (OFF_A1 + 32)
#define OFF_X1  (OFF_E3 + NN*DD)
#define OFF_X2  (OFF_X1 + 256*128)
#define OFF_E0  (OFF_X2 + 32*128)

// ---- scratch ----
__device__ float g_mf[NN*DD];
__device__ float g_x[NN*DD];
__device__ float g_m2[NN*DD];
__device__ float g_magg[NN*DD];
__device__ float g_asrc[NN];
__device__ float g_adst[NN];
__device__ int   g_deg[NN];
__device__ int   g_off[NN+1];
__device__ int   g_cur[NN];
__device__ int   g_csrc[EE];
__device__ int   g_bsum[NB];
__device__ int   g_boff[NB];
__device__ float g_Wcomb[DD*CC1];        // 128x256
__device__ float g_bcomb[CC1];
__device__ float g_us[DD];
__device__ float g_ud[DD];
__device__ float g_cs[2];
__device__ float g_Tbuf[CC1*DD + CC1];   // T = s1^T@m2 ; then colsum(s1)

// ============================ graph build ============================
__global__ void k_count(const int* __restrict__ dst) {
    int e = blockIdx.x*blockDim.x + threadIdx.x;
    if (e < EE) atomicAdd(&g_deg[dst[e]], 1);
}

__global__ void k_scan1() {   // NB blocks x 128: per-block sums
    __shared__ int sh[128];
    int t = threadIdx.x;
    int i = blockIdx.x*128 + t;
    sh[t] = (i < NN) ? g_deg[i] : 0;
    __syncthreads();
    #pragma unroll
    for (int st = 64; st > 0; st >>= 1) {
        if (t < st) sh[t] += sh[t+st];
        __syncthreads();
    }
    if (t == 0) g_bsum[blockIdx.x] = sh[0];
}

__global__ void k_scan2() {   // 1 block x 256: scan of block sums
    __shared__ int sh[256];
    int t = threadIdx.x;
    sh[t] = (t < NB) ? g_bsum[t] : 0;
    __syncthreads();
    #pragma unroll
    for (int off = 1; off < 256; off <<= 1) {
        int v = (t >= off) ? sh[t-off] : 0;
        __syncthreads();
        sh[t] += v;
        __syncthreads();
    }
    if (t < NB) g_boff[t] = (t == 0) ? 0 : sh[t-1];
}

__global__ void k_scan3() {   // NB blocks x 128: local scan + base offset
    __shared__ int sh[128];
    int t = threadIdx.x;
    int i = blockIdx.x*128 + t;
    int d = (i < NN) ? g_deg[i] : 0;
    sh[t] = d;
    __syncthreads();
    #pragma unroll
    for (int off = 1; off < 128; off <<= 1) {
        int v = (t >= off) ? sh[t-off] : 0;
        __syncthreads();
        sh[t] += v;
        __syncthreads();
    }
    int excl = g_boff[blockIdx.x] + sh[t] - d;
    if (i < NN) { g_off[i] = excl; g_cur[i] = excl; }
    if (i == 0) g_off[NN] = EE;
}

__global__ void k_fill(const int* __restrict__ src, const int* __restrict__ dst) {
    int e = blockIdx.x*blockDim.x + threadIdx.x;
    if (e < EE) {
        int p = atomicAdd(&g_cur[dst[e]], 1);
        g_csrc[p] = src[e];
    }
}

// ============================ weight folding ============================
__global__ __launch_bounds__(256) void k_fold(
    const float* __restrict__ We1, const float* __restrict__ be1,
    const float* __restrict__ Wa1, const float* __restrict__ ba1,
    const float* __restrict__ attW)
{
    int b = blockIdx.x, t = threadIdx.x;
    if (b < 128) {
        __shared__ float sWe[128];
        if (t < 128) sWe[t] = We1[b*128 + t];
        __syncthreads();
        float acc = 0.f;
        #pragma unroll 8
        for (int k = 0; k < 128; k++) acc = fmaf(sWe[k], Wa1[k*256 + t], acc);
        g_Wcomb[b*256 + t] = acc;
    } else {
        __shared__ float ts[128], td[128], bc[256];
        if (t < 128) {
            float s1v = 0.f, s2v = 0.f;
            for (int c = 0; c < 256; c++) {
                float w = Wa1[t*256 + c];
                s1v = fmaf(w, attW[c], s1v);
                s2v = fmaf(w, attW[256 + c], s2v);
            }
            ts[t] = s1v; td[t] = s2v;
        }
        {
            float s = 0.f;
            for (int e = 0; e < 128; e++) s = fmaf(be1[e], Wa1[e*256 + t], s);
            bc[t] = s + ba1[t];
            g_bcomb[t] = bc[t];
        }
        __syncthreads();
        if (t < 128) {
            float u1 = 0.f, u2 = 0.f;
            for (int e = 0; e < 128; e++) {
                float w = We1[t*128 + e];
                u1 = fmaf(w, ts[e], u1);
                u2 = fmaf(w, td[e], u2);
            }
            g_us[t] = u1; g_ud[t] = u2;
        }
        if (t == 0) {
            float c1v = 0.f, c2v = 0.f;
            for (int c = 0; c < 256; c++) {
                c1v = fmaf(bc[c], attW[c], c1v);
                c2v = fmaf(bc[c], attW[256 + c], c2v);
            }
            g_cs[0] = c1v; g_cs[1] = c2v;
        }
    }
}

// ============================ segment mean (warp/node, fp32) ============================
template<bool NORM, bool DOTS>
__global__ __launch_bounds__(256) void k_segmean(
    const float* __restrict__ zin, float* __restrict__ out, float* __restrict__ out2)
{
    int node = blockIdx.x*8 + (threadIdx.x >> 5);
    if (node >= NN) return;
    int lane = threadIdx.x & 31;
    int e0 = g_off[node], e1 = g_off[node+1];
    float4 acc = make_float4(0.f,0.f,0.f,0.f);
    int j = e0;
    for (; j + 2 <= e1; j += 2) {
        int s0 = g_csrc[j], s1i = g_csrc[j+1];
        float4 v0 = *(const float4*)(zin + (size_t)s0*DD + lane*4);
        float4 v1 = *(const float4*)(zin + (size_t)s1i*DD + lane*4);
        acc.x += v0.x + v1.x; acc.y += v0.y + v1.y;
        acc.z += v0.z + v1.z; acc.w += v0.w + v1.w;
    }
    if (j < e1) {
        int s0 = g_csrc[j];
        float4 v0 = *(const float4*)(zin + (size_t)s0*DD + lane*4);
        acc.x += v0.x; acc.y += v0.y; acc.z += v0.z; acc.w += v0.w;
    }
    float inv = 1.0f / (float)(e1 - e0);
    acc.x *= inv; acc.y *= inv; acc.z *= inv; acc.w *= inv;
    if (NORM) {
        float ss = acc.x*acc.x + acc.y*acc.y + acc.z*acc.z + acc.w*acc.w;
        #pragma unroll
        for (int o = 16; o > 0; o >>= 1) ss += __shfl_xor_sync(0xffffffffu, ss, o);
        float r = 1.0f / fmaxf(sqrtf(ss), 1e-12f);
        acc.x *= r; acc.y *= r; acc.z *= r; acc.w *= r;
    }
    *(float4*)(out + (size_t)node*DD + lane*4) = acc;
    if (out2) *(float4*)(out2 + (size_t)node*DD + lane*4) = acc;
    if (DOTS) {
        float4 us4 = *(const float4*)(g_us + lane*4);
        float4 ud4 = *(const float4*)(g_ud + lane*4);
        float as = acc.x*us4.x + acc.y*us4.y + acc.z*us4.z + acc.w*us4.w;
        float ad = acc.x*ud4.x + acc.y*ud4.y + acc.z*ud4.z + acc.w*ud4.w;
        #pragma unroll
        for (int o = 16; o > 0; o >>= 1) {
            as += __shfl_xor_sync(0xffffffffu, as, o);
            ad += __shfl_xor_sync(0xffffffffu, ad, o);
        }
        if (lane == 0) { g_asrc[node] = as + g_cs[0]; g_adst[node] = ad + g_cs[1]; }
    }
}

// ============================ GEMM 128x128 + L2-norm epilogue ============================
__global__ __launch_bounds__(256) void k_gemm_norm(
    const float* __restrict__ A, const float* __restrict__ B,
    const float* __restrict__ bias, float* __restrict__ C, float* __restrict__ C2)
{
    __shared__ float As[8][128];
    __shared__ float Bs[8][128];
    __shared__ float red[128][16];
    int tid = threadIdx.x;
    int row0 = blockIdx.x*128;
    int tr = tid/16, tc = tid%16;
    float acc[8][8];
    #pragma unroll
    for (int i = 0; i < 8; i++)
        #pragma unroll
        for (int jj = 0; jj < 8; jj++) acc[i][jj] = 0.0f;

    int aRow = tid/2, aCol = (tid%2)*4;
    int bRow = tid/32, bCol = (tid%32)*4;

    for (int k0 = 0; k0 < 128; k0 += 8) {
        float4 av = make_float4(0.f,0.f,0.f,0.f);
        int gr = row0 + aRow;
        if (gr < NN) av = *(const float4*)(A + (size_t)gr*128 + k0 + aCol);
        As[aCol+0][aRow] = av.x; As[aCol+1][aRow] = av.y;
        As[aCol+2][aRow] = av.z; As[aCol+3][aRow] = av.w;
        *(float4*)&Bs[bRow][bCol] = *(const float4*)(B + (size_t)(k0+bRow)*128 + bCol);
        __syncthreads();
        #pragma unroll
        for (int kk = 0; kk < 8; kk++) {
            float ra[8], rb[8];
            *(float4*)(ra)   = *(float4*)&As[kk][tr*8];
            *(float4*)(ra+4) = *(float4*)&As[kk][tr*8+4];
            *(float4*)(rb)   = *(float4*)&Bs[kk][tc*8];
            *(float4*)(rb+4) = *(float4*)&Bs[kk][tc*8+4];
            #pragma unroll
            for (int i = 0; i < 8; i++)
                #pragma unroll
                for (int jj = 0; jj < 8; jj++)
                    acc[i][jj] = fmaf(ra[i], rb[jj], acc[i][jj]);
        }
        __syncthreads();
    }
    float bb[8];
    #pragma unroll
    for (int jj = 0; jj < 8; jj++) bb[jj] = bias[tc*8 + jj];
    #pragma unroll
    for (int i = 0; i < 8; i++) {
        float ssq = 0.f;
        #pragma unroll
        for (int jj = 0; jj < 8; jj++) {
            acc[i][jj] += bb[jj];
            ssq = fmaf(acc[i][jj], acc[i][jj], ssq);
        }
        red[tr*8+i][tc] = ssq;
    }
    __syncthreads();
    #pragma unroll
    for (int i = 0; i < 8; i++) {
        int row = tr*8 + i;
        float s = 0.f;
        #pragma unroll
        for (int t = 0; t < 16; t++) s += red[row][t];
        float r = 1.0f / fmaxf(sqrtf(s), 1e-12f);
        int gr = row0 + row;
        if (gr < NN) {
            float4 o0, o1;
            o0.x = acc[i][0]*r; o0.y = acc[i][1]*r; o0.z = acc[i][2]*r; o0.w = acc[i][3]*r;
            o1.x = acc[i][4]*r; o1.y = acc[i][5]*r; o1.z = acc[i][6]*r; o1.w = acc[i][7]*r;
            *(float4*)(C  + (size_t)gr*128 + tc*8)     = o0;
            *(float4*)(C  + (size_t)gr*128 + tc*8 + 4) = o1;
            *(float4*)(C2 + (size_t)gr*128 + tc*8)     = o0;
            *(float4*)(C2 + (size_t)gr*128 + tc*8 + 4) = o1;
        }
    }
}

// ============================ GAT aggregation (warp/node, fp32) ============================
__global__ __launch_bounds__(256) void k_gatagg(const float* __restrict__ attb)
{
    int node = blockIdx.x*8 + (threadIdx.x >> 5);
    if (node >= NN) return;
    int lane = threadIdx.x & 31;
    int e0 = g_off[node], e1 = g_off[node+1];
    float adb = g_adst[node] + attb[0];

    float mx = -FLT_MAX;
    for (int j = e0 + lane; j < e1; j += 32) {
        float e = g_asrc[g_csrc[j]] + adb;
        e = (e > 0.f) ? e : 0.01f*e;
        mx = fmaxf(mx, e);
    }
    #pragma unroll
    for (int o = 16; o > 0; o >>= 1) mx = fmaxf(mx, __shfl_xor_sync(0xffffffffu, mx, o));

    float4 acc = make_float4(0.f,0.f,0.f,0.f);
    float denom = 0.f;
    for (int base = e0; base < e1; base += 32) {
        int j = base + lane;
        int s = 0; float a = 0.f;
        if (j < e1) {
            s = g_csrc[j];
            float e = g_asrc[s] + adb;
            e = (e > 0.f) ? e : 0.01f*e;
            a = __expf(e - mx);
            denom += a;
        }
        int cnt = min(32, e1 - base);
        #pragma unroll 4
        for (int t = 0; t < cnt; t++) {
            float ab = __shfl_sync(0xffffffffu, a, t);
            int   sb = __shfl_sync(0xffffffffu, s, t);
            float4 v = *(const float4*)(g_m2 + (size_t)sb*DD + lane*4);
            acc.x = fmaf(ab, v.x, acc.x); acc.y = fmaf(ab, v.y, acc.y);
            acc.z = fmaf(ab, v.z, acc.z); acc.w = fmaf(ab, v.w, acc.w);
        }
    }
    #pragma unroll
    for (int o = 16; o > 0; o >>= 1) denom += __shfl_xor_sync(0xffffffffu, denom, o);
    float r = 1.0f / denom;
    acc.x *= r; acc.y *= r; acc.z *= r; acc.w *= r;
    *(float4*)(g_magg + (size_t)node*DD + lane*4) = acc;
}

// ============================ GEMM 64x256 + row-softmax -> s1 ============================
__global__ __launch_bounds__(256) void k_gemm_s1(float* __restrict__ s1out)
{
    __shared__ float As[8][64];
    __shared__ float Bs[8][256];
    __shared__ float red[64][16];
    int tid = threadIdx.x;
    int row0 = blockIdx.x*64;
    int tr = tid/16, tc = tid%16;
    float acc[4][16];
    #pragma unroll
    for (int i = 0; i < 4; i++)
        #pragma unroll
        for (int jj = 0; jj < 16; jj++) acc[i][jj] = 0.f;

    int aRow = tid/4, aCol = (tid%4)*2;
    int bRow = tid/32, bCol = (tid%32)*8;

    for (int k0 = 0; k0 < 128; k0 += 8) {
        float2 av = make_float2(0.f,0.f);
        int gr = row0 + aRow;
        if (gr < NN) av = *(const float2*)(g_magg + (size_t)gr*128 + k0 + aCol);
        As[aCol+0][aRow] = av.x; As[aCol+1][aRow] = av.y;
        *(float4*)&Bs[bRow][bCol]   = *(const float4*)(g_Wcomb + (size_t)(k0+bRow)*256 + bCol);
        *(float4*)&Bs[bRow][bCol+4] = *(const float4*)(g_Wcomb + (size_t)(k0+bRow)*256 + bCol + 4);
        __syncthreads();
        #pragma unroll
        for (int kk = 0; kk < 8; kk++) {
            float ra[4], rb[16];
            *(float4*)(ra)    = *(float4*)&As[kk][tr*4];
            *(float4*)(rb)    = *(float4*)&Bs[kk][tc*16];
            *(float4*)(rb+4)  = *(float4*)&Bs[kk][tc*16+4];
            *(float4*)(rb+8)  = *(float4*)&Bs[kk][tc*16+8];
            *(float4*)(rb+12) = *(float4*)&Bs[kk][tc*16+12];
            #pragma unroll
            for (int i = 0; i < 4; i++)
                #pragma unroll
                for (int jj = 0; jj < 16; jj++)
                    acc[i][jj] = fmaf(ra[i], rb[jj], acc[i][jj]);
        }
        __syncthreads();
    }
    float bb[16];
    #pragma unroll
    for (int jj = 0; jj < 16; jj++) bb[jj] = g_bcomb[tc*16 + jj];
    #pragma unroll
    for (int i = 0; i < 4; i++) {
        float lm = -FLT_MAX;
        #pragma unroll
        for (int jj = 0; jj < 16; jj++) {
            acc[i][jj] += bb[jj];
            lm = fmaxf(lm, acc[i][jj]);
        }
        red[tr*4+i][tc] = lm;
    }
    __syncthreads();
    float rowmax[4];
    #pragma unroll
    for (int i = 0; i < 4; i++) {
        float m = -FLT_MAX;
        #pragma unroll
        for (int t = 0; t < 16; t++) m = fmaxf(m, red[tr*4+i][t]);
        rowmax[i] = m;
    }
    __syncthreads();
    #pragma unroll
    for (int i = 0; i < 4; i++) {
        float ls = 0.f;
        #pragma unroll
        for (int jj = 0; jj < 16; jj++) {
            acc[i][jj] = __expf(acc[i][jj] - rowmax[i]);
            ls += acc[i][jj];
        }
        red[tr*4+i][tc] = ls;
    }
    __syncthreads();
    #pragma unroll
    for (int i = 0; i < 4; i++) {
        int gr = row0 + tr*4 + i;
        if (gr >= NN) continue;
        float s = 0.f;
        #pragma unroll
        for (int t = 0; t < 16; t++) s += red[tr*4+i][t];
        float rinv = 1.0f / s;
        #pragma unroll
        for (int jj = 0; jj < 16; jj += 4) {
            float4 o;
            o.x = acc[i][jj]*rinv;   o.y = acc[i][jj+1]*rinv;
            o.z = acc[i][jj+2]*rinv; o.w = acc[i][jj+3]*rinv;
            *(float4*)(s1out + (size_t)gr*256 + tc*16 + jj) = o;
        }
    }
}

// ============================ T = s1^T @ m2 + colsum(s1) ============================
#define SPLITS 80
__global__ __launch_bounds__(256) void k_at_b(const float* __restrict__ S)
{
    __shared__ float sS[16][64];
    __shared__ float sZ[16][128];
    int chunk = blockIdx.x;
    int k_begin = (int)((long long)NN * chunk / SPLITS);
    int k_end   = (int)((long long)NN * (chunk+1) / SPLITS);
    int m0 = blockIdx.y * 64;
    int tid = threadIdx.x;
    int tr = tid/16, tc = tid%16;
    float acc[4][8];
    #pragma unroll
    for (int i = 0; i < 4; i++)
        #pragma unroll
        for (int jj = 0; jj < 8; jj++) acc[i][jj] = 0.f;
    float colacc = 0.f;

    for (int k0 = k_begin; k0 < k_end; k0 += 16) {
        int kc = min(16, k_end - k0);
        {
            int r = tid/16, c4 = (tid%16)*4;
            float4 v = make_float4(0.f,0.f,0.f,0.f);
            if (r < kc) v = *(const float4*)(S + (size_t)(k0+r)*CC1 + m0 + c4);
            *(float4*)&sS[r][c4] = v;
        }
        #pragma unroll
        for (int half = 0; half < 2; half++) {
            int r = tid/32 + half*8, c4 = (tid%32)*4;
            float4 v = make_float4(0.f,0.f,0.f,0.f);
            if (r < kc) v = *(const float4*)(g_m2 + (size_t)(k0+r)*DD + c4);
            *(float4*)&sZ[r][c4] = v;
        }
        __syncthreads();
        if (tid < 64) {
            #pragma unroll
            for (int r = 0; r < 16; r++) colacc += sS[r][tid];
        }
        #pragma unroll
        for (int kk = 0; kk < 16; kk++) {
            float ra[4], rb[8];
            *(float4*)(ra)   = *(float4*)&sS[kk][tr*4];
            *(float4*)(rb)   = *(float4*)&sZ[kk][tc*8];
            *(float4*)(rb+4) = *(float4*)&sZ[kk][tc*8+4];
            #pragma unroll
            for (int i = 0; i < 4; i++)
                #pragma unroll
                for (int jj = 0; jj < 8; jj++)
                    acc[i][jj] = fmaf(ra[i], rb[jj], acc[i][jj]);
        }
        __syncthreads();
    }
    #pragma unroll
    for (int i = 0; i < 4; i++)
        #pragma unroll
        for (int jj = 0; jj < 8; jj++)
            atomicAdd(&g_Tbuf[(m0 + tr*4 + i)*DD + tc*8 + jj], acc[i][jj]);
    if (tid < 64) atomicAdd(&g_Tbuf[CC1*DD + m0 + tid], colacc);
}

// ============================ x1 = T@We1 + colsum (x) be1 ============================
__global__ __launch_bounds__(256) void k_x1(
    const float* __restrict__ We1, const float* __restrict__ be1,
    float* __restrict__ out)
{
    int elem = blockIdx.x*256 + threadIdx.x;
    int k = elem >> 7, d = elem & 127;
    float s = 0.f;
    #pragma unroll 8
    for (int e = 0; e < 128; e++) s = fmaf(g_Tbuf[k*128 + e], We1[e*128 + d], s);
    out[OFF_X1 + elem] = s + g_Tbuf[CC1*DD + k]*be1[d];
}

// ============================ analytic coarse tail ============================
__global__ __launch_bounds__(256) void k_tail(
    const float* __restrict__ We1, const float* __restrict__ be1,
    const float* __restrict__ We2, const float* __restrict__ be2,
    const float* __restrict__ Wa2, const float* __restrict__ ba2,
    float* __restrict__ out)
{
    __shared__ float sumT[128];
    __shared__ float meanx1[128];
    __shared__ float meanvec[128];
    __shared__ float s2row[32];
    __shared__ float sc[256];
    int t = threadIdx.x;

    if (t < 128) {
        float s = 0.f;
        for (int k = 0; k < 256; k++) s += g_Tbuf[k*128 + t];
        sumT[t] = s;
    }
    sc[t] = g_Tbuf[CC1*DD + t];
    __syncthreads();
    #pragma unroll
    for (int st = 128; st > 0; st >>= 1) {
        if (t < st) sc[t] += sc[t+st];
        __syncthreads();
    }
    float sumcol = sc[0];
    if (t < 128) {
        float s = 0.f;
        for (int e = 0; e < 128; e++) s = fmaf(sumT[e], We1[e*128 + t], s);
        meanx1[t] = (s + sumcol*be1[t]) * (1.0f/256.0f);
    }
    __syncthreads();
    if (t < 128) {
        float s = 0.f;
        for (int e = 0; e < 128; e++) s = fmaf(meanx1[e], We2[e*128 + t], s);
        meanvec[t] = s + be2[t];
    }
    __syncthreads();
    if (t < 32) {
        float s = 0.f;
        for (int d = 0; d < 128; d++) s = fmaf(meanvec[d], Wa2[d*32 + t], s);
        float v = s + ba2[t];
        float mx = v;
        #pragma unroll
        for (int o = 16; o > 0; o >>= 1) mx = fmaxf(mx, __shfl_xor_sync(0xffffffffu, mx, o));
        float ex = __expf(v - mx);
        float sm = ex;
        #pragma unroll
        for (int o = 16; o > 0; o >>= 1) sm += __shfl_xor_sync(0xffffffffu, sm, o);
        s2row[t] = ex / sm;
    }
    __syncthreads();
    for (int i = t; i < 256*32; i += 256) out[OFF_S2 + i] = s2row[i & 31];
    if (t < 32) out[OFF_A1 + t] = 1.0f;
    for (int i = t; i < 32*128; i += 256)
        out[OFF_X2 + i] = 256.0f * s2row[i >> 7] * meanvec[i & 127];
    if (t == 0) {
        float s = 0.f;
        for (int d = 0; d < 128; d++) s += meanvec[d];
        out[OFF_E0] = s * (1.0f/16.0f);
    }
}

// ============================ launch ============================
extern "C" void kernel_launch(void* const* d_in, const int* in_sizes, int n_in,
                              void* d_out, int out_size)
{
    const float* feature = (const float*)d_in[0];
    const int*   eidx    = (const int*)d_in[1];
    const int*   src     = eidx;
    const int*   dst     = eidx + EE;
    const float* Wf   = (const float*)d_in[2];
    const float* bf   = (const float*)d_in[3];
    const float* We1  = (const float*)d_in[4];
    const float* be1  = (const float*)d_in[5];
    const float* Wa1  = (const float*)d_in[6];
    const float* ba1  = (const float*)d_in[7];
    const float* attW1 = (const float*)d_in[8];
    const float* attb1 = (const float*)d_in[9];
    const float* We2  = (const float*)d_in[10];
    const float* be2  = (const float*)d_in[11];
    const float* Wa2  = (const float*)d_in[12];
    const float* ba2  = (const float*)d_in[13];
    float* out = (float*)d_out;

    void *deg_p, *tbuf_p;
    float *g_mf_p, *g_x_p, *g_m2_p;
    cudaGetSymbolAddress(&deg_p,  g_deg);
    cudaGetSymbolAddress(&tbuf_p, g_Tbuf);
    cudaGetSymbolAddress((void**)&g_mf_p, g_mf);
    cudaGetSymbolAddress((void**)&g_x_p,  g_x);
    cudaGetSymbolAddress((void**)&g_m2_p, g_m2);

    // zero accumulators / degree counters
    cudaMemsetAsync(deg_p,  0, NN*sizeof(int));
    cudaMemsetAsync(tbuf_p, 0, (CC1*DD + CC1)*sizeof(float));

    // graph build + weight folding
    k_count<<<(EE + 255)/256, 256>>>(dst);
    k_fold<<<129, 256>>>(We1, be1, Wa1, ba1, attW1);
    k_scan1<<<NB, 128>>>();
    k_scan2<<<1, 256>>>();
    k_scan3<<<NB, 128>>>();
    k_fill<<<(EE + 255)/256, 256>>>(src, dst);

    // mf = segmean(feature)
    k_segmean<false,false><<<(NN+7)/8, 256>>>(feature, g_mf_p, (float*)0);
    // x = normalize(mf@Wf + bf); embed3 = x
    k_gemm_norm<<<(NN+127)/128, 256>>>(g_mf_p, Wf, bf, g_x_p, out + OFF_E3);
    // m2 = segmean(x) + fused a_src/a_dst
    k_segmean<false,true><<<(NN+7)/8, 256>>>(g_x_p, g_m2_p, (float*)0);
    // GAT aggregation on 128-wide m2
    k_gatagg<<<(NN+7)/8, 256>>>(attb1);
    // s1 = softmax(magg@W_comb + b_comb)
    k_gemm_s1<<<(NN+63)/64, 256>>>(out + OFF_S1);
    // T = s1^T @ m2, colsum(s1)
    k_at_b<<<dim3(SPLITS, 4), 256>>>(out + OFF_S1);
    // x1 = T@We1 + colsum (x) be1
    k_x1<<<128, 256>>>(We1, be1, out);
    // analytic coarse level
    k_tail<<<1, 256>>>(We1, be1, We2, be2, Wa2, ba2, out);
}

// round 5
// speedup vs baseline: 1.5918x; 1.0735x over previous
#include <cuda_runtime.h>
#include <math.h>
#include <float.h>

#define NN   20000
#define EE   340000
#define DD   128
#define CC1  256
#define NB   157      // ceil(NN/128)

// ---- output layout (element offsets into float* d_out) ----
#define OFF_S1  0
#define OFF_S2  (NN*CC1)
#define OFF_A1  (OFF_S2 + 256*32)
#define OFF_E3  (OFF_A1 + 32)
#define OFF_X1  (OFF_E3 + NN*DD)
#define OFF_X2  (OFF_X1 + 256*128)
#define OFF_E0  (OFF_X2 + 32*128)

// ---- scratch ----
__device__ float g_zf[NN*DD];
__device__ float g_x[NN*DD];
__device__ float g_m2[NN*DD];
__device__ float g_magg[NN*DD];
__device__ float g_asrc[NN];
__device__ float g_adst[NN];
__device__ int   g_deg[NN];
__device__ int   g_off[NN+1];
__device__ int   g_cur[NN];
__device__ int   g_csrc[EE];
__device__ float g_Wcomb[DD*CC1];        // 128x256
__device__ float g_bcomb[CC1];
__device__ float g_us[DD];
__device__ float g_ud[DD];
__device__ float g_cs[2];
__device__ float g_Tbuf[CC1*DD + CC1];   // T = s1^T@m2 ; then colsum(s1)

// ---- persistent side stream + events (created at load, before harness checkpoints) ----
struct SideRes {
    cudaStream_t s;
    cudaEvent_t fork, join;
    SideRes() {
        cudaStreamCreateWithFlags(&s, cudaStreamNonBlocking);
        cudaEventCreateWithFlags(&fork, cudaEventDisableTiming);
        cudaEventCreateWithFlags(&join, cudaEventDisableTiming);
    }
};
static SideRes g_sr;

// ============================ graph build ============================
__global__ void k_count(const int* __restrict__ dst) {
    int e = blockIdx.x*blockDim.x + threadIdx.x;
    if (e < EE) atomicAdd(&g_deg[dst[e]], 1);
}

// single-kernel scan: each block independently computes its base prefix
__global__ void k_scanall() {   // NB blocks x 128
    __shared__ int sh[128];
    int t = threadIdx.x, b = blockIdx.x;
    // base = sum of deg[0 .. b*128)
    int base = 0;
    for (int i = t; i < b*128; i += 128) base += g_deg[i];
    sh[t] = base; __syncthreads();
    #pragma unroll
    for (int st = 64; st > 0; st >>= 1) {
        if (t < st) sh[t] += sh[t+st];
        __syncthreads();
    }
    base = sh[0];
    __syncthreads();
    // local inclusive scan of this 128-chunk
    int i = b*128 + t;
    int d = (i < NN) ? g_deg[i] : 0;
    sh[t] = d; __syncthreads();
    #pragma unroll
    for (int off = 1; off < 128; off <<= 1) {
        int v = (t >= off) ? sh[t-off] : 0;
        __syncthreads();
        sh[t] += v;
        __syncthreads();
    }
    int excl = base + sh[t] - d;
    if (i < NN) { g_off[i] = excl; g_cur[i] = excl; }
    if (i == 0) g_off[NN] = EE;
}

__global__ void k_fill(const int* __restrict__ src, const int* __restrict__ dst) {
    int e = blockIdx.x*blockDim.x + threadIdx.x;
    if (e < EE) {
        int p = atomicAdd(&g_cur[dst[e]], 1);
        g_csrc[p] = src[e];
    }
}

// ============================ weight folding ============================
__global__ __launch_bounds__(256) void k_fold(
    const float* __restrict__ We1, const float* __restrict__ be1,
    const float* __restrict__ Wa1, const float* __restrict__ ba1,
    const float* __restrict__ attW)
{
    int b = blockIdx.x, t = threadIdx.x;
    if (b < 128) {
        __shared__ float sWe[128];
        if (t < 128) sWe[t] = We1[b*128 + t];
        __syncthreads();
        float acc = 0.f;
        #pragma unroll 8
        for (int k = 0; k < 128; k++) acc = fmaf(sWe[k], Wa1[k*256 + t], acc);
        g_Wcomb[b*256 + t] = acc;
    } else {
        __shared__ float ts[128], td[128], bc[256];
        if (t < 128) {
            float s1v = 0.f, s2v = 0.f;
            for (int c = 0; c < 256; c++) {
                float w = Wa1[t*256 + c];
                s1v = fmaf(w, attW[c], s1v);
                s2v = fmaf(w, attW[256 + c], s2v);
            }
            ts[t] = s1v; td[t] = s2v;
        }
        {
            float s = 0.f;
            for (int e = 0; e < 128; e++) s = fmaf(be1[e], Wa1[e*256 + t], s);
            bc[t] = s + ba1[t];
            g_bcomb[t] = bc[t];
        }
        __syncthreads();
        if (t < 128) {
            float u1 = 0.f, u2 = 0.f;
            for (int e = 0; e < 128; e++) {
                float w = We1[t*128 + e];
                u1 = fmaf(w, ts[e], u1);
                u2 = fmaf(w, td[e], u2);
            }
            g_us[t] = u1; g_ud[t] = u2;
        }
        if (t == 0) {
            float c1v = 0.f, c2v = 0.f;
            for (int c = 0; c < 256; c++) {
                c1v = fmaf(bc[c], attW[c], c1v);
                c2v = fmaf(bc[c], attW[256 + c], c2v);
            }
            g_cs[0] = c1v; g_cs[1] = c2v;
        }
    }
}

// ============================ GEMM 128x128 + bias -> zf ============================
__global__ __launch_bounds__(256) void k_gemm_zf(
    const float* __restrict__ A, const float* __restrict__ B,
    const float* __restrict__ bias, float* __restrict__ C)
{
    __shared__ float As[8][128];
    __shared__ float Bs[8][128];
    int tid = threadIdx.x;
    int row0 = blockIdx.x*128;
    int tr = tid/16, tc = tid%16;
    float acc[8][8];
    #pragma unroll
    for (int i = 0; i < 8; i++)
        #pragma unroll
        for (int jj = 0; jj < 8; jj++) acc[i][jj] = 0.0f;

    int aRow = tid/2, aCol = (tid%2)*4;
    int bRow = tid/32, bCol = (tid%32)*4;

    for (int k0 = 0; k0 < 128; k0 += 8) {
        float4 av = make_float4(0.f,0.f,0.f,0.f);
        int gr = row0 + aRow;
        if (gr < NN) av = *(const float4*)(A + (size_t)gr*128 + k0 + aCol);
        As[aCol+0][aRow] = av.x; As[aCol+1][aRow] = av.y;
        As[aCol+2][aRow] = av.z; As[aCol+3][aRow] = av.w;
        *(float4*)&Bs[bRow][bCol] = *(const float4*)(B + (size_t)(k0+bRow)*128 + bCol);
        __syncthreads();
        #pragma unroll
        for (int kk = 0; kk < 8; kk++) {
            float ra[8], rb[8];
            *(float4*)(ra)   = *(float4*)&As[kk][tr*8];
            *(float4*)(ra+4) = *(float4*)&As[kk][tr*8+4];
            *(float4*)(rb)   = *(float4*)&Bs[kk][tc*8];
            *(float4*)(rb+4) = *(float4*)&Bs[kk][tc*8+4];
            #pragma unroll
            for (int i = 0; i < 8; i++)
                #pragma unroll
                for (int jj = 0; jj < 8; jj++)
                    acc[i][jj] = fmaf(ra[i], rb[jj], acc[i][jj]);
        }
        __syncthreads();
    }
    float bb[8];
    #pragma unroll
    for (int jj = 0; jj < 8; jj++) bb[jj] = bias[tc*8 + jj];
    #pragma unroll
    for (int i = 0; i < 8; i++) {
        int gr = row0 + tr*8 + i;
        if (gr >= NN) continue;
        float4 o0, o1;
        o0.x = acc[i][0]+bb[0]; o0.y = acc[i][1]+bb[1];
        o0.z = acc[i][2]+bb[2]; o0.w = acc[i][3]+bb[3];
        o1.x = acc[i][4]+bb[4]; o1.y = acc[i][5]+bb[5];
        o1.z = acc[i][6]+bb[6]; o1.w = acc[i][7]+bb[7];
        *(float4*)(C + (size_t)gr*128 + tc*8)     = o0;
        *(float4*)(C + (size_t)gr*128 + tc*8 + 4) = o1;
    }
}

// ============================ segment mean (warp/node, fp32) ============================
template<bool NORM, bool DOTS>
__global__ __launch_bounds__(256) void k_segmean(
    const float* __restrict__ zin, float* __restrict__ out, float* __restrict__ out2)
{
    int node = blockIdx.x*8 + (threadIdx.x >> 5);
    if (node >= NN) return;
    int lane = threadIdx.x & 31;
    int e0 = g_off[node], e1 = g_off[node+1];
    float4 acc = make_float4(0.f,0.f,0.f,0.f);
    int j = e0;
    for (; j + 2 <= e1; j += 2) {
        int s0 = g_csrc[j], s1i = g_csrc[j+1];
        float4 v0 = *(const float4*)(zin + (size_t)s0*DD + lane*4);
        float4 v1 = *(const float4*)(zin + (size_t)s1i*DD + lane*4);
        acc.x += v0.x + v1.x; acc.y += v0.y + v1.y;
        acc.z += v0.z + v1.z; acc.w += v0.w + v1.w;
    }
    if (j < e1) {
        int s0 = g_csrc[j];
        float4 v0 = *(const float4*)(zin + (size_t)s0*DD + lane*4);
        acc.x += v0.x; acc.y += v0.y; acc.z += v0.z; acc.w += v0.w;
    }
    float inv = 1.0f / (float)(e1 - e0);
    acc.x *= inv; acc.y *= inv; acc.z *= inv; acc.w *= inv;
    if (NORM) {
        float ss = acc.x*acc.x + acc.y*acc.y + acc.z*acc.z + acc.w*acc.w;
        #pragma unroll
        for (int o = 16; o > 0; o >>= 1) ss += __shfl_xor_sync(0xffffffffu, ss, o);
        float r = 1.0f / fmaxf(sqrtf(ss), 1e-12f);
        acc.x *= r; acc.y *= r; acc.z *= r; acc.w *= r;
    }
    *(float4*)(out + (size_t)node*DD + lane*4) = acc;
    if (out2) *(float4*)(out2 + (size_t)node*DD + lane*4) = acc;
    if (DOTS) {
        float4 us4 = *(const float4*)(g_us + lane*4);
        float4 ud4 = *(const float4*)(g_ud + lane*4);
        float as = acc.x*us4.x + acc.y*us4.y + acc.z*us4.z + acc.w*us4.w;
        float ad = acc.x*ud4.x + acc.y*ud4.y + acc.z*ud4.z + acc.w*ud4.w;
        #pragma unroll
        for (int o = 16; o > 0; o >>= 1) {
            as += __shfl_xor_sync(0xffffffffu, as, o);
            ad += __shfl_xor_sync(0xffffffffu, ad, o);
        }
        if (lane == 0) { g_asrc[node] = as + g_cs[0]; g_adst[node] = ad + g_cs[1]; }
    }
}

// ============================ GAT aggregation (warp/node, fp32) ============================
__global__ __launch_bounds__(256) void k_gatagg(const float* __restrict__ attb)
{
    int node = blockIdx.x*8 + (threadIdx.x >> 5);
    if (node >= NN) return;
    int lane = threadIdx.x & 31;
    int e0 = g_off[node], e1 = g_off[node+1];
    float adb = g_adst[node] + attb[0];

    float mx = -FLT_MAX;
    for (int j = e0 + lane; j < e1; j += 32) {
        float e = g_asrc[g_csrc[j]] + adb;
        e = (e > 0.f) ? e : 0.01f*e;
        mx = fmaxf(mx, e);
    }
    #pragma unroll
    for (int o = 16; o > 0; o >>= 1) mx = fmaxf(mx, __shfl_xor_sync(0xffffffffu, mx, o));

    float4 acc = make_float4(0.f,0.f,0.f,0.f);
    float denom = 0.f;
    for (int base = e0; base < e1; base += 32) {
        int j = base + lane;
        int s = 0; float a = 0.f;
        if (j < e1) {
            s = g_csrc[j];
            float e = g_asrc[s] + adb;
            e = (e > 0.f) ? e : 0.01f*e;
            a = __expf(e - mx);
            denom += a;
        }
        int cnt = min(32, e1 - base);
        #pragma unroll 4
        for (int t = 0; t < cnt; t++) {
            float ab = __shfl_sync(0xffffffffu, a, t);
            int   sb = __shfl_sync(0xffffffffu, s, t);
            float4 v = *(const float4*)(g_m2 + (size_t)sb*DD + lane*4);
            acc.x = fmaf(ab, v.x, acc.x); acc.y = fmaf(ab, v.y, acc.y);
            acc.z = fmaf(ab, v.z, acc.z); acc.w = fmaf(ab, v.w, acc.w);
        }
    }
    #pragma unroll
    for (int o = 16; o > 0; o >>= 1) denom += __shfl_xor_sync(0xffffffffu, denom, o);
    float r = 1.0f / denom;
    acc.x *= r; acc.y *= r; acc.z *= r; acc.w *= r;
    *(float4*)(g_magg + (size_t)node*DD + lane*4) = acc;
}

// ============================ GEMM 64x256 + row-softmax -> s1 ============================
__global__ __launch_bounds__(256) void k_gemm_s1(float* __restrict__ s1out)
{
    __shared__ float As[8][64];
    __shared__ float Bs[8][256];
    __shared__ float red[64][16];
    int tid = threadIdx.x;
    int row0 = blockIdx.x*64;
    int tr = tid/16, tc = tid%16;
    float acc[4][16];
    #pragma unroll
    for (int i = 0; i < 4; i++)
        #pragma unroll
        for (int jj = 0; jj < 16; jj++) acc[i][jj] = 0.f;

    int aRow = tid/4, aCol = (tid%4)*2;
    int bRow = tid/32, bCol = (tid%32)*8;

    for (int k0 = 0; k0 < 128; k0 += 8) {
        float2 av = make_float2(0.f,0.f);
        int gr = row0 + aRow;
        if (gr < NN) av = *(const float2*)(g_magg + (size_t)gr*128 + k0 + aCol);
        As[aCol+0][aRow] = av.x; As[aCol+1][aRow] = av.y;
        *(float4*)&Bs[bRow][bCol]   = *(const float4*)(g_Wcomb + (size_t)(k0+bRow)*256 + bCol);
        *(float4*)&Bs[bRow][bCol+4] = *(const float4*)(g_Wcomb + (size_t)(k0+bRow)*256 + bCol + 4);
        __syncthreads();
        #pragma unroll
        for (int kk = 0; kk < 8; kk++) {
            float ra[4], rb[16];
            *(float4*)(ra)    = *(float4*)&As[kk][tr*4];
            *(float4*)(rb)    = *(float4*)&Bs[kk][tc*16];
            *(float4*)(rb+4)  = *(float4*)&Bs[kk][tc*16+4];
            *(float4*)(rb+8)  = *(float4*)&Bs[kk][tc*16+8];
            *(float4*)(rb+12) = *(float4*)&Bs[kk][tc*16+12];
            #pragma unroll
            for (int i = 0; i < 4; i++)
                #pragma unroll
                for (int jj = 0; jj < 16; jj++)
                    acc[i][jj] = fmaf(ra[i], rb[jj], acc[i][jj]);
        }
        __syncthreads();
    }
    float bb[16];
    #pragma unroll
    for (int jj = 0; jj < 16; jj++) bb[jj] = g_bcomb[tc*16 + jj];
    #pragma unroll
    for (int i = 0; i < 4; i++) {
        float lm = -FLT_MAX;
        #pragma unroll
        for (int jj = 0; jj < 16; jj++) {
            acc[i][jj] += bb[jj];
            lm = fmaxf(lm, acc[i][jj]);
        }
        red[tr*4+i][tc] = lm;
    }
    __syncthreads();
    float rowmax[4];
    #pragma unroll
    for (int i = 0; i < 4; i++) {
        float m = -FLT_MAX;
        #pragma unroll
        for (int t = 0; t < 16; t++) m = fmaxf(m, red[tr*4+i][t]);
        rowmax[i] = m;
    }
    __syncthreads();
    #pragma unroll
    for (int i = 0; i < 4; i++) {
        float ls = 0.f;
        #pragma unroll
        for (int jj = 0; jj < 16; jj++) {
            acc[i][jj] = __expf(acc[i][jj] - rowmax[i]);
            ls += acc[i][jj];
        }
        red[tr*4+i][tc] = ls;
    }
    __syncthreads();
    #pragma unroll
    for (int i = 0; i < 4; i++) {
        int gr = row0 + tr*4 + i;
        if (gr >= NN) continue;
        float s = 0.f;
        #pragma unroll
        for (int t = 0; t < 16; t++) s += red[tr*4+i][t];
        float rinv = 1.0f / s;
        #pragma unroll
        for (int jj = 0; jj < 16; jj += 4) {
            float4 o;
            o.x = acc[i][jj]*rinv;   o.y = acc[i][jj+1]*rinv;
            o.z = acc[i][jj+2]*rinv; o.w = acc[i][jj+3]*rinv;
            *(float4*)(s1out + (size_t)gr*256 + tc*16 + jj) = o;
        }
    }
}

// ============================ T = s1^T @ m2 + colsum(s1) ============================
#define SPLITS 80
__global__ __launch_bounds__(256) void k_at_b(const float* __restrict__ S)
{
    __shared__ float sS[16][64];
    __shared__ float sZ[16][128];
    int chunk = blockIdx.x;
    int k_begin = (int)((long long)NN * chunk / SPLITS);
    int k_end   = (int)((long long)NN * (chunk+1) / SPLITS);
    int m0 = blockIdx.y * 64;
    int tid = threadIdx.x;
    int tr = tid/16, tc = tid%16;
    float acc[4][8];
    #pragma unroll
    for (int i = 0; i < 4; i++)
        #pragma unroll
        for (int jj = 0; jj < 8; jj++) acc[i][jj] = 0.f;
    float colacc = 0.f;

    for (int k0 = k_begin; k0 < k_end; k0 += 16) {
        int kc = min(16, k_end - k0);
        {
            int r = tid/16, c4 = (tid%16)*4;
            float4 v = make_float4(0.f,0.f,0.f,0.f);
            if (r < kc) v = *(const float4*)(S + (size_t)(k0+r)*CC1 + m0 + c4);
            *(float4*)&sS[r][c4] = v;
        }
        #pragma unroll
        for (int half = 0; half < 2; half++) {
            int r = tid/32 + half*8, c4 = (tid%32)*4;
            float4 v = make_float4(0.f,0.f,0.f,0.f);
            if (r < kc) v = *(const float4*)(g_m2 + (size_t)(k0+r)*DD + c4);
            *(float4*)&sZ[r][c4] = v;
        }
        __syncthreads();
        if (tid < 64) {
            #pragma unroll
            for (int r = 0; r < 16; r++) colacc += sS[r][tid];
        }
        #pragma unroll
        for (int kk = 0; kk < 16; kk++) {
            float ra[4], rb[8];
            *(float4*)(ra)   = *(float4*)&sS[kk][tr*4];
            *(float4*)(rb)   = *(float4*)&sZ[kk][tc*8];
            *(float4*)(rb+4) = *(float4*)&sZ[kk][tc*8+4];
            #pragma unroll
            for (int i = 0; i < 4; i++)
                #pragma unroll
                for (int jj = 0; jj < 8; jj++)
                    acc[i][jj] = fmaf(ra[i], rb[jj], acc[i][jj]);
        }
        __syncthreads();
    }
    #pragma unroll
    for (int i = 0; i < 4; i++)
        #pragma unroll
        for (int jj = 0; jj < 8; jj++)
            atomicAdd(&g_Tbuf[(m0 + tr*4 + i)*DD + tc*8 + jj], acc[i][jj]);
    if (tid < 64) atomicAdd(&g_Tbuf[CC1*DD + m0 + tid], colacc);
}

// ============================ x1 + analytic coarse tail (merged) ============================
__global__ __launch_bounds__(256) void k_x1tail(
    const float* __restrict__ We1, const float* __restrict__ be1,
    const float* __restrict__ We2, const float* __restrict__ be2,
    const float* __restrict__ Wa2, const float* __restrict__ ba2,
    float* __restrict__ out)
{
    int t = threadIdx.x;
    if (blockIdx.x < 128) {
        // x1 = T@We1 + colsum (x) be1
        int elem = blockIdx.x*256 + t;
        int k = elem >> 7, d = elem & 127;
        float s = 0.f;
        #pragma unroll 8
        for (int e = 0; e < 128; e++) s = fmaf(g_Tbuf[k*128 + e], We1[e*128 + d], s);
        out[OFF_X1 + elem] = s + g_Tbuf[CC1*DD + k]*be1[d];
        return;
    }
    // tail block
    __shared__ float sumT[128];
    __shared__ float meanx1[128];
    __shared__ float meanvec[128];
    __shared__ float s2row[32];
    __shared__ float sc[256];

    if (t < 128) {
        float s = 0.f;
        for (int k = 0; k < 256; k++) s += g_Tbuf[k*128 + t];
        sumT[t] = s;
    }
    sc[t] = g_Tbuf[CC1*DD + t];
    __syncthreads();
    #pragma unroll
    for (int st = 128; st > 0; st >>= 1) {
        if (t < st) sc[t] += sc[t+st];
        __syncthreads();
    }
    float sumcol = sc[0];
    if (t < 128) {
        float s = 0.f;
        for (int e = 0; e < 128; e++) s = fmaf(sumT[e], We1[e*128 + t], s);
        meanx1[t] = (s + sumcol*be1[t]) * (1.0f/256.0f);
    }
    __syncthreads();
    if (t < 128) {
        float s = 0.f;
        for (int e = 0; e < 128; e++) s = fmaf(meanx1[e], We2[e*128 + t], s);
        meanvec[t] = s + be2[t];
    }
    __syncthreads();
    if (t < 32) {
        float s = 0.f;
        for (int d = 0; d < 128; d++) s = fmaf(meanvec[d], Wa2[d*32 + t], s);
        float v = s + ba2[t];
        float mx = v;
        #pragma unroll
        for (int o = 16; o > 0; o >>= 1) mx = fmaxf(mx, __shfl_xor_sync(0xffffffffu, mx, o));
        float ex = __expf(v - mx);
        float sm = ex;
        #pragma unroll
        for (int o = 16; o > 0; o >>= 1) sm += __shfl_xor_sync(0xffffffffu, sm, o);
        s2row[t] = ex / sm;
    }
    __syncthreads();
    for (int i = t; i < 256*32; i += 256) out[OFF_S2 + i] = s2row[i & 31];
    if (t < 32) out[OFF_A1 + t] = 1.0f;
    for (int i = t; i < 32*128; i += 256)
        out[OFF_X2 + i] = 256.0f * s2row[i >> 7] * meanvec[i & 127];
    if (t == 0) {
        float s = 0.f;
        for (int d = 0; d < 128; d++) s += meanvec[d];
        out[OFF_E0] = s * (1.0f/16.0f);
    }
}

// ============================ launch ============================
extern "C" void kernel_launch(void* const* d_in, const int* in_sizes, int n_in,
                              void* d_out, int out_size)
{
    const float* feature = (const float*)d_in[0];
    const int*   eidx    = (const int*)d_in[1];
    const int*   src     = eidx;
    const int*   dst     = eidx + EE;
    const float* Wf   = (const float*)d_in[2];
    const float* bf   = (const float*)d_in[3];
    const float* We1  = (const float*)d_in[4];
    const float* be1  = (const float*)d_in[5];
    const float* Wa1  = (const float*)d_in[6];
    const float* ba1  = (const float*)d_in[7];
    const float* attW1 = (const float*)d_in[8];
    const float* attb1 = (const float*)d_in[9];
    const float* We2  = (const float*)d_in[10];
    const float* be2  = (const float*)d_in[11];
    const float* Wa2  = (const float*)d_in[12];
    const float* ba2  = (const float*)d_in[13];
    float* out = (float*)d_out;

    void *deg_p, *tbuf_p;
    float *zf_p, *x_p, *m2_p;
    cudaGetSymbolAddress(&deg_p,  g_deg);
    cudaGetSymbolAddress(&tbuf_p, g_Tbuf);
    cudaGetSymbolAddress((void**)&zf_p, g_zf);
    cudaGetSymbolAddress((void**)&x_p,  g_x);
    cudaGetSymbolAddress((void**)&m2_p, g_m2);

    cudaStream_t side = g_sr.s;

    // ---- fork: side stream does dense prep (independent of the graph) ----
    cudaEventRecord(g_sr.fork, 0);
    cudaStreamWaitEvent(side, g_sr.fork, 0);
    cudaMemsetAsync(tbuf_p, 0, (CC1*DD + CC1)*sizeof(float), side);
    k_gemm_zf<<<(NN+127)/128, 256, 0, side>>>(feature, Wf, bf, zf_p);
    k_fold<<<129, 256, 0, side>>>(We1, be1, Wa1, ba1, attW1);
    cudaEventRecord(g_sr.join, side);

    // ---- main stream: graph build ----
    cudaMemsetAsync(deg_p, 0, NN*sizeof(int));
    k_count<<<(EE + 255)/256, 256>>>(dst);
    k_scanall<<<NB, 128>>>();
    k_fill<<<(EE + 255)/256, 256>>>(src, dst);

    // ---- join, then serial chain ----
    cudaStreamWaitEvent(0, g_sr.join, 0);

    // x = normalize(segmean(zf)); embed3 = x
    k_segmean<true,false><<<(NN+7)/8, 256>>>(zf_p, x_p, out + OFF_E3);
    // m2 = segmean(x) + fused a_src/a_dst
    k_segmean<false,true><<<(NN+7)/8, 256>>>(x_p, m2_p, (float*)0);
    // GAT aggregation on 128-wide m2
    k_gatagg<<<(NN+7)/8, 256>>>(attb1);
    // s1 = softmax(magg@W_comb + b_comb)
    k_gemm_s1<<<(NN+63)/64, 256>>>(out + OFF_S1);
    // T = s1^T @ m2, colsum(s1)
    k_at_b<<<dim3(SPLITS, 4), 256>>>(out + OFF_S1);
    // x1 + analytic coarse level (merged)
    k_x1tail<<<129, 256>>>(We1, be1, We2, be2, Wa2, ba2, out);
}

// round 6
// speedup vs baseline: 2.4590x; 1.5448x over previous
#include <cuda_runtime.h>
#include <math.h>
#include <float.h>
#include <stdint.h>

#define NN   20000
#define EE   340000
#define DD   128
#define CC1  256
#define NB   157      // ceil(NN/128)
#define CHUNKS 74     // at_b split-K chunks (74*2 = 148 blocks = 1/SM)

// ---- output layout (element offsets into float* d_out) ----
#define OFF_S1  0
#define OFF_S2  (NN*CC1)
#define OFF_A1  (OFF_S2 + 256*32)
#define OFF_E3  (OFF_A1 + 32)
#define OFF_X1  (OFF_E3 + NN*DD)
#define OFF_X2  (OFF_X1 + 256*128)
#define OFF_E0  (OFF_X2 + 32*128)

// ---- scratch ----
__device__ float g_zf[NN*DD];
__device__ float g_x[NN*DD];
__device__ float g_m2[NN*DD];
__device__ float g_magg[NN*DD];
__device__ float g_asrc[NN];
__device__ float g_adst[NN];
__device__ int   g_deg[NN];
__device__ int   g_off[NN+1];
__device__ int   g_cur[NN];
__device__ int   g_csrc[EE];
__device__ float g_Wcomb[DD*CC1];        // 128x256
__device__ float g_bcomb[CC1];
__device__ float g_us[DD];
__device__ float g_ud[DD];
__device__ float g_cs[2];
__device__ float g_part[CHUNKS*2*128*128]; // at_b per-block partials (9.7MB)
__device__ float g_colsum[CC1];
__device__ float g_sumT[DD];

// ---- persistent side stream + events ----
struct SideRes {
    cudaStream_t s;
    cudaEvent_t fork, join;
    SideRes() {
        cudaStreamCreateWithFlags(&s, cudaStreamNonBlocking);
        cudaEventCreateWithFlags(&fork, cudaEventDisableTiming);
        cudaEventCreateWithFlags(&join, cudaEventDisableTiming);
    }
};
static SideRes g_sr;

// ---- tf32 helpers ----
__device__ __forceinline__ float to_tf32(float x) {
    float r;
    asm("cvt.rna.tf32.f32 %0, %1;" : "=f"(r) : "f"(x));
    return r;
}
__device__ __forceinline__ void mma_tf32(float c[4],
    uint32_t a0, uint32_t a1, uint32_t a2, uint32_t a3,
    uint32_t b0, uint32_t b1)
{
    asm volatile(
        "mma.sync.aligned.m16n8k8.row.col.f32.tf32.tf32.f32 "
        "{%0,%1,%2,%3},{%4,%5,%6,%7},{%8,%9},{%0,%1,%2,%3};\n"
        : "+f"(c[0]), "+f"(c[1]), "+f"(c[2]), "+f"(c[3])
        : "r"(a0), "r"(a1), "r"(a2), "r"(a3), "r"(b0), "r"(b1));
}
__device__ __forceinline__ uint32_t fbits(float x) { return __float_as_uint(x); }

// ============================ graph build ============================
__global__ void k_count(const int* __restrict__ dst) {
    int e = blockIdx.x*blockDim.x + threadIdx.x;
    if (e < EE) atomicAdd(&g_deg[dst[e]], 1);
}

__global__ void k_scanall() {   // NB blocks x 128
    __shared__ int sh[128];
    int t = threadIdx.x, b = blockIdx.x;
    int base = 0;
    for (int i = t; i < b*128; i += 128) base += g_deg[i];
    sh[t] = base; __syncthreads();
    #pragma unroll
    for (int st = 64; st > 0; st >>= 1) {
        if (t < st) sh[t] += sh[t+st];
        __syncthreads();
    }
    base = sh[0];
    __syncthreads();
    int i = b*128 + t;
    int d = (i < NN) ? g_deg[i] : 0;
    sh[t] = d; __syncthreads();
    #pragma unroll
    for (int off = 1; off < 128; off <<= 1) {
        int v = (t >= off) ? sh[t-off] : 0;
        __syncthreads();
        sh[t] += v;
        __syncthreads();
    }
    int excl = base + sh[t] - d;
    if (i < NN) { g_off[i] = excl; g_cur[i] = excl; }
    if (i == 0) g_off[NN] = EE;
}

__global__ void k_fill(const int* __restrict__ src, const int* __restrict__ dst) {
    int e = blockIdx.x*blockDim.x + threadIdx.x;
    if (e < EE) {
        int p = atomicAdd(&g_cur[dst[e]], 1);
        g_csrc[p] = src[e];
    }
}

// ============================ weight folding ============================
__global__ __launch_bounds__(256) void k_fold(
    const float* __restrict__ We1, const float* __restrict__ be1,
    const float* __restrict__ Wa1, const float* __restrict__ ba1,
    const float* __restrict__ attW)
{
    int b = blockIdx.x, t = threadIdx.x;
    if (b < 128) {
        __shared__ float sWe[128];
        if (t < 128) sWe[t] = We1[b*128 + t];
        __syncthreads();
        float acc = 0.f;
        #pragma unroll 8
        for (int k = 0; k < 128; k++) acc = fmaf(sWe[k], Wa1[k*256 + t], acc);
        g_Wcomb[b*256 + t] = acc;
    } else {
        __shared__ float ts[128], td[128], bc[256];
        if (t < 128) {
            float s1v = 0.f, s2v = 0.f;
            for (int c = 0; c < 256; c++) {
                float w = Wa1[t*256 + c];
                s1v = fmaf(w, attW[c], s1v);
                s2v = fmaf(w, attW[256 + c], s2v);
            }
            ts[t] = s1v; td[t] = s2v;
        }
        {
            float s = 0.f;
            for (int e = 0; e < 128; e++) s = fmaf(be1[e], Wa1[e*256 + t], s);
            bc[t] = s + ba1[t];
            g_bcomb[t] = bc[t];
        }
        __syncthreads();
        if (t < 128) {
            float u1 = 0.f, u2 = 0.f;
            for (int e = 0; e < 128; e++) {
                float w = We1[t*128 + e];
                u1 = fmaf(w, ts[e], u1);
                u2 = fmaf(w, td[e], u2);
            }
            g_us[t] = u1; g_ud[t] = u2;
        }
        if (t == 0) {
            float c1v = 0.f, c2v = 0.f;
            for (int c = 0; c < 256; c++) {
                c1v = fmaf(bc[c], attW[c], c1v);
                c2v = fmaf(bc[c], attW[256 + c], c2v);
            }
            g_cs[0] = c1v; g_cs[1] = c2v;
        }
    }
}

// ============================ GEMM 128x128 + bias -> zf (scalar; overlapped) ============================
__global__ __launch_bounds__(256) void k_gemm_zf(
    const float* __restrict__ A, const float* __restrict__ B,
    const float* __restrict__ bias, float* __restrict__ C)
{
    __shared__ float As[8][128];
    __shared__ float Bs[8][128];
    int tid = threadIdx.x;
    int row0 = blockIdx.x*128;
    int tr = tid/16, tc = tid%16;
    float acc[8][8];
    #pragma unroll
    for (int i = 0; i < 8; i++)
        #pragma unroll
        for (int jj = 0; jj < 8; jj++) acc[i][jj] = 0.0f;

    int aRow = tid/2, aCol = (tid%2)*4;
    int bRow = tid/32, bCol = (tid%32)*4;

    for (int k0 = 0; k0 < 128; k0 += 8) {
        float4 av = make_float4(0.f,0.f,0.f,0.f);
        int gr = row0 + aRow;
        if (gr < NN) av = *(const float4*)(A + (size_t)gr*128 + k0 + aCol);
        As[aCol+0][aRow] = av.x; As[aCol+1][aRow] = av.y;
        As[aCol+2][aRow] = av.z; As[aCol+3][aRow] = av.w;
        *(float4*)&Bs[bRow][bCol] = *(const float4*)(B + (size_t)(k0+bRow)*128 + bCol);
        __syncthreads();
        #pragma unroll
        for (int kk = 0; kk < 8; kk++) {
            float ra[8], rb[8];
            *(float4*)(ra)   = *(float4*)&As[kk][tr*8];
            *(float4*)(ra+4) = *(float4*)&As[kk][tr*8+4];
            *(float4*)(rb)   = *(float4*)&Bs[kk][tc*8];
            *(float4*)(rb+4) = *(float4*)&Bs[kk][tc*8+4];
            #pragma unroll
            for (int i = 0; i < 8; i++)
                #pragma unroll
                for (int jj = 0; jj < 8; jj++)
                    acc[i][jj] = fmaf(ra[i], rb[jj], acc[i][jj]);
        }
        __syncthreads();
    }
    float bb[8];
    #pragma unroll
    for (int jj = 0; jj < 8; jj++) bb[jj] = bias[tc*8 + jj];
    #pragma unroll
    for (int i = 0; i < 8; i++) {
        int gr = row0 + tr*8 + i;
        if (gr >= NN) continue;
        float4 o0, o1;
        o0.x = acc[i][0]+bb[0]; o0.y = acc[i][1]+bb[1];
        o0.z = acc[i][2]+bb[2]; o0.w = acc[i][3]+bb[3];
        o1.x = acc[i][4]+bb[4]; o1.y = acc[i][5]+bb[5];
        o1.z = acc[i][6]+bb[6]; o1.w = acc[i][7]+bb[7];
        *(float4*)(C + (size_t)gr*128 + tc*8)     = o0;
        *(float4*)(C + (size_t)gr*128 + tc*8 + 4) = o1;
    }
}

// ============================ segment mean (warp/node, fp32) ============================
template<bool NORM, bool DOTS>
__global__ __launch_bounds__(256) void k_segmean(
    const float* __restrict__ zin, float* __restrict__ out, float* __restrict__ out2)
{
    int node = blockIdx.x*8 + (threadIdx.x >> 5);
    if (node >= NN) return;
    int lane = threadIdx.x & 31;
    int e0 = g_off[node], e1 = g_off[node+1];
    float4 acc = make_float4(0.f,0.f,0.f,0.f);
    int j = e0;
    for (; j + 2 <= e1; j += 2) {
        int s0 = g_csrc[j], s1i = g_csrc[j+1];
        float4 v0 = *(const float4*)(zin + (size_t)s0*DD + lane*4);
        float4 v1 = *(const float4*)(zin + (size_t)s1i*DD + lane*4);
        acc.x += v0.x + v1.x; acc.y += v0.y + v1.y;
        acc.z += v0.z + v1.z; acc.w += v0.w + v1.w;
    }
    if (j < e1) {
        int s0 = g_csrc[j];
        float4 v0 = *(const float4*)(zin + (size_t)s0*DD + lane*4);
        acc.x += v0.x; acc.y += v0.y; acc.z += v0.z; acc.w += v0.w;
    }
    float inv = 1.0f / (float)(e1 - e0);
    acc.x *= inv; acc.y *= inv; acc.z *= inv; acc.w *= inv;
    if (NORM) {
        float ss = acc.x*acc.x + acc.y*acc.y + acc.z*acc.z + acc.w*acc.w;
        #pragma unroll
        for (int o = 16; o > 0; o >>= 1) ss += __shfl_xor_sync(0xffffffffu, ss, o);
        float r = 1.0f / fmaxf(sqrtf(ss), 1e-12f);
        acc.x *= r; acc.y *= r; acc.z *= r; acc.w *= r;
    }
    *(float4*)(out + (size_t)node*DD + lane*4) = acc;
    if (out2) *(float4*)(out2 + (size_t)node*DD + lane*4) = acc;
    if (DOTS) {
        float4 us4 = *(const float4*)(g_us + lane*4);
        float4 ud4 = *(const float4*)(g_ud + lane*4);
        float as = acc.x*us4.x + acc.y*us4.y + acc.z*us4.z + acc.w*us4.w;
        float ad = acc.x*ud4.x + acc.y*ud4.y + acc.z*ud4.z + acc.w*ud4.w;
        #pragma unroll
        for (int o = 16; o > 0; o >>= 1) {
            as += __shfl_xor_sync(0xffffffffu, as, o);
            ad += __shfl_xor_sync(0xffffffffu, ad, o);
        }
        if (lane == 0) { g_asrc[node] = as + g_cs[0]; g_adst[node] = ad + g_cs[1]; }
    }
}

// ============================ GAT aggregation (warp/node, fp32) ============================
__global__ __launch_bounds__(256) void k_gatagg(const float* __restrict__ attb)
{
    int node = blockIdx.x*8 + (threadIdx.x >> 5);
    if (node >= NN) return;
    int lane = threadIdx.x & 31;
    int e0 = g_off[node], e1 = g_off[node+1];
    float adb = g_adst[node] + attb[0];

    float mx = -FLT_MAX;
    for (int j = e0 + lane; j < e1; j += 32) {
        float e = g_asrc[g_csrc[j]] + adb;
        e = (e > 0.f) ? e : 0.01f*e;
        mx = fmaxf(mx, e);
    }
    #pragma unroll
    for (int o = 16; o > 0; o >>= 1) mx = fmaxf(mx, __shfl_xor_sync(0xffffffffu, mx, o));

    float4 acc = make_float4(0.f,0.f,0.f,0.f);
    float denom = 0.f;
    for (int base = e0; base < e1; base += 32) {
        int j = base + lane;
        int s = 0; float a = 0.f;
        if (j < e1) {
            s = g_csrc[j];
            float e = g_asrc[s] + adb;
            e = (e > 0.f) ? e : 0.01f*e;
            a = __expf(e - mx);
            denom += a;
        }
        int cnt = min(32, e1 - base);
        #pragma unroll 4
        for (int t = 0; t < cnt; t++) {
            float ab = __shfl_sync(0xffffffffu, a, t);
            int   sb = __shfl_sync(0xffffffffu, s, t);
            float4 v = *(const float4*)(g_m2 + (size_t)sb*DD + lane*4);
            acc.x = fmaf(ab, v.x, acc.x); acc.y = fmaf(ab, v.y, acc.y);
            acc.z = fmaf(ab, v.z, acc.z); acc.w = fmaf(ab, v.w, acc.w);
        }
    }
    #pragma unroll
    for (int o = 16; o > 0; o >>= 1) denom += __shfl_xor_sync(0xffffffffu, denom, o);
    float r = 1.0f / denom;
    acc.x *= r; acc.y *= r; acc.z *= r; acc.w *= r;
    *(float4*)(g_magg + (size_t)node*DD + lane*4) = acc;
}

// ============================ s1 = softmax(magg@Wcomb + bcomb) : TF32 MMA ============================
// block tile 64(m) x 256(n), K=128 in 4 slabs of 32. 8 warps: warp tile 32x64.
__global__ __launch_bounds__(256) void k_gemm_s1(float* __restrict__ s1out)
{
    __shared__ float As[64][36];     // [m][k], ld 36: conflict-free frags
    __shared__ float Bs[32][264];    // [k][n], ld 264
    __shared__ float sbc[256];
    __shared__ float redmax[64][4];
    __shared__ float redsum[64][4];

    int tid = threadIdx.x;
    int w = tid >> 5, lane = tid & 31;
    int gid = lane >> 2, tid4 = lane & 3;
    int msub = (w >> 2) * 32, nsub = (w & 3) * 64;
    int row0 = blockIdx.x * 64;

    float acc[2][8][4];
    #pragma unroll
    for (int mf = 0; mf < 2; mf++)
        #pragma unroll
        for (int nf = 0; nf < 8; nf++)
            #pragma unroll
            for (int q = 0; q < 4; q++) acc[mf][nf][q] = 0.f;

    sbc[tid] = g_bcomb[tid];

    for (int k0 = 0; k0 < 128; k0 += 32) {
        // stage A: 64x32
        {
            int r = tid >> 2, cs = (tid & 3) * 8;
            int gr = row0 + r;
            float4 va = make_float4(0.f,0.f,0.f,0.f), vb = va;
            if (gr < NN) {
                va = *(const float4*)(g_magg + (size_t)gr*128 + k0 + cs);
                vb = *(const float4*)(g_magg + (size_t)gr*128 + k0 + cs + 4);
            }
            As[r][cs+0] = to_tf32(va.x); As[r][cs+1] = to_tf32(va.y);
            As[r][cs+2] = to_tf32(va.z); As[r][cs+3] = to_tf32(va.w);
            As[r][cs+4] = to_tf32(vb.x); As[r][cs+5] = to_tf32(vb.y);
            As[r][cs+6] = to_tf32(vb.z); As[r][cs+7] = to_tf32(vb.w);
        }
        // stage B: 32x256
        {
            int r = tid >> 3, cs = (tid & 7) * 32;
            #pragma unroll
            for (int i = 0; i < 8; i++) {
                float4 v = *(const float4*)(g_Wcomb + (size_t)(k0+r)*256 + cs + i*4);
                Bs[r][cs+i*4+0] = to_tf32(v.x); Bs[r][cs+i*4+1] = to_tf32(v.y);
                Bs[r][cs+i*4+2] = to_tf32(v.z); Bs[r][cs+i*4+3] = to_tf32(v.w);
            }
        }
        __syncthreads();
        #pragma unroll
        for (int kk = 0; kk < 4; kk++) {
            int kb = kk*8;
            uint32_t a[2][4];
            #pragma unroll
            for (int mf = 0; mf < 2; mf++) {
                int m = msub + mf*16 + gid;
                a[mf][0] = fbits(As[m  ][kb + tid4    ]);
                a[mf][1] = fbits(As[m+8][kb + tid4    ]);
                a[mf][2] = fbits(As[m  ][kb + tid4 + 4]);
                a[mf][3] = fbits(As[m+8][kb + tid4 + 4]);
            }
            #pragma unroll
            for (int nf = 0; nf < 8; nf++) {
                int c = nsub + nf*8 + gid;
                uint32_t b0 = fbits(Bs[kb + tid4    ][c]);
                uint32_t b1 = fbits(Bs[kb + tid4 + 4][c]);
                mma_tf32(acc[0][nf], a[0][0], a[0][1], a[0][2], a[0][3], b0, b1);
                mma_tf32(acc[1][nf], a[1][0], a[1][1], a[1][2], a[1][3], b0, b1);
            }
        }
        __syncthreads();
    }

    // bias
    #pragma unroll
    for (int mf = 0; mf < 2; mf++)
        #pragma unroll
        for (int nf = 0; nf < 8; nf++) {
            int c0 = nsub + nf*8 + 2*tid4;
            acc[mf][nf][0] += sbc[c0];   acc[mf][nf][1] += sbc[c0+1];
            acc[mf][nf][2] += sbc[c0];   acc[mf][nf][3] += sbc[c0+1];
        }
    // row max (partial per warp)
    #pragma unroll
    for (int mf = 0; mf < 2; mf++) {
        float mA = -FLT_MAX, mB = -FLT_MAX;
        #pragma unroll
        for (int nf = 0; nf < 8; nf++) {
            mA = fmaxf(mA, fmaxf(acc[mf][nf][0], acc[mf][nf][1]));
            mB = fmaxf(mB, fmaxf(acc[mf][nf][2], acc[mf][nf][3]));
        }
        mA = fmaxf(mA, __shfl_xor_sync(0xffffffffu, mA, 1));
        mA = fmaxf(mA, __shfl_xor_sync(0xffffffffu, mA, 2));
        mB = fmaxf(mB, __shfl_xor_sync(0xffffffffu, mB, 1));
        mB = fmaxf(mB, __shfl_xor_sync(0xffffffffu, mB, 2));
        if (tid4 == 0) {
            redmax[msub + mf*16 + gid    ][w & 3] = mA;
            redmax[msub + mf*16 + gid + 8][w & 3] = mB;
        }
    }
    __syncthreads();
    float rmax[2][2];
    #pragma unroll
    for (int mf = 0; mf < 2; mf++)
        #pragma unroll
        for (int h = 0; h < 2; h++) {
            int rl = msub + mf*16 + gid + h*8;
            rmax[mf][h] = fmaxf(fmaxf(redmax[rl][0], redmax[rl][1]),
                                fmaxf(redmax[rl][2], redmax[rl][3]));
        }
    // exp + row sum (partial per warp)
    #pragma unroll
    for (int mf = 0; mf < 2; mf++) {
        float sA = 0.f, sB = 0.f;
        #pragma unroll
        for (int nf = 0; nf < 8; nf++) {
            acc[mf][nf][0] = __expf(acc[mf][nf][0] - rmax[mf][0]);
            acc[mf][nf][1] = __expf(acc[mf][nf][1] - rmax[mf][0]);
            acc[mf][nf][2] = __expf(acc[mf][nf][2] - rmax[mf][1]);
            acc[mf][nf][3] = __expf(acc[mf][nf][3] - rmax[mf][1]);
            sA += acc[mf][nf][0] + acc[mf][nf][1];
            sB += acc[mf][nf][2] + acc[mf][nf][3];
        }
        sA += __shfl_xor_sync(0xffffffffu, sA, 1);
        sA += __shfl_xor_sync(0xffffffffu, sA, 2);
        sB += __shfl_xor_sync(0xffffffffu, sB, 1);
        sB += __shfl_xor_sync(0xffffffffu, sB, 2);
        if (tid4 == 0) {
            redsum[msub + mf*16 + gid    ][w & 3] = sA;
            redsum[msub + mf*16 + gid + 8][w & 3] = sB;
        }
    }
    __syncthreads();
    #pragma unroll
    for (int mf = 0; mf < 2; mf++) {
        #pragma unroll
        for (int h = 0; h < 2; h++) {
            int rl = msub + mf*16 + gid + h*8;
            int gr = row0 + rl;
            if (gr >= NN) continue;
            float rinv = 1.0f / (redsum[rl][0] + redsum[rl][1] + redsum[rl][2] + redsum[rl][3]);
            #pragma unroll
            for (int nf = 0; nf < 8; nf++) {
                int c0 = nsub + nf*8 + 2*tid4;
                float2 o;
                o.x = acc[mf][nf][h*2+0] * rinv;
                o.y = acc[mf][nf][h*2+1] * rinv;
                *(float2*)(s1out + (size_t)gr*256 + c0) = o;
            }
        }
    }
}

// ============================ T partials = s1^T @ m2 : TF32 MMA ============================
// grid (CHUNKS, 2): block = (K chunk, m-tile of 128). 8 warps: warp tile 32x64.
__global__ __launch_bounds__(256) void k_atb(const float* __restrict__ S)
{
    __shared__ float Ss[32][136];   // [k][m], ld 136: conflict-free
    __shared__ float Zs[32][136];   // [k][n]

    int tid = threadIdx.x;
    int w = tid >> 5, lane = tid & 31;
    int gid = lane >> 2, tid4 = lane & 3;
    int msub = (w >> 1) * 32, nsub = (w & 1) * 64;
    int chunk = blockIdx.x, mt = blockIdx.y;
    int m0 = mt * 128;
    int k_begin = (int)((long long)NN * chunk / CHUNKS);
    int k_end   = (int)((long long)NN * (chunk+1) / CHUNKS);

    float acc[2][8][4];
    #pragma unroll
    for (int mf = 0; mf < 2; mf++)
        #pragma unroll
        for (int nf = 0; nf < 8; nf++)
            #pragma unroll
            for (int q = 0; q < 4; q++) acc[mf][nf][q] = 0.f;
    float colacc = 0.f;

    for (int k0 = k_begin; k0 < k_end; k0 += 32) {
        int r = tid >> 3, seg = (tid & 7) * 16;
        int gk = k0 + r;
        // stage s1 slab (cols m0..m0+127) and m2 slab
        #pragma unroll
        for (int i = 0; i < 4; i++) {
            float4 v = make_float4(0.f,0.f,0.f,0.f);
            if (gk < k_end) v = *(const float4*)(S + (size_t)gk*256 + m0 + seg + i*4);
            Ss[r][seg+i*4+0] = to_tf32(v.x); Ss[r][seg+i*4+1] = to_tf32(v.y);
            Ss[r][seg+i*4+2] = to_tf32(v.z); Ss[r][seg+i*4+3] = to_tf32(v.w);
        }
        #pragma unroll
        for (int i = 0; i < 4; i++) {
            float4 v = make_float4(0.f,0.f,0.f,0.f);
            if (gk < k_end) v = *(const float4*)(g_m2 + (size_t)gk*128 + seg + i*4);
            Zs[r][seg+i*4+0] = to_tf32(v.x); Zs[r][seg+i*4+1] = to_tf32(v.y);
            Zs[r][seg+i*4+2] = to_tf32(v.z); Zs[r][seg+i*4+3] = to_tf32(v.w);
        }
        __syncthreads();
        if (tid < 128) {
            #pragma unroll 8
            for (int rr = 0; rr < 32; rr++) colacc += Ss[rr][tid];
        }
        #pragma unroll
        for (int kk = 0; kk < 4; kk++) {
            int kb = kk*8;
            uint32_t a[2][4];
            #pragma unroll
            for (int mf = 0; mf < 2; mf++) {
                int m = msub + mf*16 + gid;
                a[mf][0] = fbits(Ss[kb + tid4    ][m  ]);
                a[mf][1] = fbits(Ss[kb + tid4    ][m+8]);
                a[mf][2] = fbits(Ss[kb + tid4 + 4][m  ]);
                a[mf][3] = fbits(Ss[kb + tid4 + 4][m+8]);
            }
            #pragma unroll
            for (int nf = 0; nf < 8; nf++) {
                int c = nsub + nf*8 + gid;
                uint32_t b0 = fbits(Zs[kb + tid4    ][c]);
                uint32_t b1 = fbits(Zs[kb + tid4 + 4][c]);
                mma_tf32(acc[0][nf], a[0][0], a[0][1], a[0][2], a[0][3], b0, b1);
                mma_tf32(acc[1][nf], a[1][0], a[1][1], a[1][2], a[1][3], b0, b1);
            }
        }
        __syncthreads();
    }

    float* P = g_part + (size_t)(chunk*2 + mt) * 16384;
    #pragma unroll
    for (int mf = 0; mf < 2; mf++) {
        int mloc = msub + mf*16 + gid;
        #pragma unroll
        for (int nf = 0; nf < 8; nf++) {
            int c0 = nsub + nf*8 + 2*tid4;
            float2 lo; lo.x = acc[mf][nf][0]; lo.y = acc[mf][nf][1];
            float2 hi; hi.x = acc[mf][nf][2]; hi.y = acc[mf][nf][3];
            *(float2*)(P + (size_t)mloc*128 + c0)     = lo;
            *(float2*)(P + (size_t)(mloc+8)*128 + c0) = hi;
        }
    }
    if (tid < 128) atomicAdd(&g_colsum[m0 + tid], colacc);
}

// ============================ x1 = T@We1 + colsum (x) be1 (reduce partials) ============================
__global__ __launch_bounds__(256) void k_x1(
    const float* __restrict__ We1, const float* __restrict__ be1,
    float* __restrict__ out)
{
    __shared__ float sT[2][128];
    int t = threadIdx.x;
    int rowsel = t >> 7;
    int d = t & 127;
    int k = blockIdx.x*2 + rowsel;     // 0..255
    int mt = k >> 7, mloc = k & 127;
    float s = 0.f;
    #pragma unroll 2
    for (int c = 0; c < CHUNKS; c++)
        s += g_part[(size_t)(c*2 + mt)*16384 + (size_t)mloc*128 + d];
    sT[rowsel][d] = s;
    __syncthreads();
    if (t < 128) atomicAdd(&g_sumT[t], sT[0][t] + sT[1][t]);
    float colk = g_colsum[k];
    float acc = 0.f;
    #pragma unroll 8
    for (int e = 0; e < 128; e++) acc = fmaf(sT[rowsel][e], We1[e*128 + d], acc);
    out[OFF_X1 + k*128 + d] = acc + colk * be1[d];
}

// ============================ analytic coarse tail ============================
__global__ __launch_bounds__(256) void k_tail(
    const float* __restrict__ We1, const float* __restrict__ be1,
    const float* __restrict__ We2, const float* __restrict__ be2,
    const float* __restrict__ Wa2, const float* __restrict__ ba2,
    float* __restrict__ out)
{
    __shared__ float sumT[128];
    __shared__ float meanx1[128];
    __shared__ float meanvec[128];
    __shared__ float s2row[32];
    __shared__ float sc[256];
    int t = threadIdx.x;

    if (t < 128) sumT[t] = g_sumT[t];
    sc[t] = g_colsum[t];
    __syncthreads();
    #pragma unroll
    for (int st = 128; st > 0; st >>= 1) {
        if (t < st) sc[t] += sc[t+st];
        __syncthreads();
    }
    float sumcol = sc[0];
    if (t < 128) {
        float s = 0.f;
        for (int e = 0; e < 128; e++) s = fmaf(sumT[e], We1[e*128 + t], s);
        meanx1[t] = (s + sumcol*be1[t]) * (1.0f/256.0f);
    }
    __syncthreads();
    if (t < 128) {
        float s = 0.f;
        for (int e = 0; e < 128; e++) s = fmaf(meanx1[e], We2[e*128 + t], s);
        meanvec[t] = s + be2[t];
    }
    __syncthreads();
    if (t < 32) {
        float s = 0.f;
        for (int d = 0; d < 128; d++) s = fmaf(meanvec[d], Wa2[d*32 + t], s);
        float v = s + ba2[t];
        float mx = v;
        #pragma unroll
        for (int o = 16; o > 0; o >>= 1) mx = fmaxf(mx, __shfl_xor_sync(0xffffffffu, mx, o));
        float ex = __expf(v - mx);
        float sm = ex;
        #pragma unroll
        for (int o = 16; o > 0; o >>= 1) sm += __shfl_xor_sync(0xffffffffu, sm, o);
        s2row[t] = ex / sm;
    }
    __syncthreads();
    for (int i = t; i < 256*32; i += 256) out[OFF_S2 + i] = s2row[i & 31];
    if (t < 32) out[OFF_A1 + t] = 1.0f;
    for (int i = t; i < 32*128; i += 256)
        out[OFF_X2 + i] = 256.0f * s2row[i >> 7] * meanvec[i & 127];
    if (t == 0) {
        float s = 0.f;
        for (int d = 0; d < 128; d++) s += meanvec[d];
        out[OFF_E0] = s * (1.0f/16.0f);
    }
}

// ============================ launch ============================
extern "C" void kernel_launch(void* const* d_in, const int* in_sizes, int n_in,
                              void* d_out, int out_size)
{
    const float* feature = (const float*)d_in[0];
    const int*   eidx    = (const int*)d_in[1];
    const int*   src     = eidx;
    const int*   dst     = eidx + EE;
    const float* Wf   = (const float*)d_in[2];
    const float* bf   = (const float*)d_in[3];
    const float* We1  = (const float*)d_in[4];
    const float* be1  = (const float*)d_in[5];
    const float* Wa1  = (const float*)d_in[6];
    const float* ba1  = (const float*)d_in[7];
    const float* attW1 = (const float*)d_in[8];
    const float* attb1 = (const float*)d_in[9];
    const float* We2  = (const float*)d_in[10];
    const float* be2  = (const float*)d_in[11];
    const float* Wa2  = (const float*)d_in[12];
    const float* ba2  = (const float*)d_in[13];
    float* out = (float*)d_out;

    void *deg_p, *colsum_p, *sumT_p;
    float *zf_p, *x_p, *m2_p;
    cudaGetSymbolAddress(&deg_p,    g_deg);
    cudaGetSymbolAddress(&colsum_p, g_colsum);
    cudaGetSymbolAddress(&sumT_p,   g_sumT);
    cudaGetSymbolAddress((void**)&zf_p, g_zf);
    cudaGetSymbolAddress((void**)&x_p,  g_x);
    cudaGetSymbolAddress((void**)&m2_p, g_m2);

    cudaStream_t side = g_sr.s;

    // ---- fork: side stream does dense prep (independent of the graph) ----
    cudaEventRecord(g_sr.fork, 0);
    cudaStreamWaitEvent(side, g_sr.fork, 0);
    cudaMemsetAsync(colsum_p, 0, CC1*sizeof(float), side);
    cudaMemsetAsync(sumT_p,   0, DD*sizeof(float), side);
    k_gemm_zf<<<(NN+127)/128, 256, 0, side>>>(feature, Wf, bf, zf_p);
    k_fold<<<129, 256, 0, side>>>(We1, be1, Wa1, ba1, attW1);
    cudaEventRecord(g_sr.join, side);

    // ---- main stream: graph build ----
    cudaMemsetAsync(deg_p, 0, NN*sizeof(int));
    k_count<<<(EE + 255)/256, 256>>>(dst);
    k_scanall<<<NB, 128>>>();
    k_fill<<<(EE + 255)/256, 256>>>(src, dst);

    // ---- join, then serial chain ----
    cudaStreamWaitEvent(0, g_sr.join, 0);

    // x = normalize(segmean(zf)); embed3 = x
    k_segmean<true,false><<<(NN+7)/8, 256>>>(zf_p, x_p, out + OFF_E3);
    // m2 = segmean(x) + fused a_src/a_dst
    k_segmean<false,true><<<(NN+7)/8, 256>>>(x_p, m2_p, (float*)0);
    // GAT aggregation on 128-wide m2
    k_gatagg<<<(NN+7)/8, 256>>>(attb1);
    // s1 = softmax(magg@W_comb + b_comb)  [TF32 MMA]
    k_gemm_s1<<<(NN+63)/64, 256>>>(out + OFF_S1);
    // T partials = s1^T @ m2 + colsum  [TF32 MMA, 148 blocks]
    k_atb<<<dim3(CHUNKS, 2), 256>>>(out + OFF_S1);
    // x1 = T@We1 + colsum (x) be1 (+ sumT accumulation)
    k_x1<<<128, 256>>>(We1, be1, out);
    // analytic coarse level
    k_tail<<<1, 256>>>(We1, be1, We2, be2, Wa2, ba2, out);
}

// round 7
// speedup vs baseline: 2.6244x; 1.0673x over previous
#include <cuda_runtime.h>
#include <math.h>
#include <float.h>
#include <stdint.h>

#define NN   20000
#define EE   340000
#define DD   128
#define CC1  256
#define NB   157      // ceil(NN/128)
#define CHUNKS 74     // at_b split-K chunks (74*2 = 148 blocks = 1/SM)

// ---- output layout (element offsets into float* d_out) ----
#define OFF_S1  0
#define OFF_S2  (NN*CC1)
#define OFF_A1  (OFF_S2 + 256*32)
#define OFF_E3  (OFF_A1 + 32)
#define OFF_X1  (OFF_E3 + NN*DD)
#define OFF_X2  (OFF_X1 + 256*128)
#define OFF_E0  (OFF_X2 + 32*128)

// ---- scratch ----
__device__ float g_zf[NN*DD];
__device__ float g_x[NN*DD];
__device__ float g_m2[NN*DD];
__device__ float g_magg[NN*DD];
__device__ float g_asrc[NN];
__device__ float g_adst[NN];
__device__ int   g_deg[NN];
__device__ int   g_off[NN+1];
__device__ int   g_cur[NN];
__device__ int   g_csrc[EE];
__device__ float g_Wcomb[DD*CC1];        // 128x256
__device__ float g_bcomb[CC1];
__device__ float g_us[DD];
__device__ float g_ud[DD];
__device__ float g_cs[2];
__device__ float g_part[CHUNKS*2*128*128]; // at_b per-block partials (9.7MB)
__device__ float g_colsum[CC1];
__device__ float g_sumT[DD];

// ---- persistent side stream + events ----
struct SideRes {
    cudaStream_t s;
    cudaEvent_t fork, join;
    SideRes() {
        cudaStreamCreateWithFlags(&s, cudaStreamNonBlocking);
        cudaEventCreateWithFlags(&fork, cudaEventDisableTiming);
        cudaEventCreateWithFlags(&join, cudaEventDisableTiming);
    }
};
static SideRes g_sr;

// ---- tf32 helpers ----
__device__ __forceinline__ float to_tf32(float x) {
    float r;
    asm("cvt.rna.tf32.f32 %0, %1;" : "=f"(r) : "f"(x));
    return r;
}
__device__ __forceinline__ void mma_tf32(float c[4],
    uint32_t a0, uint32_t a1, uint32_t a2, uint32_t a3,
    uint32_t b0, uint32_t b1)
{
    asm volatile(
        "mma.sync.aligned.m16n8k8.row.col.f32.tf32.tf32.f32 "
        "{%0,%1,%2,%3},{%4,%5,%6,%7},{%8,%9},{%0,%1,%2,%3};\n"
        : "+f"(c[0]), "+f"(c[1]), "+f"(c[2]), "+f"(c[3])
        : "r"(a0), "r"(a1), "r"(a2), "r"(a3), "r"(b0), "r"(b1));
}
__device__ __forceinline__ uint32_t fbits(float x) { return __float_as_uint(x); }

// ============================ graph build ============================
__global__ void k_count(const int* __restrict__ dst) {
    int e = blockIdx.x*blockDim.x + threadIdx.x;
    if (e < EE) atomicAdd(&g_deg[dst[e]], 1);
}

__global__ void k_scanall() {   // NB blocks x 128
    __shared__ int sh[128];
    int t = threadIdx.x, b = blockIdx.x;
    int base = 0;
    for (int i = t; i < b*128; i += 128) base += g_deg[i];
    sh[t] = base; __syncthreads();
    #pragma unroll
    for (int st = 64; st > 0; st >>= 1) {
        if (t < st) sh[t] += sh[t+st];
        __syncthreads();
    }
    base = sh[0];
    __syncthreads();
    int i = b*128 + t;
    int d = (i < NN) ? g_deg[i] : 0;
    sh[t] = d; __syncthreads();
    #pragma unroll
    for (int off = 1; off < 128; off <<= 1) {
        int v = (t >= off) ? sh[t-off] : 0;
        __syncthreads();
        sh[t] += v;
        __syncthreads();
    }
    int excl = base + sh[t] - d;
    if (i < NN) { g_off[i] = excl; g_cur[i] = excl; }
    if (i == 0) g_off[NN] = EE;
}

__global__ void k_fill(const int* __restrict__ src, const int* __restrict__ dst) {
    int e = blockIdx.x*blockDim.x + threadIdx.x;
    if (e < EE) {
        int p = atomicAdd(&g_cur[dst[e]], 1);
        g_csrc[p] = src[e];
    }
}

// ============================ weight folding ============================
__global__ __launch_bounds__(256) void k_fold(
    const float* __restrict__ We1, const float* __restrict__ be1,
    const float* __restrict__ Wa1, const float* __restrict__ ba1,
    const float* __restrict__ attW)
{
    int b = blockIdx.x, t = threadIdx.x;
    if (b < 128) {
        __shared__ float sWe[128];
        if (t < 128) sWe[t] = We1[b*128 + t];
        __syncthreads();
        float acc = 0.f;
        #pragma unroll 8
        for (int k = 0; k < 128; k++) acc = fmaf(sWe[k], Wa1[k*256 + t], acc);
        g_Wcomb[b*256 + t] = acc;
    } else {
        __shared__ float ts[128], td[128], bc[256];
        if (t < 128) {
            float s1v = 0.f, s2v = 0.f;
            for (int c = 0; c < 256; c++) {
                float w = Wa1[t*256 + c];
                s1v = fmaf(w, attW[c], s1v);
                s2v = fmaf(w, attW[256 + c], s2v);
            }
            ts[t] = s1v; td[t] = s2v;
        }
        {
            float s = 0.f;
            for (int e = 0; e < 128; e++) s = fmaf(be1[e], Wa1[e*256 + t], s);
            bc[t] = s + ba1[t];
            g_bcomb[t] = bc[t];
        }
        __syncthreads();
        if (t < 128) {
            float u1 = 0.f, u2 = 0.f;
            for (int e = 0; e < 128; e++) {
                float w = We1[t*128 + e];
                u1 = fmaf(w, ts[e], u1);
                u2 = fmaf(w, td[e], u2);
            }
            g_us[t] = u1; g_ud[t] = u2;
        }
        if (t == 0) {
            float c1v = 0.f, c2v = 0.f;
            for (int c = 0; c < 256; c++) {
                c1v = fmaf(bc[c], attW[c], c1v);
                c2v = fmaf(bc[c], attW[256 + c], c2v);
            }
            g_cs[0] = c1v; g_cs[1] = c2v;
        }
    }
}

// ============================ zf = feature@Wf + bf : TF32 MMA ============================
// block tile 128(m) x 128(n), K=128 in 4 slabs of 32. 8 warps: warp tile 32x64.
__global__ __launch_bounds__(256) void k_gemm_zf(
    const float* __restrict__ A, const float* __restrict__ B,
    const float* __restrict__ bias, float* __restrict__ C)
{
    __shared__ float As[128][36];
    __shared__ float Bs[32][136];
    int tid = threadIdx.x;
    int w = tid >> 5, lane = tid & 31;
    int gid = lane >> 2, tid4 = lane & 3;
    int msub = (w >> 1) * 32, nsub = (w & 1) * 64;
    int row0 = blockIdx.x * 128;

    float acc[2][8][4];
    #pragma unroll
    for (int mf = 0; mf < 2; mf++)
        #pragma unroll
        for (int nf = 0; nf < 8; nf++)
            #pragma unroll
            for (int q = 0; q < 4; q++) acc[mf][nf][q] = 0.f;

    for (int k0 = 0; k0 < 128; k0 += 32) {
        {   // stage A: 128 x 32
            int r = tid >> 1, cs = (tid & 1) * 16;
            int gr = row0 + r;
            #pragma unroll
            for (int i = 0; i < 4; i++) {
                float4 v = make_float4(0.f,0.f,0.f,0.f);
                if (gr < NN) v = *(const float4*)(A + (size_t)gr*128 + k0 + cs + i*4);
                As[r][cs+i*4+0] = to_tf32(v.x); As[r][cs+i*4+1] = to_tf32(v.y);
                As[r][cs+i*4+2] = to_tf32(v.z); As[r][cs+i*4+3] = to_tf32(v.w);
            }
        }
        {   // stage B: 32 x 128
            int r = tid >> 3, cs = (tid & 7) * 16;
            #pragma unroll
            for (int i = 0; i < 4; i++) {
                float4 v = *(const float4*)(B + (size_t)(k0+r)*128 + cs + i*4);
                Bs[r][cs+i*4+0] = to_tf32(v.x); Bs[r][cs+i*4+1] = to_tf32(v.y);
                Bs[r][cs+i*4+2] = to_tf32(v.z); Bs[r][cs+i*4+3] = to_tf32(v.w);
            }
        }
        __syncthreads();
        #pragma unroll
        for (int kk = 0; kk < 4; kk++) {
            int kb = kk*8;
            uint32_t a[2][4];
            #pragma unroll
            for (int mf = 0; mf < 2; mf++) {
                int m = msub + mf*16 + gid;
                a[mf][0] = fbits(As[m  ][kb + tid4    ]);
                a[mf][1] = fbits(As[m+8][kb + tid4    ]);
                a[mf][2] = fbits(As[m  ][kb + tid4 + 4]);
                a[mf][3] = fbits(As[m+8][kb + tid4 + 4]);
            }
            #pragma unroll
            for (int nf = 0; nf < 8; nf++) {
                int c = nsub + nf*8 + gid;
                uint32_t b0 = fbits(Bs[kb + tid4    ][c]);
                uint32_t b1 = fbits(Bs[kb + tid4 + 4][c]);
                mma_tf32(acc[0][nf], a[0][0], a[0][1], a[0][2], a[0][3], b0, b1);
                mma_tf32(acc[1][nf], a[1][0], a[1][1], a[1][2], a[1][3], b0, b1);
            }
        }
        __syncthreads();
    }
    #pragma unroll
    for (int mf = 0; mf < 2; mf++) {
        int rlo = row0 + msub + mf*16 + gid;
        int rhi = rlo + 8;
        #pragma unroll
        for (int nf = 0; nf < 8; nf++) {
            int c0 = nsub + nf*8 + 2*tid4;
            float b0v = bias[c0], b1v = bias[c0+1];
            if (rlo < NN) {
                float2 o; o.x = acc[mf][nf][0]+b0v; o.y = acc[mf][nf][1]+b1v;
                *(float2*)(C + (size_t)rlo*128 + c0) = o;
            }
            if (rhi < NN) {
                float2 o; o.x = acc[mf][nf][2]+b0v; o.y = acc[mf][nf][3]+b1v;
                *(float2*)(C + (size_t)rhi*128 + c0) = o;
            }
        }
    }
}

// ============================ segment mean (warp/node, shfl-batched gathers) ============================
template<bool NORM, bool DOTS>
__global__ __launch_bounds__(256) void k_segmean(
    const float* __restrict__ zin, float* __restrict__ out, float* __restrict__ out2)
{
    int node = blockIdx.x*8 + (threadIdx.x >> 5);
    if (node >= NN) return;
    int lane = threadIdx.x & 31;
    int e0 = g_off[node], e1 = g_off[node+1];
    float4 acc = make_float4(0.f,0.f,0.f,0.f);
    const float* zl = zin + lane*4;

    for (int base = e0; base < e1; base += 32) {
        int j = base + lane;
        int myidx = (j < e1) ? g_csrc[j] : 0;
        int cnt = min(32, e1 - base);
        int t = 0;
        for (; t + 4 <= cnt; t += 4) {
            int s0 = __shfl_sync(0xffffffffu, myidx, t);
            int s1i = __shfl_sync(0xffffffffu, myidx, t+1);
            int s2 = __shfl_sync(0xffffffffu, myidx, t+2);
            int s3 = __shfl_sync(0xffffffffu, myidx, t+3);
            float4 v0 = *(const float4*)(zl + (size_t)s0*DD);
            float4 v1 = *(const float4*)(zl + (size_t)s1i*DD);
            float4 v2 = *(const float4*)(zl + (size_t)s2*DD);
            float4 v3 = *(const float4*)(zl + (size_t)s3*DD);
            acc.x += (v0.x+v1.x) + (v2.x+v3.x);
            acc.y += (v0.y+v1.y) + (v2.y+v3.y);
            acc.z += (v0.z+v1.z) + (v2.z+v3.z);
            acc.w += (v0.w+v1.w) + (v2.w+v3.w);
        }
        for (; t < cnt; t++) {
            int sb = __shfl_sync(0xffffffffu, myidx, t);
            float4 v = *(const float4*)(zl + (size_t)sb*DD);
            acc.x += v.x; acc.y += v.y; acc.z += v.z; acc.w += v.w;
        }
    }
    float inv = 1.0f / (float)(e1 - e0);
    acc.x *= inv; acc.y *= inv; acc.z *= inv; acc.w *= inv;
    if (NORM) {
        float ss = acc.x*acc.x + acc.y*acc.y + acc.z*acc.z + acc.w*acc.w;
        #pragma unroll
        for (int o = 16; o > 0; o >>= 1) ss += __shfl_xor_sync(0xffffffffu, ss, o);
        float r = 1.0f / fmaxf(sqrtf(ss), 1e-12f);
        acc.x *= r; acc.y *= r; acc.z *= r; acc.w *= r;
    }
    *(float4*)(out + (size_t)node*DD + lane*4) = acc;
    if (out2) *(float4*)(out2 + (size_t)node*DD + lane*4) = acc;
    if (DOTS) {
        float4 us4 = *(const float4*)(g_us + lane*4);
        float4 ud4 = *(const float4*)(g_ud + lane*4);
        float as = acc.x*us4.x + acc.y*us4.y + acc.z*us4.z + acc.w*us4.w;
        float ad = acc.x*ud4.x + acc.y*ud4.y + acc.z*ud4.z + acc.w*ud4.w;
        #pragma unroll
        for (int o = 16; o > 0; o >>= 1) {
            as += __shfl_xor_sync(0xffffffffu, as, o);
            ad += __shfl_xor_sync(0xffffffffu, ad, o);
        }
        if (lane == 0) { g_asrc[node] = as + g_cs[0]; g_adst[node] = ad + g_cs[1]; }
    }
}

// ============================ GAT aggregation (warp/node, shfl-batched gathers) ============================
__global__ __launch_bounds__(256) void k_gatagg(const float* __restrict__ attb)
{
    int node = blockIdx.x*8 + (threadIdx.x >> 5);
    if (node >= NN) return;
    int lane = threadIdx.x & 31;
    int e0 = g_off[node], e1 = g_off[node+1];
    float adb = g_adst[node] + attb[0];
    const float* zl = g_m2 + lane*4;

    float mx = -FLT_MAX;
    for (int j = e0 + lane; j < e1; j += 32) {
        float e = g_asrc[g_csrc[j]] + adb;
        e = (e > 0.f) ? e : 0.01f*e;
        mx = fmaxf(mx, e);
    }
    #pragma unroll
    for (int o = 16; o > 0; o >>= 1) mx = fmaxf(mx, __shfl_xor_sync(0xffffffffu, mx, o));

    float4 acc = make_float4(0.f,0.f,0.f,0.f);
    float denom = 0.f;
    for (int base = e0; base < e1; base += 32) {
        int j = base + lane;
        int s = 0; float a = 0.f;
        if (j < e1) {
            s = g_csrc[j];
            float e = g_asrc[s] + adb;
            e = (e > 0.f) ? e : 0.01f*e;
            a = __expf(e - mx);
            denom += a;
        }
        int cnt = min(32, e1 - base);
        int t = 0;
        for (; t + 4 <= cnt; t += 4) {
            float a0 = __shfl_sync(0xffffffffu, a, t);
            float a1 = __shfl_sync(0xffffffffu, a, t+1);
            float a2 = __shfl_sync(0xffffffffu, a, t+2);
            float a3 = __shfl_sync(0xffffffffu, a, t+3);
            int   s0 = __shfl_sync(0xffffffffu, s, t);
            int   s1i = __shfl_sync(0xffffffffu, s, t+1);
            int   s2 = __shfl_sync(0xffffffffu, s, t+2);
            int   s3 = __shfl_sync(0xffffffffu, s, t+3);
            float4 v0 = *(const float4*)(zl + (size_t)s0*DD);
            float4 v1 = *(const float4*)(zl + (size_t)s1i*DD);
            float4 v2 = *(const float4*)(zl + (size_t)s2*DD);
            float4 v3 = *(const float4*)(zl + (size_t)s3*DD);
            acc.x = fmaf(a0, v0.x, fmaf(a1, v1.x, fmaf(a2, v2.x, fmaf(a3, v3.x, acc.x))));
            acc.y = fmaf(a0, v0.y, fmaf(a1, v1.y, fmaf(a2, v2.y, fmaf(a3, v3.y, acc.y))));
            acc.z = fmaf(a0, v0.z, fmaf(a1, v1.z, fmaf(a2, v2.z, fmaf(a3, v3.z, acc.z))));
            acc.w = fmaf(a0, v0.w, fmaf(a1, v1.w, fmaf(a2, v2.w, fmaf(a3, v3.w, acc.w))));
        }
        for (; t < cnt; t++) {
            float ab = __shfl_sync(0xffffffffu, a, t);
            int   sb = __shfl_sync(0xffffffffu, s, t);
            float4 v = *(const float4*)(zl + (size_t)sb*DD);
            acc.x = fmaf(ab, v.x, acc.x); acc.y = fmaf(ab, v.y, acc.y);
            acc.z = fmaf(ab, v.z, acc.z); acc.w = fmaf(ab, v.w, acc.w);
        }
    }
    #pragma unroll
    for (int o = 16; o > 0; o >>= 1) denom += __shfl_xor_sync(0xffffffffu, denom, o);
    float r = 1.0f / denom;
    acc.x *= r; acc.y *= r; acc.z *= r; acc.w *= r;
    *(float4*)(g_magg + (size_t)node*DD + lane*4) = acc;
}

// ============================ s1 = softmax(magg@Wcomb + bcomb) : TF32 MMA ============================
__global__ __launch_bounds__(256) void k_gemm_s1(float* __restrict__ s1out)
{
    __shared__ float As[64][36];
    __shared__ float Bs[32][264];
    __shared__ float sbc[256];
    __shared__ float redmax[64][4];
    __shared__ float redsum[64][4];

    int tid = threadIdx.x;
    int w = tid >> 5, lane = tid & 31;
    int gid = lane >> 2, tid4 = lane & 3;
    int msub = (w >> 2) * 32, nsub = (w & 3) * 64;
    int row0 = blockIdx.x * 64;

    float acc[2][8][4];
    #pragma unroll
    for (int mf = 0; mf < 2; mf++)
        #pragma unroll
        for (int nf = 0; nf < 8; nf++)
            #pragma unroll
            for (int q = 0; q < 4; q++) acc[mf][nf][q] = 0.f;

    sbc[tid] = g_bcomb[tid];

    for (int k0 = 0; k0 < 128; k0 += 32) {
        {
            int r = tid >> 2, cs = (tid & 3) * 8;
            int gr = row0 + r;
            float4 va = make_float4(0.f,0.f,0.f,0.f), vb = va;
            if (gr < NN) {
                va = *(const float4*)(g_magg + (size_t)gr*128 + k0 + cs);
                vb = *(const float4*)(g_magg + (size_t)gr*128 + k0 + cs + 4);
            }
            As[r][cs+0] = to_tf32(va.x); As[r][cs+1] = to_tf32(va.y);
            As[r][cs+2] = to_tf32(va.z); As[r][cs+3] = to_tf32(va.w);
            As[r][cs+4] = to_tf32(vb.x); As[r][cs+5] = to_tf32(vb.y);
            As[r][cs+6] = to_tf32(vb.z); As[r][cs+7] = to_tf32(vb.w);
        }
        {
            int r = tid >> 3, cs = (tid & 7) * 32;
            #pragma unroll
            for (int i = 0; i < 8; i++) {
                float4 v = *(const float4*)(g_Wcomb + (size_t)(k0+r)*256 + cs + i*4);
                Bs[r][cs+i*4+0] = to_tf32(v.x); Bs[r][cs+i*4+1] = to_tf32(v.y);
                Bs[r][cs+i*4+2] = to_tf32(v.z); Bs[r][cs+i*4+3] = to_tf32(v.w);
            }
        }
        __syncthreads();
        #pragma unroll
        for (int kk = 0; kk < 4; kk++) {
            int kb = kk*8;
            uint32_t a[2][4];
            #pragma unroll
            for (int mf = 0; mf < 2; mf++) {
                int m = msub + mf*16 + gid;
                a[mf][0] = fbits(As[m  ][kb + tid4    ]);
                a[mf][1] = fbits(As[m+8][kb + tid4    ]);
                a[mf][2] = fbits(As[m  ][kb + tid4 + 4]);
                a[mf][3] = fbits(As[m+8][kb + tid4 + 4]);
            }
            #pragma unroll
            for (int nf = 0; nf < 8; nf++) {
                int c = nsub + nf*8 + gid;
                uint32_t b0 = fbits(Bs[kb + tid4    ][c]);
                uint32_t b1 = fbits(Bs[kb + tid4 + 4][c]);
                mma_tf32(acc[0][nf], a[0][0], a[0][1], a[0][2], a[0][3], b0, b1);
                mma_tf32(acc[1][nf], a[1][0], a[1][1], a[1][2], a[1][3], b0, b1);
            }
        }
        __syncthreads();
    }

    #pragma unroll
    for (int mf = 0; mf < 2; mf++)
        #pragma unroll
        for (int nf = 0; nf < 8; nf++) {
            int c0 = nsub + nf*8 + 2*tid4;
            acc[mf][nf][0] += sbc[c0];   acc[mf][nf][1] += sbc[c0+1];
            acc[mf][nf][2] += sbc[c0];   acc[mf][nf][3] += sbc[c0+1];
        }
    #pragma unroll
    for (int mf = 0; mf < 2; mf++) {
        float mA = -FLT_MAX, mB = -FLT_MAX;
        #pragma unroll
        for (int nf = 0; nf < 8; nf++) {
            mA = fmaxf(mA, fmaxf(acc[mf][nf][0], acc[mf][nf][1]));
            mB = fmaxf(mB, fmaxf(acc[mf][nf][2], acc[mf][nf][3]));
        }
        mA = fmaxf(mA, __shfl_xor_sync(0xffffffffu, mA, 1));
        mA = fmaxf(mA, __shfl_xor_sync(0xffffffffu, mA, 2));
        mB = fmaxf(mB, __shfl_xor_sync(0xffffffffu, mB, 1));
        mB = fmaxf(mB, __shfl_xor_sync(0xffffffffu, mB, 2));
        if (tid4 == 0) {
            redmax[msub + mf*16 + gid    ][w & 3] = mA;
            redmax[msub + mf*16 + gid + 8][w & 3] = mB;
        }
    }
    __syncthreads();
    float rmax[2][2];
    #pragma unroll
    for (int mf = 0; mf < 2; mf++)
        #pragma unroll
        for (int h = 0; h < 2; h++) {
            int rl = msub + mf*16 + gid + h*8;
            rmax[mf][h] = fmaxf(fmaxf(redmax[rl][0], redmax[rl][1]),
                                fmaxf(redmax[rl][2], redmax[rl][3]));
        }
    #pragma unroll
    for (int mf = 0; mf < 2; mf++) {
        float sA = 0.f, sB = 0.f;
        #pragma unroll
        for (int nf = 0; nf < 8; nf++) {
            acc[mf][nf][0] = __expf(acc[mf][nf][0] - rmax[mf][0]);
            acc[mf][nf][1] = __expf(acc[mf][nf][1] - rmax[mf][0]);
            acc[mf][nf][2] = __expf(acc[mf][nf][2] - rmax[mf][1]);
            acc[mf][nf][3] = __expf(acc[mf][nf][3] - rmax[mf][1]);
            sA += acc[mf][nf][0] + acc[mf][nf][1];
            sB += acc[mf][nf][2] + acc[mf][nf][3];
        }
        sA += __shfl_xor_sync(0xffffffffu, sA, 1);
        sA += __shfl_xor_sync(0xffffffffu, sA, 2);
        sB += __shfl_xor_sync(0xffffffffu, sB, 1);
        sB += __shfl_xor_sync(0xffffffffu, sB, 2);
        if (tid4 == 0) {
            redsum[msub + mf*16 + gid    ][w & 3] = sA;
            redsum[msub + mf*16 + gid + 8][w & 3] = sB;
        }
    }
    __syncthreads();
    #pragma unroll
    for (int mf = 0; mf < 2; mf++) {
        #pragma unroll
        for (int h = 0; h < 2; h++) {
            int rl = msub + mf*16 + gid + h*8;
            int gr = row0 + rl;
            if (gr >= NN) continue;
            float rinv = 1.0f / (redsum[rl][0] + redsum[rl][1] + redsum[rl][2] + redsum[rl][3]);
            #pragma unroll
            for (int nf = 0; nf < 8; nf++) {
                int c0 = nsub + nf*8 + 2*tid4;
                float2 o;
                o.x = acc[mf][nf][h*2+0] * rinv;
                o.y = acc[mf][nf][h*2+1] * rinv;
                *(float2*)(s1out + (size_t)gr*256 + c0) = o;
            }
        }
    }
}

// ============================ T partials = s1^T @ m2 : TF32 MMA ============================
__global__ __launch_bounds__(256) void k_atb(const float* __restrict__ S)
{
    __shared__ float Ss[32][136];
    __shared__ float Zs[32][136];

    int tid = threadIdx.x;
    int w = tid >> 5, lane = tid & 31;
    int gid = lane >> 2, tid4 = lane & 3;
    int msub = (w >> 1) * 32, nsub = (w & 1) * 64;
    int chunk = blockIdx.x, mt = blockIdx.y;
    int m0 = mt * 128;
    int k_begin = (int)((long long)NN * chunk / CHUNKS);
    int k_end   = (int)((long long)NN * (chunk+1) / CHUNKS);

    float acc[2][8][4];
    #pragma unroll
    for (int mf = 0; mf < 2; mf++)
        #pragma unroll
        for (int nf = 0; nf < 8; nf++)
            #pragma unroll
            for (int q = 0; q < 4; q++) acc[mf][nf][q] = 0.f;
    float colacc = 0.f;

    for (int k0 = k_begin; k0 < k_end; k0 += 32) {
        int r = tid >> 3, seg = (tid & 7) * 16;
        int gk = k0 + r;
        #pragma unroll
        for (int i = 0; i < 4; i++) {
            float4 v = make_float4(0.f,0.f,0.f,0.f);
            if (gk < k_end) v = *(const float4*)(S + (size_t)gk*256 + m0 + seg + i*4);
            Ss[r][seg+i*4+0] = to_tf32(v.x); Ss[r][seg+i*4+1] = to_tf32(v.y);
            Ss[r][seg+i*4+2] = to_tf32(v.z); Ss[r][seg+i*4+3] = to_tf32(v.w);
        }
        #pragma unroll
        for (int i = 0; i < 4; i++) {
            float4 v = make_float4(0.f,0.f,0.f,0.f);
            if (gk < k_end) v = *(const float4*)(g_m2 + (size_t)gk*128 + seg + i*4);
            Zs[r][seg+i*4+0] = to_tf32(v.x); Zs[r][seg+i*4+1] = to_tf32(v.y);
            Zs[r][seg+i*4+2] = to_tf32(v.z); Zs[r][seg+i*4+3] = to_tf32(v.w);
        }
        __syncthreads();
        if (tid < 128) {
            #pragma unroll 8
            for (int rr = 0; rr < 32; rr++) colacc += Ss[rr][tid];
        }
        #pragma unroll
        for (int kk = 0; kk < 4; kk++) {
            int kb = kk*8;
            uint32_t a[2][4];
            #pragma unroll
            for (int mf = 0; mf < 2; mf++) {
                int m = msub + mf*16 + gid;
                a[mf][0] = fbits(Ss[kb + tid4    ][m  ]);
                a[mf][1] = fbits(Ss[kb + tid4    ][m+8]);
                a[mf][2] = fbits(Ss[kb + tid4 + 4][m  ]);
                a[mf][3] = fbits(Ss[kb + tid4 + 4][m+8]);
            }
            #pragma unroll
            for (int nf = 0; nf < 8; nf++) {
                int c = nsub + nf*8 + gid;
                uint32_t b0 = fbits(Zs[kb + tid4    ][c]);
                uint32_t b1 = fbits(Zs[kb + tid4 + 4][c]);
                mma_tf32(acc[0][nf], a[0][0], a[0][1], a[0][2], a[0][3], b0, b1);
                mma_tf32(acc[1][nf], a[1][0], a[1][1], a[1][2], a[1][3], b0, b1);
            }
        }
        __syncthreads();
    }

    float* P = g_part + (size_t)(chunk*2 + mt) * 16384;
    #pragma unroll
    for (int mf = 0; mf < 2; mf++) {
        int mloc = msub + mf*16 + gid;
        #pragma unroll
        for (int nf = 0; nf < 8; nf++) {
            int c0 = nsub + nf*8 + 2*tid4;
            float2 lo; lo.x = acc[mf][nf][0]; lo.y = acc[mf][nf][1];
            float2 hi; hi.x = acc[mf][nf][2]; hi.y = acc[mf][nf][3];
            *(float2*)(P + (size_t)mloc*128 + c0)     = lo;
            *(float2*)(P + (size_t)(mloc+8)*128 + c0) = hi;
        }
    }
    if (tid < 128) atomicAdd(&g_colsum[m0 + tid], colacc);
}

// ============================ x1 = T@We1 + colsum (x) be1 (reduce partials) ============================
__global__ __launch_bounds__(256) void k_x1(
    const float* __restrict__ We1, const float* __restrict__ be1,
    float* __restrict__ out)
{
    __shared__ float sT[2][128];
    int t = threadIdx.x;
    int rowsel = t >> 7;
    int d = t & 127;
    int k = blockIdx.x*2 + rowsel;
    int mt = k >> 7, mloc = k & 127;
    float s = 0.f;
    #pragma unroll 2
    for (int c = 0; c < CHUNKS; c++)
        s += g_part[(size_t)(c*2 + mt)*16384 + (size_t)mloc*128 + d];
    sT[rowsel][d] = s;
    __syncthreads();
    if (t < 128) atomicAdd(&g_sumT[t], sT[0][t] + sT[1][t]);
    float colk = g_colsum[k];
    float acc = 0.f;
    #pragma unroll 8
    for (int e = 0; e < 128; e++) acc = fmaf(sT[rowsel][e], We1[e*128 + d], acc);
    out[OFF_X1 + k*128 + d] = acc + colk * be1[d];
}

// ============================ analytic coarse tail ============================
__global__ __launch_bounds__(256) void k_tail(
    const float* __restrict__ We1, const float* __restrict__ be1,
    const float* __restrict__ We2, const float* __restrict__ be2,
    const float* __restrict__ Wa2, const float* __restrict__ ba2,
    float* __restrict__ out)
{
    __shared__ float sumT[128];
    __shared__ float meanx1[128];
    __shared__ float meanvec[128];
    __shared__ float s2row[32];
    __shared__ float sc[256];
    int t = threadIdx.x;

    if (t < 128) sumT[t] = g_sumT[t];
    sc[t] = g_colsum[t];
    __syncthreads();
    #pragma unroll
    for (int st = 128; st > 0; st >>= 1) {
        if (t < st) sc[t] += sc[t+st];
        __syncthreads();
    }
    float sumcol = sc[0];
    if (t < 128) {
        float s = 0.f;
        for (int e = 0; e < 128; e++) s = fmaf(sumT[e], We1[e*128 + t], s);
        meanx1[t] = (s + sumcol*be1[t]) * (1.0f/256.0f);
    }
    __syncthreads();
    if (t < 128) {
        float s = 0.f;
        for (int e = 0; e < 128; e++) s = fmaf(meanx1[e], We2[e*128 + t], s);
        meanvec[t] = s + be2[t];
    }
    __syncthreads();
    if (t < 32) {
        float s = 0.f;
        for (int d = 0; d < 128; d++) s = fmaf(meanvec[d], Wa2[d*32 + t], s);
        float v = s + ba2[t];
        float mx = v;
        #pragma unroll
        for (int o = 16; o > 0; o >>= 1) mx = fmaxf(mx, __shfl_xor_sync(0xffffffffu, mx, o));
        float ex = __expf(v - mx);
        float sm = ex;
        #pragma unroll
        for (int o = 16; o > 0; o >>= 1) sm += __shfl_xor_sync(0xffffffffu, sm, o);
        s2row[t] = ex / sm;
    }
    __syncthreads();
    for (int i = t; i < 256*32; i += 256) out[OFF_S2 + i] = s2row[i & 31];
    if (t < 32) out[OFF_A1 + t] = 1.0f;
    for (int i = t; i < 32*128; i += 256)
        out[OFF_X2 + i] = 256.0f * s2row[i >> 7] * meanvec[i & 127];
    if (t == 0) {
        float s = 0.f;
        for (int d = 0; d < 128; d++) s += meanvec[d];
        out[OFF_E0] = s * (1.0f/16.0f);
    }
}

// ============================ launch ============================
extern "C" void kernel_launch(void* const* d_in, const int* in_sizes, int n_in,
                              void* d_out, int out_size)
{
    const float* feature = (const float*)d_in[0];
    const int*   eidx    = (const int*)d_in[1];
    const int*   src     = eidx;
    const int*   dst     = eidx + EE;
    const float* Wf   = (const float*)d_in[2];
    const float* bf   = (const float*)d_in[3];
    const float* We1  = (const float*)d_in[4];
    const float* be1  = (const float*)d_in[5];
    const float* Wa1  = (const float*)d_in[6];
    const float* ba1  = (const float*)d_in[7];
    const float* attW1 = (const float*)d_in[8];
    const float* attb1 = (const float*)d_in[9];
    const float* We2  = (const float*)d_in[10];
    const float* be2  = (const float*)d_in[11];
    const float* Wa2  = (const float*)d_in[12];
    const float* ba2  = (const float*)d_in[13];
    float* out = (float*)d_out;

    void *deg_p, *colsum_p, *sumT_p;
    float *zf_p, *x_p, *m2_p;
    cudaGetSymbolAddress(&deg_p,    g_deg);
    cudaGetSymbolAddress(&colsum_p, g_colsum);
    cudaGetSymbolAddress(&sumT_p,   g_sumT);
    cudaGetSymbolAddress((void**)&zf_p, g_zf);
    cudaGetSymbolAddress((void**)&x_p,  g_x);
    cudaGetSymbolAddress((void**)&m2_p, g_m2);

    cudaStream_t side = g_sr.s;

    // ---- fork: side stream does dense prep (independent of the graph) ----
    cudaEventRecord(g_sr.fork, 0);
    cudaStreamWaitEvent(side, g_sr.fork, 0);
    cudaMemsetAsync(colsum_p, 0, CC1*sizeof(float), side);
    cudaMemsetAsync(sumT_p,   0, DD*sizeof(float), side);
    k_gemm_zf<<<(NN+127)/128, 256, 0, side>>>(feature, Wf, bf, zf_p);
    k_fold<<<129, 256, 0, side>>>(We1, be1, Wa1, ba1, attW1);
    cudaEventRecord(g_sr.join, side);

    // ---- main stream: graph build ----
    cudaMemsetAsync(deg_p, 0, NN*sizeof(int));
    k_count<<<(EE + 255)/256, 256>>>(dst);
    k_scanall<<<NB, 128>>>();
    k_fill<<<(EE + 255)/256, 256>>>(src, dst);

    // ---- join, then serial chain ----
    cudaStreamWaitEvent(0, g_sr.join, 0);

    // x = normalize(segmean(zf)); embed3 = x
    k_segmean<true,false><<<(NN+7)/8, 256>>>(zf_p, x_p, out + OFF_E3);
    // m2 = segmean(x) + fused a_src/a_dst
    k_segmean<false,true><<<(NN+7)/8, 256>>>(x_p, m2_p, (float*)0);
    // GAT aggregation on 128-wide m2
    k_gatagg<<<(NN+7)/8, 256>>>(attb1);
    // s1 = softmax(magg@W_comb + b_comb)  [TF32 MMA]
    k_gemm_s1<<<(NN+63)/64, 256>>>(out + OFF_S1);
    // T partials = s1^T @ m2 + colsum  [TF32 MMA, 148 blocks]
    k_atb<<<dim3(CHUNKS, 2), 256>>>(out + OFF_S1);
    // x1 = T@We1 + colsum (x) be1 (+ sumT accumulation)
    k_x1<<<128, 256>>>(We1, be1, out);
    // analytic coarse level
    k_tail<<<1, 256>>>(We1, be1, We2, be2, Wa2, ba2, out);
}

// round 9
// speedup vs baseline: 2.8464x; 1.0846x over previous
#include <cuda_runtime.h>
#include <math.h>
#include <float.h>
#include <stdint.h>

#define NN   20000
#define EE   340000
#define DD   128
#define CC1  256
#define NB   157      // ceil(NN/128)
#define SCHUNKS 148   // fused s1+atb chunks: 1 block/SM

// ---- output layout (element offsets into float* d_out) ----
#define OFF_S1  0
#define OFF_S2  (NN*CC1)
#define OFF_A1  (OFF_S2 + 256*32)
#define OFF_E3  (OFF_A1 + 32)
#define OFF_X1  (OFF_E3 + NN*DD)
#define OFF_X2  (OFF_X1 + 256*128)
#define OFF_E0  (OFF_X2 + 32*128)

// ---- scratch ----
__device__ float g_zf[NN*DD];
__device__ float g_x[NN*DD];
__device__ float g_m2[NN*DD];
__device__ float g_magg[NN*DD];
__device__ float g_asrc[NN];
__device__ float g_adst[NN];
__device__ int   g_deg[NN];
__device__ int   g_off[NN+1];
__device__ int   g_cur[NN];
__device__ int   g_csrc[EE];
__device__ float g_Wcomb[DD*CC1];        // 128x256
__device__ float g_bcomb[CC1];
__device__ float g_us[DD];
__device__ float g_ud[DD];
__device__ float g_cs[2];
__device__ float g_part[SCHUNKS*CC1*DD]; // per-chunk T partials (19.4MB)
__device__ float g_colsum[CC1];
__device__ float g_sumT[DD];

// ---- persistent side stream + events ----
struct SideRes {
    cudaStream_t s;
    cudaEvent_t fork, join;
    SideRes() {
        cudaStreamCreateWithFlags(&s, cudaStreamNonBlocking);
        cudaEventCreateWithFlags(&fork, cudaEventDisableTiming);
        cudaEventCreateWithFlags(&join, cudaEventDisableTiming);
    }
};
static SideRes g_sr;

// ---- tf32 helpers ----
__device__ __forceinline__ float to_tf32(float x) {
    float r;
    asm("cvt.rna.tf32.f32 %0, %1;" : "=f"(r) : "f"(x));
    return r;
}
__device__ __forceinline__ void mma_tf32(float c[4],
    uint32_t a0, uint32_t a1, uint32_t a2, uint32_t a3,
    uint32_t b0, uint32_t b1)
{
    asm volatile(
        "mma.sync.aligned.m16n8k8.row.col.f32.tf32.tf32.f32 "
        "{%0,%1,%2,%3},{%4,%5,%6,%7},{%8,%9},{%0,%1,%2,%3};\n"
        : "+f"(c[0]), "+f"(c[1]), "+f"(c[2]), "+f"(c[3])
        : "r"(a0), "r"(a1), "r"(a2), "r"(a3), "r"(b0), "r"(b1));
}
__device__ __forceinline__ uint32_t fbits(float x) { return __float_as_uint(x); }

// ============================ graph build ============================
__global__ void k_count(const int* __restrict__ dst) {
    int e = blockIdx.x*blockDim.x + threadIdx.x;
    if (e < EE) atomicAdd(&g_deg[dst[e]], 1);
}

__global__ void k_scanall() {   // NB blocks x 128
    __shared__ int sh[128];
    int t = threadIdx.x, b = blockIdx.x;
    int base = 0;
    for (int i = t; i < b*128; i += 128) base += g_deg[i];
    sh[t] = base; __syncthreads();
    #pragma unroll
    for (int st = 64; st > 0; st >>= 1) {
        if (t < st) sh[t] += sh[t+st];
        __syncthreads();
    }
    base = sh[0];
    __syncthreads();
    int i = b*128 + t;
    int d = (i < NN) ? g_deg[i] : 0;
    sh[t] = d; __syncthreads();
    #pragma unroll
    for (int off = 1; off < 128; off <<= 1) {
        int v = (t >= off) ? sh[t-off] : 0;
        __syncthreads();
        sh[t] += v;
        __syncthreads();
    }
    int excl = base + sh[t] - d;
    if (i < NN) { g_off[i] = excl; g_cur[i] = excl; }
    if (i == 0) g_off[NN] = EE;
}

__global__ void k_fill(const int* __restrict__ src, const int* __restrict__ dst) {
    int e = blockIdx.x*blockDim.x + threadIdx.x;
    if (e < EE) {
        int p = atomicAdd(&g_cur[dst[e]], 1);
        g_csrc[p] = src[e];
    }
}

// ============================ weight folding ============================
__global__ __launch_bounds__(256) void k_fold(
    const float* __restrict__ We1, const float* __restrict__ be1,
    const float* __restrict__ Wa1, const float* __restrict__ ba1,
    const float* __restrict__ attW)
{
    int b = blockIdx.x, t = threadIdx.x;
    if (b < 128) {
        __shared__ float sWe[128];
        if (t < 128) sWe[t] = We1[b*128 + t];
        __syncthreads();
        float acc = 0.f;
        #pragma unroll 8
        for (int k = 0; k < 128; k++) acc = fmaf(sWe[k], Wa1[k*256 + t], acc);
        g_Wcomb[b*256 + t] = acc;
    } else {
        __shared__ float ts[128], td[128], bc[256];
        if (t < 128) {
            float s1v = 0.f, s2v = 0.f;
            for (int c = 0; c < 256; c++) {
                float w = Wa1[t*256 + c];
                s1v = fmaf(w, attW[c], s1v);
                s2v = fmaf(w, attW[256 + c], s2v);
            }
            ts[t] = s1v; td[t] = s2v;
        }
        {
            float s = 0.f;
            for (int e = 0; e < 128; e++) s = fmaf(be1[e], Wa1[e*256 + t], s);
            bc[t] = s + ba1[t];
            g_bcomb[t] = bc[t];
        }
        __syncthreads();
        if (t < 128) {
            float u1 = 0.f, u2 = 0.f;
            for (int e = 0; e < 128; e++) {
                float w = We1[t*128 + e];
                u1 = fmaf(w, ts[e], u1);
                u2 = fmaf(w, td[e], u2);
            }
            g_us[t] = u1; g_ud[t] = u2;
        }
        if (t == 0) {
            float c1v = 0.f, c2v = 0.f;
            for (int c = 0; c < 256; c++) {
                c1v = fmaf(bc[c], attW[c], c1v);
                c2v = fmaf(bc[c], attW[256 + c], c2v);
            }
            g_cs[0] = c1v; g_cs[1] = c2v;
        }
    }
}

// ============================ zf = feature@Wf + bf : split-TF32 MMA (~fp32 acc) ============================
__global__ __launch_bounds__(256) void k_gemm_zf(
    const float* __restrict__ A, const float* __restrict__ B,
    const float* __restrict__ bias, float* __restrict__ C)
{
    extern __shared__ float zs[];
    float* Ahi = zs;
    float* Alo = Ahi + 128*36;
    float* Bhi = Alo + 128*36;
    float* Blo = Bhi + 32*136;

    int tid = threadIdx.x;
    int w = tid >> 5, lane = tid & 31;
    int gid = lane >> 2, tid4 = lane & 3;
    int msub = (w >> 1) * 32, nsub = (w & 1) * 64;
    int row0 = blockIdx.x * 128;

    float acc[2][8][4];
    #pragma unroll
    for (int mf = 0; mf < 2; mf++)
        #pragma unroll
        for (int nf = 0; nf < 8; nf++)
            #pragma unroll
            for (int q = 0; q < 4; q++) acc[mf][nf][q] = 0.f;

    for (int k0 = 0; k0 < 128; k0 += 32) {
        {   // stage A: 128 x 32 (hi/lo split)
            int r = tid >> 1, cs = (tid & 1) * 16;
            int gr = row0 + r;
            #pragma unroll
            for (int i = 0; i < 4; i++) {
                float4 v = make_float4(0.f,0.f,0.f,0.f);
                if (gr < NN) v = *(const float4*)(A + (size_t)gr*128 + k0 + cs + i*4);
                float hx = to_tf32(v.x), hy = to_tf32(v.y), hz = to_tf32(v.z), hw = to_tf32(v.w);
                Ahi[r*36+cs+i*4+0] = hx; Alo[r*36+cs+i*4+0] = to_tf32(v.x - hx);
                Ahi[r*36+cs+i*4+1] = hy; Alo[r*36+cs+i*4+1] = to_tf32(v.y - hy);
                Ahi[r*36+cs+i*4+2] = hz; Alo[r*36+cs+i*4+2] = to_tf32(v.z - hz);
                Ahi[r*36+cs+i*4+3] = hw; Alo[r*36+cs+i*4+3] = to_tf32(v.w - hw);
            }
        }
        {   // stage B: 32 x 128 (hi/lo split)
            int r = tid >> 3, cs = (tid & 7) * 16;
            #pragma unroll
            for (int i = 0; i < 4; i++) {
                float4 v = *(const float4*)(B + (size_t)(k0+r)*128 + cs + i*4);
                float hx = to_tf32(v.x), hy = to_tf32(v.y), hz = to_tf32(v.z), hw = to_tf32(v.w);
                Bhi[r*136+cs+i*4+0] = hx; Blo[r*136+cs+i*4+0] = to_tf32(v.x - hx);
                Bhi[r*136+cs+i*4+1] = hy; Blo[r*136+cs+i*4+1] = to_tf32(v.y - hy);
                Bhi[r*136+cs+i*4+2] = hz; Blo[r*136+cs+i*4+2] = to_tf32(v.z - hz);
                Bhi[r*136+cs+i*4+3] = hw; Blo[r*136+cs+i*4+3] = to_tf32(v.w - hw);
            }
        }
        __syncthreads();
        #pragma unroll
        for (int kk = 0; kk < 4; kk++) {
            int kb = kk*8;
            uint32_t ah[2][4], al[2][4];
            #pragma unroll
            for (int mf = 0; mf < 2; mf++) {
                int m = msub + mf*16 + gid;
                ah[mf][0] = fbits(Ahi[m*36     + kb + tid4    ]);
                ah[mf][1] = fbits(Ahi[(m+8)*36 + kb + tid4    ]);
                ah[mf][2] = fbits(Ahi[m*36     + kb + tid4 + 4]);
                ah[mf][3] = fbits(Ahi[(m+8)*36 + kb + tid4 + 4]);
                al[mf][0] = fbits(Alo[m*36     + kb + tid4    ]);
                al[mf][1] = fbits(Alo[(m+8)*36 + kb + tid4    ]);
                al[mf][2] = fbits(Alo[m*36     + kb + tid4 + 4]);
                al[mf][3] = fbits(Alo[(m+8)*36 + kb + tid4 + 4]);
            }
            #pragma unroll
            for (int nf = 0; nf < 8; nf++) {
                int c = nsub + nf*8 + gid;
                uint32_t bh0 = fbits(Bhi[(kb+tid4)*136 + c]);
                uint32_t bh1 = fbits(Bhi[(kb+tid4+4)*136 + c]);
                uint32_t bl0 = fbits(Blo[(kb+tid4)*136 + c]);
                uint32_t bl1 = fbits(Blo[(kb+tid4+4)*136 + c]);
                #pragma unroll
                for (int mf = 0; mf < 2; mf++) {
                    mma_tf32(acc[mf][nf], ah[mf][0], ah[mf][1], ah[mf][2], ah[mf][3], bh0, bh1);
                    mma_tf32(acc[mf][nf], ah[mf][0], ah[mf][1], ah[mf][2], ah[mf][3], bl0, bl1);
                    mma_tf32(acc[mf][nf], al[mf][0], al[mf][1], al[mf][2], al[mf][3], bh0, bh1);
                }
            }
        }
        __syncthreads();
    }
    #pragma unroll
    for (int mf = 0; mf < 2; mf++) {
        int rlo = row0 + msub + mf*16 + gid;
        int rhi = rlo + 8;
        #pragma unroll
        for (int nf = 0; nf < 8; nf++) {
            int c0 = nsub + nf*8 + 2*tid4;
            float b0v = bias[c0], b1v = bias[c0+1];
            if (rlo < NN) {
                float2 o; o.x = acc[mf][nf][0]+b0v; o.y = acc[mf][nf][1]+b1v;
                *(float2*)(C + (size_t)rlo*128 + c0) = o;
            }
            if (rhi < NN) {
                float2 o; o.x = acc[mf][nf][2]+b0v; o.y = acc[mf][nf][3]+b1v;
                *(float2*)(C + (size_t)rhi*128 + c0) = o;
            }
        }
    }
}

// ============================ segment mean (warp/node, shfl-batched gathers) ============================
template<bool NORM, bool DOTS>
__global__ __launch_bounds__(256) void k_segmean(
    const float* __restrict__ zin, float* __restrict__ out, float* __restrict__ out2)
{
    int node = blockIdx.x*8 + (threadIdx.x >> 5);
    if (node >= NN) return;
    int lane = threadIdx.x & 31;
    int e0 = g_off[node], e1 = g_off[node+1];
    float4 acc = make_float4(0.f,0.f,0.f,0.f);
    const float* zl = zin + lane*4;

    for (int base = e0; base < e1; base += 32) {
        int j = base + lane;
        int myidx = (j < e1) ? g_csrc[j] : 0;
        int cnt = min(32, e1 - base);
        int t = 0;
        for (; t + 4 <= cnt; t += 4) {
            int s0 = __shfl_sync(0xffffffffu, myidx, t);
            int s1i = __shfl_sync(0xffffffffu, myidx, t+1);
            int s2 = __shfl_sync(0xffffffffu, myidx, t+2);
            int s3 = __shfl_sync(0xffffffffu, myidx, t+3);
            float4 v0 = *(const float4*)(zl + (size_t)s0*DD);
            float4 v1 = *(const float4*)(zl + (size_t)s1i*DD);
            float4 v2 = *(const float4*)(zl + (size_t)s2*DD);
            float4 v3 = *(const float4*)(zl + (size_t)s3*DD);
            acc.x += (v0.x+v1.x) + (v2.x+v3.x);
            acc.y += (v0.y+v1.y) + (v2.y+v3.y);
            acc.z += (v0.z+v1.z) + (v2.z+v3.z);
            acc.w += (v0.w+v1.w) + (v2.w+v3.w);
        }
        for (; t < cnt; t++) {
            int sb = __shfl_sync(0xffffffffu, myidx, t);
            float4 v = *(const float4*)(zl + (size_t)sb*DD);
            acc.x += v.x; acc.y += v.y; acc.z += v.z; acc.w += v.w;
        }
    }
    float inv = 1.0f / (float)(e1 - e0);
    acc.x *= inv; acc.y *= inv; acc.z *= inv; acc.w *= inv;
    if (NORM) {
        float ss = acc.x*acc.x + acc.y*acc.y + acc.z*acc.z + acc.w*acc.w;
        #pragma unroll
        for (int o = 16; o > 0; o >>= 1) ss += __shfl_xor_sync(0xffffffffu, ss, o);
        float r = 1.0f / fmaxf(sqrtf(ss), 1e-12f);
        acc.x *= r; acc.y *= r; acc.z *= r; acc.w *= r;
    }
    *(float4*)(out + (size_t)node*DD + lane*4) = acc;
    if (out2) *(float4*)(out2 + (size_t)node*DD + lane*4) = acc;
    if (DOTS) {
        float4 us4 = *(const float4*)(g_us + lane*4);
        float4 ud4 = *(const float4*)(g_ud + lane*4);
        float as = acc.x*us4.x + acc.y*us4.y + acc.z*us4.z + acc.w*us4.w;
        float ad = acc.x*ud4.x + acc.y*ud4.y + acc.z*ud4.z + acc.w*ud4.w;
        #pragma unroll
        for (int o = 16; o > 0; o >>= 1) {
            as += __shfl_xor_sync(0xffffffffu, as, o);
            ad += __shfl_xor_sync(0xffffffffu, ad, o);
        }
        if (lane == 0) { g_asrc[node] = as + g_cs[0]; g_adst[node] = ad + g_cs[1]; }
    }
}

// ============================ GAT aggregation (warp/node, shfl-batched gathers) ============================
__global__ __launch_bounds__(256) void k_gatagg(const float* __restrict__ attb)
{
    int node = blockIdx.x*8 + (threadIdx.x >> 5);
    if (node >= NN) return;
    int lane = threadIdx.x & 31;
    int e0 = g_off[node], e1 = g_off[node+1];
    float adb = g_adst[node] + attb[0];
    const float* zl = g_m2 + lane*4;

    float mx = -FLT_MAX;
    for (int j = e0 + lane; j < e1; j += 32) {
        float e = g_asrc[g_csrc[j]] + adb;
        e = (e > 0.f) ? e : 0.01f*e;
        mx = fmaxf(mx, e);
    }
    #pragma unroll
    for (int o = 16; o > 0; o >>= 1) mx = fmaxf(mx, __shfl_xor_sync(0xffffffffu, mx, o));

    float4 acc = make_float4(0.f,0.f,0.f,0.f);
    float denom = 0.f;
    for (int base = e0; base < e1; base += 32) {
        int j = base + lane;
        int s = 0; float a = 0.f;
        if (j < e1) {
            s = g_csrc[j];
            float e = g_asrc[s] + adb;
            e = (e > 0.f) ? e : 0.01f*e;
            a = __expf(e - mx);
            denom += a;
        }
        int cnt = min(32, e1 - base);
        int t = 0;
        for (; t + 4 <= cnt; t += 4) {
            float a0 = __shfl_sync(0xffffffffu, a, t);
            float a1 = __shfl_sync(0xffffffffu, a, t+1);
            float a2 = __shfl_sync(0xffffffffu, a, t+2);
            float a3 = __shfl_sync(0xffffffffu, a, t+3);
            int   s0 = __shfl_sync(0xffffffffu, s, t);
            int   s1i = __shfl_sync(0xffffffffu, s, t+1);
            int   s2 = __shfl_sync(0xffffffffu, s, t+2);
            int   s3 = __shfl_sync(0xffffffffu, s, t+3);
            float4 v0 = *(const float4*)(zl + (size_t)s0*DD);
            float4 v1 = *(const float4*)(zl + (size_t)s1i*DD);
            float4 v2 = *(const float4*)(zl + (size_t)s2*DD);
            float4 v3 = *(const float4*)(zl + (size_t)s3*DD);
            acc.x = fmaf(a0, v0.x, fmaf(a1, v1.x, fmaf(a2, v2.x, fmaf(a3, v3.x, acc.x))));
            acc.y = fmaf(a0, v0.y, fmaf(a1, v1.y, fmaf(a2, v2.y, fmaf(a3, v3.y, acc.y))));
            acc.z = fmaf(a0, v0.z, fmaf(a1, v1.z, fmaf(a2, v2.z, fmaf(a3, v3.z, acc.z))));
            acc.w = fmaf(a0, v0.w, fmaf(a1, v1.w, fmaf(a2, v2.w, fmaf(a3, v3.w, acc.w))));
        }
        for (; t < cnt; t++) {
            float ab = __shfl_sync(0xffffffffu, a, t);
            int   sb = __shfl_sync(0xffffffffu, s, t);
            float4 v = *(const float4*)(zl + (size_t)sb*DD);
            acc.x = fmaf(ab, v.x, acc.x); acc.y = fmaf(ab, v.y, acc.y);
            acc.z = fmaf(ab, v.z, acc.z); acc.w = fmaf(ab, v.w, acc.w);
        }
    }
    #pragma unroll
    for (int o = 16; o > 0; o >>= 1) denom += __shfl_xor_sync(0xffffffffu, denom, o);
    float r = 1.0f / denom;
    acc.x *= r; acc.y *= r; acc.z *= r; acc.w *= r;
    *(float4*)(g_magg + (size_t)node*DD + lane*4) = acc;
}

// ============================ FUSED: s1 = softmax(magg@Wcomb+bcomb); T += s1^T@m2 ============================
// grid SCHUNKS (=148, 1/SM), 512 threads (16 warps). Wcomb held in smem.
// dyn smem floats: Wc[128*264] Ss[32*264] m2s[32*136] As[32*132] bc[256] redm[256] reds[256]
#define S1ATB_SMEM_FLOATS (128*264 + 32*264 + 32*136 + 32*132 + 256 + 256 + 256)
__global__ __launch_bounds__(512) void k_s1atb(float* __restrict__ s1out)
{
    extern __shared__ float sm[];
    float* Wc   = sm;                 // [k=128][n=264]
    float* Ssm  = Wc  + 128*264;      // [k=32][m=264]
    float* m2s  = Ssm + 32*264;       // [k=32][n=136]
    float* As   = m2s + 32*136;       // [m=32][k=132]  (128 used + pad)
    float* bc   = As  + 32*132;       // [256]
    float* redm = bc  + 256;          // [32][8]
    float* reds = redm + 256;         // [32][8]

    int tid = threadIdx.x;
    int w = tid >> 5, lane = tid & 31;
    int gid = lane >> 2, tid4 = lane & 3;
    int chunk = blockIdx.x;
    int k_begin = (int)((long long)NN * chunk / SCHUNKS);
    int k_end   = (int)((long long)NN * (chunk+1) / SCHUNKS);

    // S-phase warp mapping: warp covers rows [mhalf, mhalf+16), cols [ncol0, ncol0+32)
    int mhalf = (w >> 3) * 16, ncol0 = (w & 7) * 32;
    // T-phase warp mapping
    int msubT = (w >> 1) * 32, nsubT = (w & 1) * 64;

    // load Wcomb (tf32) + bias
    {
        int r = tid >> 2, cs = (tid & 3) * 64;
        #pragma unroll
        for (int i = 0; i < 16; i++) {
            float4 v = *(const float4*)(g_Wcomb + (size_t)r*256 + cs + i*4);
            Wc[r*264+cs+i*4+0] = to_tf32(v.x); Wc[r*264+cs+i*4+1] = to_tf32(v.y);
            Wc[r*264+cs+i*4+2] = to_tf32(v.z); Wc[r*264+cs+i*4+3] = to_tf32(v.w);
        }
    }
    if (tid < 256) bc[tid] = g_bcomb[tid];

    float accT[2][8][4];
    #pragma unroll
    for (int mf = 0; mf < 2; mf++)
        #pragma unroll
        for (int nf = 0; nf < 8; nf++)
            #pragma unroll
            for (int q = 0; q < 4; q++) accT[mf][nf][q] = 0.f;
    float colacc = 0.f;

    __syncthreads();

    for (int s0 = k_begin; s0 < k_end; s0 += 32) {
        // ---- stage magg slab (As, [32 nodes][128 feat], ld 132) and m2 slab ----
        {
            int r = tid >> 4, cs = (tid & 15) * 8;
            int gk = s0 + r;
            float4 v0 = make_float4(0.f,0.f,0.f,0.f), v1 = v0, u0 = v0, u1 = v0;
            if (gk < k_end) {
                v0 = *(const float4*)(g_magg + (size_t)gk*128 + cs);
                v1 = *(const float4*)(g_magg + (size_t)gk*128 + cs + 4);
                u0 = *(const float4*)(g_m2   + (size_t)gk*128 + cs);
                u1 = *(const float4*)(g_m2   + (size_t)gk*128 + cs + 4);
            }
            As[r*132+cs+0] = to_tf32(v0.x); As[r*132+cs+1] = to_tf32(v0.y);
            As[r*132+cs+2] = to_tf32(v0.z); As[r*132+cs+3] = to_tf32(v0.w);
            As[r*132+cs+4] = to_tf32(v1.x); As[r*132+cs+5] = to_tf32(v1.y);
            As[r*132+cs+6] = to_tf32(v1.z); As[r*132+cs+7] = to_tf32(v1.w);
            m2s[r*136+cs+0] = to_tf32(u0.x); m2s[r*136+cs+1] = to_tf32(u0.y);
            m2s[r*136+cs+2] = to_tf32(u0.z); m2s[r*136+cs+3] = to_tf32(u0.w);
            m2s[r*136+cs+4] = to_tf32(u1.x); m2s[r*136+cs+5] = to_tf32(u1.y);
            m2s[r*136+cs+6] = to_tf32(u1.z); m2s[r*136+cs+7] = to_tf32(u1.w);
        }
        __syncthreads();

        // ---- S = As @ Wc : warp tile 16x32, K=128 ----
        float sacc[4][4];
        #pragma unroll
        for (int nf = 0; nf < 4; nf++)
            #pragma unroll
            for (int q = 0; q < 4; q++) sacc[nf][q] = 0.f;
        #pragma unroll
        for (int kk = 0; kk < 16; kk++) {
            int kb = kk*8;
            uint32_t a0 = fbits(As[(mhalf+gid)*132   + kb + tid4    ]);
            uint32_t a1 = fbits(As[(mhalf+gid+8)*132 + kb + tid4    ]);
            uint32_t a2 = fbits(As[(mhalf+gid)*132   + kb + tid4 + 4]);
            uint32_t a3 = fbits(As[(mhalf+gid+8)*132 + kb + tid4 + 4]);
            #pragma unroll
            for (int nf = 0; nf < 4; nf++) {
                int c = ncol0 + nf*8 + gid;
                uint32_t b0 = fbits(Wc[(kb+tid4)*264 + c]);
                uint32_t b1 = fbits(Wc[(kb+tid4+4)*264 + c]);
                mma_tf32(sacc[nf], a0, a1, a2, a3, b0, b1);
            }
        }
        // bias
        #pragma unroll
        for (int nf = 0; nf < 4; nf++) {
            int c0 = ncol0 + nf*8 + 2*tid4;
            sacc[nf][0] += bc[c0];   sacc[nf][1] += bc[c0+1];
            sacc[nf][2] += bc[c0];   sacc[nf][3] += bc[c0+1];
        }
        // row max partial -> smem
        {
            float mA = -FLT_MAX, mB = -FLT_MAX;
            #pragma unroll
            for (int nf = 0; nf < 4; nf++) {
                mA = fmaxf(mA, fmaxf(sacc[nf][0], sacc[nf][1]));
                mB = fmaxf(mB, fmaxf(sacc[nf][2], sacc[nf][3]));
            }
            mA = fmaxf(mA, __shfl_xor_sync(0xffffffffu, mA, 1));
            mA = fmaxf(mA, __shfl_xor_sync(0xffffffffu, mA, 2));
            mB = fmaxf(mB, __shfl_xor_sync(0xffffffffu, mB, 1));
            mB = fmaxf(mB, __shfl_xor_sync(0xffffffffu, mB, 2));
            if (tid4 == 0) {
                redm[(mhalf+gid)*8   + (w & 7)] = mA;
                redm[(mhalf+gid+8)*8 + (w & 7)] = mB;
            }
        }
        __syncthreads();
        float rmaxA = -FLT_MAX, rmaxB = -FLT_MAX;
        #pragma unroll
        for (int q = 0; q < 8; q++) {
            rmaxA = fmaxf(rmaxA, redm[(mhalf+gid)*8 + q]);
            rmaxB = fmaxf(rmaxB, redm[(mhalf+gid+8)*8 + q]);
        }
        // exp + row sum partial
        {
            float sA = 0.f, sB = 0.f;
            #pragma unroll
            for (int nf = 0; nf < 4; nf++) {
                sacc[nf][0] = __expf(sacc[nf][0] - rmaxA);
                sacc[nf][1] = __expf(sacc[nf][1] - rmaxA);
                sacc[nf][2] = __expf(sacc[nf][2] - rmaxB);
                sacc[nf][3] = __expf(sacc[nf][3] - rmaxB);
                sA += sacc[nf][0] + sacc[nf][1];
                sB += sacc[nf][2] + sacc[nf][3];
            }
            sA += __shfl_xor_sync(0xffffffffu, sA, 1);
            sA += __shfl_xor_sync(0xffffffffu, sA, 2);
            sB += __shfl_xor_sync(0xffffffffu, sB, 1);
            sB += __shfl_xor_sync(0xffffffffu, sB, 2);
            if (tid4 == 0) {
                reds[(mhalf+gid)*8   + (w & 7)] = sA;
                reds[(mhalf+gid+8)*8 + (w & 7)] = sB;
            }
        }
        __syncthreads();
        {
            float ssA = 0.f, ssB = 0.f;
            #pragma unroll
            for (int q = 0; q < 8; q++) {
                ssA += reds[(mhalf+gid)*8 + q];
                ssB += reds[(mhalf+gid+8)*8 + q];
            }
            float rinvA = 1.0f / ssA, rinvB = 1.0f / ssB;
            int grA = s0 + mhalf + gid, grB = grA + 8;
            bool vA = (grA < k_end), vB = (grB < k_end);
            #pragma unroll
            for (int nf = 0; nf < 4; nf++) {
                int c0 = ncol0 + nf*8 + 2*tid4;
                float oA0 = vA ? sacc[nf][0]*rinvA : 0.f;
                float oA1 = vA ? sacc[nf][1]*rinvA : 0.f;
                float oB0 = vB ? sacc[nf][2]*rinvB : 0.f;
                float oB1 = vB ? sacc[nf][3]*rinvB : 0.f;
                Ssm[(mhalf+gid)*264 + c0]     = oA0;
                Ssm[(mhalf+gid)*264 + c0 + 1] = oA1;
                Ssm[(mhalf+gid+8)*264 + c0]     = oB0;
                Ssm[(mhalf+gid+8)*264 + c0 + 1] = oB1;
                if (vA) { float2 o; o.x = oA0; o.y = oA1; *(float2*)(s1out + (size_t)grA*256 + c0) = o; }
                if (vB) { float2 o; o.x = oB0; o.y = oB1; *(float2*)(s1out + (size_t)grB*256 + c0) = o; }
            }
        }
        __syncthreads();

        // ---- colsum + T += Ss^T @ m2s (K=32) ----
        if (tid < 256) {
            #pragma unroll 8
            for (int r = 0; r < 32; r++) colacc += Ssm[r*264 + tid];
        }
        #pragma unroll
        for (int kk = 0; kk < 4; kk++) {
            int kb = kk*8;
            uint32_t a[2][4];
            #pragma unroll
            for (int mf = 0; mf < 2; mf++) {
                int m = msubT + mf*16 + gid;
                a[mf][0] = fbits(Ssm[(kb+tid4)*264   + m  ]);
                a[mf][1] = fbits(Ssm[(kb+tid4)*264   + m+8]);
                a[mf][2] = fbits(Ssm[(kb+tid4+4)*264 + m  ]);
                a[mf][3] = fbits(Ssm[(kb+tid4+4)*264 + m+8]);
            }
            #pragma unroll
            for (int nf = 0; nf < 8; nf++) {
                int c = nsubT + nf*8 + gid;
                uint32_t b0 = fbits(m2s[(kb+tid4)*136 + c]);
                uint32_t b1 = fbits(m2s[(kb+tid4+4)*136 + c]);
                mma_tf32(accT[0][nf], a[0][0], a[0][1], a[0][2], a[0][3], b0, b1);
                mma_tf32(accT[1][nf], a[1][0], a[1][1], a[1][2], a[1][3], b0, b1);
            }
        }
        __syncthreads();
    }

    // ---- write T partial + colsum ----
    float* P = g_part + (size_t)chunk * (CC1*DD);
    #pragma unroll
    for (int mf = 0; mf < 2; mf++) {
        int mloc = msubT + mf*16 + gid;
        #pragma unroll
        for (int nf = 0; nf < 8; nf++) {
            int c0 = nsubT + nf*8 + 2*tid4;
            float2 lo; lo.x = accT[mf][nf][0]; lo.y = accT[mf][nf][1];
            float2 hi; hi.x = accT[mf][nf][2]; hi.y = accT[mf][nf][3];
            *(float2*)(P + (size_t)mloc*128 + c0)     = lo;
            *(float2*)(P + (size_t)(mloc+8)*128 + c0) = hi;
        }
    }
    if (tid < 256) atomicAdd(&g_colsum[tid], colacc);
}

// ============================ x1 = T@We1 + colsum (x) be1 (reduce partials) ============================
__global__ __launch_bounds__(256) void k_x1(
    const float* __restrict__ We1, const float* __restrict__ be1,
    float* __restrict__ out)
{
    __shared__ float sT[2][128];
    int t = threadIdx.x;
    int rowsel = t >> 7;
    int d = t & 127;
    int k = blockIdx.x*2 + rowsel;
    float s = 0.f;
    #pragma unroll 4
    for (int c = 0; c < SCHUNKS; c++)
        s += g_part[(size_t)c*(CC1*DD) + (size_t)k*128 + d];
    sT[rowsel][d] = s;
    __syncthreads();
    if (t < 128) atomicAdd(&g_sumT[t], sT[0][t] + sT[1][t]);
    float colk = g_colsum[k];
    float acc = 0.f;
    #pragma unroll 8
    for (int e = 0; e < 128; e++) acc = fmaf(sT[rowsel][e], We1[e*128 + d], acc);
    out[OFF_X1 + k*128 + d] = acc + colk * be1[d];
}

// ============================ analytic coarse tail ============================
__global__ __launch_bounds__(256) void k_tail(
    const float* __restrict__ We1, const float* __restrict__ be1,
    const float* __restrict__ We2, const float* __restrict__ be2,
    const float* __restrict__ Wa2, const float* __restrict__ ba2,
    float* __restrict__ out)
{
    __shared__ float sumT[128];
    __shared__ float meanx1[128];
    __shared__ float meanvec[128];
    __shared__ float s2row[32];
    __shared__ float sc[256];
    int t = threadIdx.x;

    if (t < 128) sumT[t] = g_sumT[t];
    sc[t] = g_colsum[t];
    __syncthreads();
    #pragma unroll
    for (int st = 128; st > 0; st >>= 1) {
        if (t < st) sc[t] += sc[t+st];
        __syncthreads();
    }
    float sumcol = sc[0];
    if (t < 128) {
        float s = 0.f;
        for (int e = 0; e < 128; e++) s = fmaf(sumT[e], We1[e*128 + t], s);
        meanx1[t] = (s + sumcol*be1[t]) * (1.0f/256.0f);
    }
    __syncthreads();
    if (t < 128) {
        float s = 0.f;
        for (int e = 0; e < 128; e++) s = fmaf(meanx1[e], We2[e*128 + t], s);
        meanvec[t] = s + be2[t];
    }
    __syncthreads();
    if (t < 32) {
        float s = 0.f;
        for (int d = 0; d < 128; d++) s = fmaf(meanvec[d], Wa2[d*32 + t], s);
        float v = s + ba2[t];
        float mx = v;
        #pragma unroll
        for (int o = 16; o > 0; o >>= 1) mx = fmaxf(mx, __shfl_xor_sync(0xffffffffu, mx, o));
        float ex = __expf(v - mx);
        float sm = ex;
        #pragma unroll
        for (int o = 16; o > 0; o >>= 1) sm += __shfl_xor_sync(0xffffffffu, sm, o);
        s2row[t] = ex / sm;
    }
    __syncthreads();
    for (int i = t; i < 256*32; i += 256) out[OFF_S2 + i] = s2row[i & 31];
    if (t < 32) out[OFF_A1 + t] = 1.0f;
    for (int i = t; i < 32*128; i += 256)
        out[OFF_X2 + i] = 256.0f * s2row[i >> 7] * meanvec[i & 127];
    if (t == 0) {
        float s = 0.f;
        for (int d = 0; d < 128; d++) s += meanvec[d];
        out[OFF_E0] = s * (1.0f/16.0f);
    }
}

// ============================ launch ============================
extern "C" void kernel_launch(void* const* d_in, const int* in_sizes, int n_in,
                              void* d_out, int out_size)
{
    const float* feature = (const float*)d_in[0];
    const int*   eidx    = (const int*)d_in[1];
    const int*   src     = eidx;
    const int*   dst     = eidx + EE;
    const float* Wf   = (const float*)d_in[2];
    const float* bf   = (const float*)d_in[3];
    const float* We1  = (const float*)d_in[4];
    const float* be1  = (const float*)d_in[5];
    const float* Wa1  = (const float*)d_in[6];
    const float* ba1  = (const float*)d_in[7];
    const float* attW1 = (const float*)d_in[8];
    const float* attb1 = (const float*)d_in[9];
    const float* We2  = (const float*)d_in[10];
    const float* be2  = (const float*)d_in[11];
    const float* Wa2  = (const float*)d_in[12];
    const float* ba2  = (const float*)d_in[13];
    float* out = (float*)d_out;

    void *deg_p, *colsum_p, *sumT_p;
    float *zf_p, *x_p, *m2_p;
    cudaGetSymbolAddress(&deg_p,    g_deg);
    cudaGetSymbolAddress(&colsum_p, g_colsum);
    cudaGetSymbolAddress(&sumT_p,   g_sumT);
    cudaGetSymbolAddress((void**)&zf_p, g_zf);
    cudaGetSymbolAddress((void**)&x_p,  g_x);
    cudaGetSymbolAddress((void**)&m2_p, g_m2);

    const int zf_smem = (128*36*2 + 32*136*2) * 4;         // 71680 B
    const int s1atb_smem = S1ATB_SMEM_FLOATS * 4;          // 206336 B
    cudaFuncSetAttribute(k_gemm_zf, cudaFuncAttributeMaxDynamicSharedMemorySize, zf_smem);
    cudaFuncSetAttribute(k_s1atb,  cudaFuncAttributeMaxDynamicSharedMemorySize, s1atb_smem);

    cudaStream_t side = g_sr.s;

    // ---- fork: side stream does dense prep (independent of the graph) ----
    cudaEventRecord(g_sr.fork, 0);
    cudaStreamWaitEvent(side, g_sr.fork, 0);
    cudaMemsetAsync(colsum_p, 0, CC1*sizeof(float), side);
    cudaMemsetAsync(sumT_p,   0, DD*sizeof(float), side);
    k_gemm_zf<<<(NN+127)/128, 256, zf_smem, side>>>(feature, Wf, bf, zf_p);
    k_fold<<<129, 256, 0, side>>>(We1, be1, Wa1, ba1, attW1);
    cudaEventRecord(g_sr.join, side);

    // ---- main stream: graph build ----
    cudaMemsetAsync(deg_p, 0, NN*sizeof(int));
    k_count<<<(EE + 255)/256, 256>>>(dst);
    k_scanall<<<NB, 128>>>();
    k_fill<<<(EE + 255)/256, 256>>>(src, dst);

    // ---- join, then serial chain ----
    cudaStreamWaitEvent(0, g_sr.join, 0);

    // x = normalize(segmean(zf)); embed3 = x
    k_segmean<true,false><<<(NN+7)/8, 256>>>(zf_p, x_p, out + OFF_E3);
    // m2 = segmean(x) + fused a_src/a_dst
    k_segmean<false,true><<<(NN+7)/8, 256>>>(x_p, m2_p, (float*)0);
    // GAT aggregation on 128-wide m2
    k_gatagg<<<(NN+7)/8, 256>>>(attb1);
    // FUSED: s1 softmax GEMM + T partials (148 blocks, 1/SM)
    k_s1atb<<<SCHUNKS, 512, s1atb_smem>>>(out + OFF_S1);
    // x1 = T@We1 + colsum (x) be1 (+ sumT accumulation)
    k_x1<<<128, 256>>>(We1, be1, out);
    // analytic coarse level
    k_tail<<<1, 256>>>(We1, be1, We2, be2, Wa2, ba2, out);
}

// round 10
// speedup vs baseline: 2.8530x; 1.0023x over previous
#include <cuda_runtime.h>
#include <math.h>
#include <float.h>
#include <stdint.h>

#define NN   20000
#define EE   340000
#define DD   128
#define CC1  256
#define SCHUNKS 148   // fused s1+atb chunks: 1 block/SM
#define SCANB 20      // ceil(NN/1024)

// ---- output layout (element offsets into float* d_out) ----
#define OFF_S1  0
#define OFF_S2  (NN*CC1)
#define OFF_A1  (OFF_S2 + 256*32)
#define OFF_E3  (OFF_A1 + 32)
#define OFF_X1  (OFF_E3 + NN*DD)
#define OFF_X2  (OFF_X1 + 256*128)
#define OFF_E0  (OFF_X2 + 32*128)

// ---- scratch ----
__device__ float g_zf[NN*DD];
__device__ float g_m2[NN*DD];
__device__ float g_magg[NN*DD];
__device__ float g_asrc[NN];
__device__ float g_adst[NN];
__device__ int   g_deg[NN];
__device__ int   g_off[NN+1];
__device__ int   g_cur[NN];
__device__ int   g_csrc[EE];
__device__ float g_Wcomb[DD*CC1];        // 128x256
__device__ float g_bcomb[CC1];
__device__ float g_us[DD];
__device__ float g_ud[DD];
__device__ float g_cs[2];
__device__ float g_part[SCHUNKS*CC1*DD]; // per-chunk T partials (19.4MB)
__device__ float g_colsum[CC1];
__device__ float g_sumT[DD];

// ---- persistent side stream + events ----
struct SideRes {
    cudaStream_t s;
    cudaEvent_t fork, join;
    SideRes() {
        cudaStreamCreateWithFlags(&s, cudaStreamNonBlocking);
        cudaEventCreateWithFlags(&fork, cudaEventDisableTiming);
        cudaEventCreateWithFlags(&join, cudaEventDisableTiming);
    }
};
static SideRes g_sr;

// ---- tf32 helpers ----
__device__ __forceinline__ float to_tf32(float x) {
    float r;
    asm("cvt.rna.tf32.f32 %0, %1;" : "=f"(r) : "f"(x));
    return r;
}
__device__ __forceinline__ void mma_tf32(float c[4],
    uint32_t a0, uint32_t a1, uint32_t a2, uint32_t a3,
    uint32_t b0, uint32_t b1)
{
    asm volatile(
        "mma.sync.aligned.m16n8k8.row.col.f32.tf32.tf32.f32 "
        "{%0,%1,%2,%3},{%4,%5,%6,%7},{%8,%9},{%0,%1,%2,%3};\n"
        : "+f"(c[0]), "+f"(c[1]), "+f"(c[2]), "+f"(c[3])
        : "r"(a0), "r"(a1), "r"(a2), "r"(a3), "r"(b0), "r"(b1));
}
__device__ __forceinline__ uint32_t fbits(float x) { return __float_as_uint(x); }

// ============================ graph build ============================
__global__ void k_count(const int* __restrict__ dst) {
    int e = blockIdx.x*blockDim.x + threadIdx.x;
    if (e < EE) atomicAdd(&g_deg[dst[e]], 1);
}

__global__ __launch_bounds__(1024) void k_scanall() {   // SCANB blocks x 1024
    __shared__ int sh[1024];
    int t = threadIdx.x, b = blockIdx.x;
    int base = 0;
    for (int i = t; i < b*1024; i += 1024) base += g_deg[i];
    sh[t] = base; __syncthreads();
    #pragma unroll
    for (int st = 512; st > 0; st >>= 1) {
        if (t < st) sh[t] += sh[t+st];
        __syncthreads();
    }
    base = sh[0];
    __syncthreads();
    int i = b*1024 + t;
    int d = (i < NN) ? g_deg[i] : 0;
    sh[t] = d; __syncthreads();
    #pragma unroll
    for (int off = 1; off < 1024; off <<= 1) {
        int v = (t >= off) ? sh[t-off] : 0;
        __syncthreads();
        sh[t] += v;
        __syncthreads();
    }
    int excl = base + sh[t] - d;
    if (i < NN) { g_off[i] = excl; g_cur[i] = excl; }
    if (i == 0) g_off[NN] = EE;
}

__global__ void k_fill(const int* __restrict__ src, const int* __restrict__ dst) {
    int e = blockIdx.x*blockDim.x + threadIdx.x;
    if (e < EE) {
        int p = atomicAdd(&g_cur[dst[e]], 1);
        g_csrc[p] = src[e];
    }
}

// ============================ weight folding ============================
__global__ __launch_bounds__(256) void k_fold(
    const float* __restrict__ We1, const float* __restrict__ be1,
    const float* __restrict__ Wa1, const float* __restrict__ ba1,
    const float* __restrict__ attW)
{
    int b = blockIdx.x, t = threadIdx.x;
    if (b < 128) {
        __shared__ float sWe[128];
        if (t < 128) sWe[t] = We1[b*128 + t];
        __syncthreads();
        float acc = 0.f;
        #pragma unroll 8
        for (int k = 0; k < 128; k++) acc = fmaf(sWe[k], Wa1[k*256 + t], acc);
        g_Wcomb[b*256 + t] = acc;
    } else {
        __shared__ float ts[128], td[128], bc[256];
        if (t < 128) {
            float s1v = 0.f, s2v = 0.f;
            for (int c = 0; c < 256; c++) {
                float w = Wa1[t*256 + c];
                s1v = fmaf(w, attW[c], s1v);
                s2v = fmaf(w, attW[256 + c], s2v);
            }
            ts[t] = s1v; td[t] = s2v;
        }
        {
            float s = 0.f;
            for (int e = 0; e < 128; e++) s = fmaf(be1[e], Wa1[e*256 + t], s);
            bc[t] = s + ba1[t];
            g_bcomb[t] = bc[t];
        }
        __syncthreads();
        if (t < 128) {
            float u1 = 0.f, u2 = 0.f;
            for (int e = 0; e < 128; e++) {
                float w = We1[t*128 + e];
                u1 = fmaf(w, ts[e], u1);
                u2 = fmaf(w, td[e], u2);
            }
            g_us[t] = u1; g_ud[t] = u2;
        }
        if (t == 0) {
            float c1v = 0.f, c2v = 0.f;
            for (int c = 0; c < 256; c++) {
                c1v = fmaf(bc[c], attW[c], c1v);
                c2v = fmaf(bc[c], attW[256 + c], c2v);
            }
            g_cs[0] = c1v; g_cs[1] = c2v;
        }
    }
}

// ============================ zf = feature@Wf + bf : split-TF32 MMA ============================
__global__ __launch_bounds__(256) void k_gemm_zf(
    const float* __restrict__ A, const float* __restrict__ B,
    const float* __restrict__ bias, float* __restrict__ C)
{
    extern __shared__ float zs[];
    float* Ahi = zs;
    float* Alo = Ahi + 128*36;
    float* Bhi = Alo + 128*36;
    float* Blo = Bhi + 32*136;

    int tid = threadIdx.x;
    int w = tid >> 5, lane = tid & 31;
    int gid = lane >> 2, tid4 = lane & 3;
    int msub = (w >> 1) * 32, nsub = (w & 1) * 64;
    int row0 = blockIdx.x * 128;

    float acc[2][8][4];
    #pragma unroll
    for (int mf = 0; mf < 2; mf++)
        #pragma unroll
        for (int nf = 0; nf < 8; nf++)
            #pragma unroll
            for (int q = 0; q < 4; q++) acc[mf][nf][q] = 0.f;

    for (int k0 = 0; k0 < 128; k0 += 32) {
        {   // stage A: 128 x 32 (hi/lo split)
            int r = tid >> 1, cs = (tid & 1) * 16;
            int gr = row0 + r;
            #pragma unroll
            for (int i = 0; i < 4; i++) {
                float4 v = make_float4(0.f,0.f,0.f,0.f);
                if (gr < NN) v = *(const float4*)(A + (size_t)gr*128 + k0 + cs + i*4);
                float hx = to_tf32(v.x), hy = to_tf32(v.y), hz = to_tf32(v.z), hw = to_tf32(v.w);
                Ahi[r*36+cs+i*4+0] = hx; Alo[r*36+cs+i*4+0] = to_tf32(v.x - hx);
                Ahi[r*36+cs+i*4+1] = hy; Alo[r*36+cs+i*4+1] = to_tf32(v.y - hy);
                Ahi[r*36+cs+i*4+2] = hz; Alo[r*36+cs+i*4+2] = to_tf32(v.z - hz);
                Ahi[r*36+cs+i*4+3] = hw; Alo[r*36+cs+i*4+3] = to_tf32(v.w - hw);
            }
        }
        {   // stage B: 32 x 128 (hi/lo split)
            int r = tid >> 3, cs = (tid & 7) * 16;
            #pragma unroll
            for (int i = 0; i < 4; i++) {
                float4 v = *(const float4*)(B + (size_t)(k0+r)*128 + cs + i*4);
                float hx = to_tf32(v.x), hy = to_tf32(v.y), hz = to_tf32(v.z), hw = to_tf32(v.w);
                Bhi[r*136+cs+i*4+0] = hx; Blo[r*136+cs+i*4+0] = to_tf32(v.x - hx);
                Bhi[r*136+cs+i*4+1] = hy; Blo[r*136+cs+i*4+1] = to_tf32(v.y - hy);
                Bhi[r*136+cs+i*4+2] = hz; Blo[r*136+cs+i*4+2] = to_tf32(v.z - hz);
                Bhi[r*136+cs+i*4+3] = hw; Blo[r*136+cs+i*4+3] = to_tf32(v.w - hw);
            }
        }
        __syncthreads();
        #pragma unroll
        for (int kk = 0; kk < 4; kk++) {
            int kb = kk*8;
            uint32_t ah[2][4], al[2][4];
            #pragma unroll
            for (int mf = 0; mf < 2; mf++) {
                int m = msub + mf*16 + gid;
                ah[mf][0] = fbits(Ahi[m*36     + kb + tid4    ]);
                ah[mf][1] = fbits(Ahi[(m+8)*36 + kb + tid4    ]);
                ah[mf][2] = fbits(Ahi[m*36     + kb + tid4 + 4]);
                ah[mf][3] = fbits(Ahi[(m+8)*36 + kb + tid4 + 4]);
                al[mf][0] = fbits(Alo[m*36     + kb + tid4    ]);
                al[mf][1] = fbits(Alo[(m+8)*36 + kb + tid4    ]);
                al[mf][2] = fbits(Alo[m*36     + kb + tid4 + 4]);
                al[mf][3] = fbits(Alo[(m+8)*36 + kb + tid4 + 4]);
            }
            #pragma unroll
            for (int nf = 0; nf < 8; nf++) {
                int c = nsub + nf*8 + gid;
                uint32_t bh0 = fbits(Bhi[(kb+tid4)*136 + c]);
                uint32_t bh1 = fbits(Bhi[(kb+tid4+4)*136 + c]);
                uint32_t bl0 = fbits(Blo[(kb+tid4)*136 + c]);
                uint32_t bl1 = fbits(Blo[(kb+tid4+4)*136 + c]);
                #pragma unroll
                for (int mf = 0; mf < 2; mf++) {
                    mma_tf32(acc[mf][nf], ah[mf][0], ah[mf][1], ah[mf][2], ah[mf][3], bh0, bh1);
                    mma_tf32(acc[mf][nf], ah[mf][0], ah[mf][1], ah[mf][2], ah[mf][3], bl0, bl1);
                    mma_tf32(acc[mf][nf], al[mf][0], al[mf][1], al[mf][2], al[mf][3], bh0, bh1);
                }
            }
        }
        __syncthreads();
    }
    #pragma unroll
    for (int mf = 0; mf < 2; mf++) {
        int rlo = row0 + msub + mf*16 + gid;
        int rhi = rlo + 8;
        #pragma unroll
        for (int nf = 0; nf < 8; nf++) {
            int c0 = nsub + nf*8 + 2*tid4;
            float b0v = bias[c0], b1v = bias[c0+1];
            if (rlo < NN) {
                float2 o; o.x = acc[mf][nf][0]+b0v; o.y = acc[mf][nf][1]+b1v;
                *(float2*)(C + (size_t)rlo*128 + c0) = o;
            }
            if (rhi < NN) {
                float2 o; o.x = acc[mf][nf][2]+b0v; o.y = acc[mf][nf][3]+b1v;
                *(float2*)(C + (size_t)rhi*128 + c0) = o;
            }
        }
    }
}

// ============================ segment mean (4 nodes/warp, shfl-batched gathers) ============================
template<bool NORM, bool DOTS>
__global__ __launch_bounds__(256) void k_segmean(
    const float* __restrict__ zin, float* __restrict__ out)
{
    int warp = threadIdx.x >> 5, lane = threadIdx.x & 31;
    int node0 = (blockIdx.x*8 + warp) * 4;
    if (node0 >= NN) return;
    int offv = 0;
    if (lane < 5) offv = g_off[min(node0 + lane, NN)];
    const float* zl = zin + lane*4;
    float4 us4, ud4;
    if (DOTS) {
        us4 = *(const float4*)(g_us + lane*4);
        ud4 = *(const float4*)(g_ud + lane*4);
    }

    #pragma unroll
    for (int ni = 0; ni < 4; ni++) {
        int node = node0 + ni;
        if (node >= NN) break;
        int e0 = __shfl_sync(0xffffffffu, offv, ni);
        int e1 = __shfl_sync(0xffffffffu, offv, ni+1);
        float4 acc = make_float4(0.f,0.f,0.f,0.f);
        for (int base = e0; base < e1; base += 32) {
            int j = base + lane;
            int myidx = (j < e1) ? g_csrc[j] : 0;
            int cnt = min(32, e1 - base);
            int t = 0;
            for (; t + 4 <= cnt; t += 4) {
                int s0 = __shfl_sync(0xffffffffu, myidx, t);
                int s1i = __shfl_sync(0xffffffffu, myidx, t+1);
                int s2 = __shfl_sync(0xffffffffu, myidx, t+2);
                int s3 = __shfl_sync(0xffffffffu, myidx, t+3);
                float4 v0 = *(const float4*)(zl + (size_t)s0*DD);
                float4 v1 = *(const float4*)(zl + (size_t)s1i*DD);
                float4 v2 = *(const float4*)(zl + (size_t)s2*DD);
                float4 v3 = *(const float4*)(zl + (size_t)s3*DD);
                acc.x += (v0.x+v1.x) + (v2.x+v3.x);
                acc.y += (v0.y+v1.y) + (v2.y+v3.y);
                acc.z += (v0.z+v1.z) + (v2.z+v3.z);
                acc.w += (v0.w+v1.w) + (v2.w+v3.w);
            }
            for (; t < cnt; t++) {
                int sb = __shfl_sync(0xffffffffu, myidx, t);
                float4 v = *(const float4*)(zl + (size_t)sb*DD);
                acc.x += v.x; acc.y += v.y; acc.z += v.z; acc.w += v.w;
            }
        }
        float inv = 1.0f / (float)(e1 - e0);
        acc.x *= inv; acc.y *= inv; acc.z *= inv; acc.w *= inv;
        if (NORM) {
            float ss = acc.x*acc.x + acc.y*acc.y + acc.z*acc.z + acc.w*acc.w;
            #pragma unroll
            for (int o = 16; o > 0; o >>= 1) ss += __shfl_xor_sync(0xffffffffu, ss, o);
            float r = 1.0f / fmaxf(sqrtf(ss), 1e-12f);
            acc.x *= r; acc.y *= r; acc.z *= r; acc.w *= r;
        }
        *(float4*)(out + (size_t)node*DD + lane*4) = acc;
        if (DOTS) {
            float as = acc.x*us4.x + acc.y*us4.y + acc.z*us4.z + acc.w*us4.w;
            float ad = acc.x*ud4.x + acc.y*ud4.y + acc.z*ud4.z + acc.w*ud4.w;
            #pragma unroll
            for (int o = 16; o > 0; o >>= 1) {
                as += __shfl_xor_sync(0xffffffffu, as, o);
                ad += __shfl_xor_sync(0xffffffffu, ad, o);
            }
            if (lane == 0) { g_asrc[node] = as + g_cs[0]; g_adst[node] = ad + g_cs[1]; }
        }
    }
}

// ============================ GAT aggregation (4 nodes/warp, shfl-batched gathers) ============================
__global__ __launch_bounds__(256) void k_gatagg(const float* __restrict__ attb)
{
    int warp = threadIdx.x >> 5, lane = threadIdx.x & 31;
    int node0 = (blockIdx.x*8 + warp) * 4;
    if (node0 >= NN) return;
    int offv = 0;
    if (lane < 5) offv = g_off[min(node0 + lane, NN)];
    float adv = 0.f;
    if (lane < 4) adv = g_adst[min(node0 + lane, NN-1)];
    float attb0 = attb[0];
    const float* zl = g_m2 + lane*4;

    #pragma unroll
    for (int ni = 0; ni < 4; ni++) {
        int node = node0 + ni;
        if (node >= NN) break;
        int e0 = __shfl_sync(0xffffffffu, offv, ni);
        int e1 = __shfl_sync(0xffffffffu, offv, ni+1);
        float adb = __shfl_sync(0xffffffffu, adv, ni) + attb0;

        float mx = -FLT_MAX;
        for (int j = e0 + lane; j < e1; j += 32) {
            float e = g_asrc[g_csrc[j]] + adb;
            e = (e > 0.f) ? e : 0.01f*e;
            mx = fmaxf(mx, e);
        }
        #pragma unroll
        for (int o = 16; o > 0; o >>= 1) mx = fmaxf(mx, __shfl_xor_sync(0xffffffffu, mx, o));

        float4 acc = make_float4(0.f,0.f,0.f,0.f);
        float denom = 0.f;
        for (int base = e0; base < e1; base += 32) {
            int j = base + lane;
            int s = 0; float a = 0.f;
            if (j < e1) {
                s = g_csrc[j];
                float e = g_asrc[s] + adb;
                e = (e > 0.f) ? e : 0.01f*e;
                a = __expf(e - mx);
                denom += a;
            }
            int cnt = min(32, e1 - base);
            int t = 0;
            for (; t + 4 <= cnt; t += 4) {
                float a0 = __shfl_sync(0xffffffffu, a, t);
                float a1 = __shfl_sync(0xffffffffu, a, t+1);
                float a2 = __shfl_sync(0xffffffffu, a, t+2);
                float a3 = __shfl_sync(0xffffffffu, a, t+3);
                int   s0 = __shfl_sync(0xffffffffu, s, t);
                int   s1i = __shfl_sync(0xffffffffu, s, t+1);
                int   s2 = __shfl_sync(0xffffffffu, s, t+2);
                int   s3 = __shfl_sync(0xffffffffu, s, t+3);
                float4 v0 = *(const float4*)(zl + (size_t)s0*DD);
                float4 v1 = *(const float4*)(zl + (size_t)s1i*DD);
                float4 v2 = *(const float4*)(zl + (size_t)s2*DD);
                float4 v3 = *(const float4*)(zl + (size_t)s3*DD);
                acc.x = fmaf(a0, v0.x, fmaf(a1, v1.x, fmaf(a2, v2.x, fmaf(a3, v3.x, acc.x))));
                acc.y = fmaf(a0, v0.y, fmaf(a1, v1.y, fmaf(a2, v2.y, fmaf(a3, v3.y, acc.y))));
                acc.z = fmaf(a0, v0.z, fmaf(a1, v1.z, fmaf(a2, v2.z, fmaf(a3, v3.z, acc.z))));
                acc.w = fmaf(a0, v0.w, fmaf(a1, v1.w, fmaf(a2, v2.w, fmaf(a3, v3.w, acc.w))));
            }
            for (; t < cnt; t++) {
                float ab = __shfl_sync(0xffffffffu, a, t);
                int   sb = __shfl_sync(0xffffffffu, s, t);
                float4 v = *(const float4*)(zl + (size_t)sb*DD);
                acc.x = fmaf(ab, v.x, acc.x); acc.y = fmaf(ab, v.y, acc.y);
                acc.z = fmaf(ab, v.z, acc.z); acc.w = fmaf(ab, v.w, acc.w);
            }
        }
        #pragma unroll
        for (int o = 16; o > 0; o >>= 1) denom += __shfl_xor_sync(0xffffffffu, denom, o);
        float r = 1.0f / denom;
        acc.x *= r; acc.y *= r; acc.z *= r; acc.w *= r;
        *(float4*)(g_magg + (size_t)node*DD + lane*4) = acc;
    }
}

// ============================ FUSED: s1 = softmax(magg@Wcomb+bcomb); T += s1^T@m2 ============================
#define S1ATB_SMEM_FLOATS (128*264 + 32*264 + 32*136 + 32*132 + 256 + 256 + 256)
__global__ __launch_bounds__(512) void k_s1atb(float* __restrict__ s1out)
{
    extern __shared__ float sm[];
    float* Wc   = sm;                 // [k=128][n=264]
    float* Ssm  = Wc  + 128*264;      // [k=32][m=264]
    float* m2s  = Ssm + 32*264;       // [k=32][n=136]
    float* As   = m2s + 32*136;       // [m=32][k=132]
    float* bc   = As  + 32*132;       // [256]
    float* redm = bc  + 256;          // [32][8]
    float* reds = redm + 256;         // [32][8]

    int tid = threadIdx.x;
    int w = tid >> 5, lane = tid & 31;
    int gid = lane >> 2, tid4 = lane & 3;
    int chunk = blockIdx.x;
    int k_begin = (int)((long long)NN * chunk / SCHUNKS);
    int k_end   = (int)((long long)NN * (chunk+1) / SCHUNKS);

    int mhalf = (w >> 3) * 16, ncol0 = (w & 7) * 32;
    int msubT = (w >> 1) * 32, nsubT = (w & 1) * 64;

    {
        int r = tid >> 2, cs = (tid & 3) * 64;
        #pragma unroll
        for (int i = 0; i < 16; i++) {
            float4 v = *(const float4*)(g_Wcomb + (size_t)r*256 + cs + i*4);
            Wc[r*264+cs+i*4+0] = to_tf32(v.x); Wc[r*264+cs+i*4+1] = to_tf32(v.y);
            Wc[r*264+cs+i*4+2] = to_tf32(v.z); Wc[r*264+cs+i*4+3] = to_tf32(v.w);
        }
    }
    if (tid < 256) bc[tid] = g_bcomb[tid];

    float accT[2][8][4];
    #pragma unroll
    for (int mf = 0; mf < 2; mf++)
        #pragma unroll
        for (int nf = 0; nf < 8; nf++)
            #pragma unroll
            for (int q = 0; q < 4; q++) accT[mf][nf][q] = 0.f;
    float colacc = 0.f;

    __syncthreads();

    for (int s0 = k_begin; s0 < k_end; s0 += 32) {
        {
            int r = tid >> 4, cs = (tid & 15) * 8;
            int gk = s0 + r;
            float4 v0 = make_float4(0.f,0.f,0.f,0.f), v1 = v0, u0 = v0, u1 = v0;
            if (gk < k_end) {
                v0 = *(const float4*)(g_magg + (size_t)gk*128 + cs);
                v1 = *(const float4*)(g_magg + (size_t)gk*128 + cs + 4);
                u0 = *(const float4*)(g_m2   + (size_t)gk*128 + cs);
                u1 = *(const float4*)(g_m2   + (size_t)gk*128 + cs + 4);
            }
            As[r*132+cs+0] = to_tf32(v0.x); As[r*132+cs+1] = to_tf32(v0.y);
            As[r*132+cs+2] = to_tf32(v0.z); As[r*132+cs+3] = to_tf32(v0.w);
            As[r*132+cs+4] = to_tf32(v1.x); As[r*132+cs+5] = to_tf32(v1.y);
            As[r*132+cs+6] = to_tf32(v1.z); As[r*132+cs+7] = to_tf32(v1.w);
            m2s[r*136+cs+0] = to_tf32(u0.x); m2s[r*136+cs+1] = to_tf32(u0.y);
            m2s[r*136+cs+2] = to_tf32(u0.z); m2s[r*136+cs+3] = to_tf32(u0.w);
            m2s[r*136+cs+4] = to_tf32(u1.x); m2s[r*136+cs+5] = to_tf32(u1.y);
            m2s[r*136+cs+6] = to_tf32(u1.z); m2s[r*136+cs+7] = to_tf32(u1.w);
        }
        __syncthreads();

        float sacc[4][4];
        #pragma unroll
        for (int nf = 0; nf < 4; nf++)
            #pragma unroll
            for (int q = 0; q < 4; q++) sacc[nf][q] = 0.f;
        #pragma unroll
        for (int kk = 0; kk < 16; kk++) {
            int kb = kk*8;
            uint32_t a0 = fbits(As[(mhalf+gid)*132   + kb + tid4    ]);
            uint32_t a1 = fbits(As[(mhalf+gid+8)*132 + kb + tid4    ]);
            uint32_t a2 = fbits(As[(mhalf+gid)*132   + kb + tid4 + 4]);
            uint32_t a3 = fbits(As[(mhalf+gid+8)*132 + kb + tid4 + 4]);
            #pragma unroll
            for (int nf = 0; nf < 4; nf++) {
                int c = ncol0 + nf*8 + gid;
                uint32_t b0 = fbits(Wc[(kb+tid4)*264 + c]);
                uint32_t b1 = fbits(Wc[(kb+tid4+4)*264 + c]);
                mma_tf32(sacc[nf], a0, a1, a2, a3, b0, b1);
            }
        }
        #pragma unroll
        for (int nf = 0; nf < 4; nf++) {
            int c0 = ncol0 + nf*8 + 2*tid4;
            sacc[nf][0] += bc[c0];   sacc[nf][1] += bc[c0+1];
            sacc[nf][2] += bc[c0];   sacc[nf][3] += bc[c0+1];
        }
        {
            float mA = -FLT_MAX, mB = -FLT_MAX;
            #pragma unroll
            for (int nf = 0; nf < 4; nf++) {
                mA = fmaxf(mA, fmaxf(sacc[nf][0], sacc[nf][1]));
                mB = fmaxf(mB, fmaxf(sacc[nf][2], sacc[nf][3]));
            }
            mA = fmaxf(mA, __shfl_xor_sync(0xffffffffu, mA, 1));
            mA = fmaxf(mA, __shfl_xor_sync(0xffffffffu, mA, 2));
            mB = fmaxf(mB, __shfl_xor_sync(0xffffffffu, mB, 1));
            mB = fmaxf(mB, __shfl_xor_sync(0xffffffffu, mB, 2));
            if (tid4 == 0) {
                redm[(mhalf+gid)*8   + (w & 7)] = mA;
                redm[(mhalf+gid+8)*8 + (w & 7)] = mB;
            }
        }
        __syncthreads();
        float rmaxA = -FLT_MAX, rmaxB = -FLT_MAX;
        #pragma unroll
        for (int q = 0; q < 8; q++) {
            rmaxA = fmaxf(rmaxA, redm[(mhalf+gid)*8 + q]);
            rmaxB = fmaxf(rmaxB, redm[(mhalf+gid+8)*8 + q]);
        }
        {
            float sA = 0.f, sB = 0.f;
            #pragma unroll
            for (int nf = 0; nf < 4; nf++) {
                sacc[nf][0] = __expf(sacc[nf][0] - rmaxA);
                sacc[nf][1] = __expf(sacc[nf][1] - rmaxA);
                sacc[nf][2] = __expf(sacc[nf][2] - rmaxB);
                sacc[nf][3] = __expf(sacc[nf][3] - rmaxB);
                sA += sacc[nf][0] + sacc[nf][1];
                sB += sacc[nf][2] + sacc[nf][3];
            }
            sA += __shfl_xor_sync(0xffffffffu, sA, 1);
            sA += __shfl_xor_sync(0xffffffffu, sA, 2);
            sB += __shfl_xor_sync(0xffffffffu, sB, 1);
            sB += __shfl_xor_sync(0xffffffffu, sB, 2);
            if (tid4 == 0) {
                reds[(mhalf+gid)*8   + (w & 7)] = sA;
                reds[(mhalf+gid+8)*8 + (w & 7)] = sB;
            }
        }
        __syncthreads();
        {
            float ssA = 0.f, ssB = 0.f;
            #pragma unroll
            for (int q = 0; q < 8; q++) {
                ssA += reds[(mhalf+gid)*8 + q];
                ssB += reds[(mhalf+gid+8)*8 + q];
            }
            float rinvA = 1.0f / ssA, rinvB = 1.0f / ssB;
            int grA = s0 + mhalf + gid, grB = grA + 8;
            bool vA = (grA < k_end), vB = (grB < k_end);
            #pragma unroll
            for (int nf = 0; nf < 4; nf++) {
                int c0 = ncol0 + nf*8 + 2*tid4;
                float oA0 = vA ? sacc[nf][0]*rinvA : 0.f;
                float oA1 = vA ? sacc[nf][1]*rinvA : 0.f;
                float oB0 = vB ? sacc[nf][2]*rinvB : 0.f;
                float oB1 = vB ? sacc[nf][3]*rinvB : 0.f;
                Ssm[(mhalf+gid)*264 + c0]     = oA0;
                Ssm[(mhalf+gid)*264 + c0 + 1] = oA1;
                Ssm[(mhalf+gid+8)*264 + c0]     = oB0;
                Ssm[(mhalf+gid+8)*264 + c0 + 1] = oB1;
                if (vA) { float2 o; o.x = oA0; o.y = oA1; *(float2*)(s1out + (size_t)grA*256 + c0) = o; }
                if (vB) { float2 o; o.x = oB0; o.y = oB1; *(float2*)(s1out + (size_t)grB*256 + c0) = o; }
            }
        }
        __syncthreads();

        if (tid < 256) {
            #pragma unroll 8
            for (int r = 0; r < 32; r++) colacc += Ssm[r*264 + tid];
        }
        #pragma unroll
        for (int kk = 0; kk < 4; kk++) {
            int kb = kk*8;
            uint32_t a[2][4];
            #pragma unroll
            for (int mf = 0; mf < 2; mf++) {
                int m = msubT + mf*16 + gid;
                a[mf][0] = fbits(Ssm[(kb+tid4)*264   + m  ]);
                a[mf][1] = fbits(Ssm[(kb+tid4)*264   + m+8]);
                a[mf][2] = fbits(Ssm[(kb+tid4+4)*264 + m  ]);
                a[mf][3] = fbits(Ssm[(kb+tid4+4)*264 + m+8]);
            }
            #pragma unroll
            for (int nf = 0; nf < 8; nf++) {
                int c = nsubT + nf*8 + gid;
                uint32_t b0 = fbits(m2s[(kb+tid4)*136 + c]);
                uint32_t b1 = fbits(m2s[(kb+tid4+4)*136 + c]);
                mma_tf32(accT[0][nf], a[0][0], a[0][1], a[0][2], a[0][3], b0, b1);
                mma_tf32(accT[1][nf], a[1][0], a[1][1], a[1][2], a[1][3], b0, b1);
            }
        }
        __syncthreads();
    }

    float* P = g_part + (size_t)chunk * (CC1*DD);
    #pragma unroll
    for (int mf = 0; mf < 2; mf++) {
        int mloc = msubT + mf*16 + gid;
        #pragma unroll
        for (int nf = 0; nf < 8; nf++) {
            int c0 = nsubT + nf*8 + 2*tid4;
            float2 lo; lo.x = accT[mf][nf][0]; lo.y = accT[mf][nf][1];
            float2 hi; hi.x = accT[mf][nf][2]; hi.y = accT[mf][nf][3];
            *(float2*)(P + (size_t)mloc*128 + c0)     = lo;
            *(float2*)(P + (size_t)(mloc+8)*128 + c0) = hi;
        }
    }
    if (tid < 256) atomicAdd(&g_colsum[tid], colacc);
}

// ============================ x1 = T@We1 + colsum (x) be1 (reduce partials) ============================
__global__ __launch_bounds__(256) void k_x1(
    const float* __restrict__ We1, const float* __restrict__ be1,
    float* __restrict__ out)
{
    __shared__ float sT[2][128];
    int t = threadIdx.x;
    int rowsel = t >> 7;
    int d = t & 127;
    int k = blockIdx.x*2 + rowsel;
    float s = 0.f;
    #pragma unroll 4
    for (int c = 0; c < SCHUNKS; c++)
        s += g_part[(size_t)c*(CC1*DD) + (size_t)k*128 + d];
    sT[rowsel][d] = s;
    __syncthreads();
    if (t < 128) atomicAdd(&g_sumT[t], sT[0][t] + sT[1][t]);
    float colk = g_colsum[k];
    float acc = 0.f;
    #pragma unroll 8
    for (int e = 0; e < 128; e++) acc = fmaf(sT[rowsel][e], We1[e*128 + d], acc);
    out[OFF_X1 + k*128 + d] = acc + colk * be1[d];
}

// ============================ analytic coarse tail ============================
__global__ __launch_bounds__(256) void k_tail(
    const float* __restrict__ We1, const float* __restrict__ be1,
    const float* __restrict__ We2, const float* __restrict__ be2,
    const float* __restrict__ Wa2, const float* __restrict__ ba2,
    float* __restrict__ out)
{
    __shared__ float sumT[128];
    __shared__ float meanx1[128];
    __shared__ float meanvec[128];
    __shared__ float s2row[32];
    __shared__ float sc[256];
    int t = threadIdx.x;

    if (t < 128) sumT[t] = g_sumT[t];
    sc[t] = g_colsum[t];
    __syncthreads();
    #pragma unroll
    for (int st = 128; st > 0; st >>= 1) {
        if (t < st) sc[t] += sc[t+st];
        __syncthreads();
    }
    float sumcol = sc[0];
    if (t < 128) {
        float s = 0.f;
        for (int e = 0; e < 128; e++) s = fmaf(sumT[e], We1[e*128 + t], s);
        meanx1[t] = (s + sumcol*be1[t]) * (1.0f/256.0f);
    }
    __syncthreads();
    if (t < 128) {
        float s = 0.f;
        for (int e = 0; e < 128; e++) s = fmaf(meanx1[e], We2[e*128 + t], s);
        meanvec[t] = s + be2[t];
    }
    __syncthreads();
    if (t < 32) {
        float s = 0.f;
        for (int d = 0; d < 128; d++) s = fmaf(meanvec[d], Wa2[d*32 + t], s);
        float v = s + ba2[t];
        float mx = v;
        #pragma unroll
        for (int o = 16; o > 0; o >>= 1) mx = fmaxf(mx, __shfl_xor_sync(0xffffffffu, mx, o));
        float ex = __expf(v - mx);
        float sm = ex;
        #pragma unroll
        for (int o = 16; o > 0; o >>= 1) sm += __shfl_xor_sync(0xffffffffu, sm, o);
        s2row[t] = ex / sm;
    }
    __syncthreads();
    for (int i = t; i < 256*32; i += 256) out[OFF_S2 + i] = s2row[i & 31];
    if (t < 32) out[OFF_A1 + t] = 1.0f;
    for (int i = t; i < 32*128; i += 256)
        out[OFF_X2 + i] = 256.0f * s2row[i >> 7] * meanvec[i & 127];
    if (t == 0) {
        float s = 0.f;
        for (int d = 0; d < 128; d++) s += meanvec[d];
        out[OFF_E0] = s * (1.0f/16.0f);
    }
}

// ============================ launch ============================
extern "C" void kernel_launch(void* const* d_in, const int* in_sizes, int n_in,
                              void* d_out, int out_size)
{
    const float* feature = (const float*)d_in[0];
    const int*   eidx    = (const int*)d_in[1];
    const int*   src     = eidx;
    const int*   dst     = eidx + EE;
    const float* Wf   = (const float*)d_in[2];
    const float* bf   = (const float*)d_in[3];
    const float* We1  = (const float*)d_in[4];
    const float* be1  = (const float*)d_in[5];
    const float* Wa1  = (const float*)d_in[6];
    const float* ba1  = (const float*)d_in[7];
    const float* attW1 = (const float*)d_in[8];
    const float* attb1 = (const float*)d_in[9];
    const float* We2  = (const float*)d_in[10];
    const float* be2  = (const float*)d_in[11];
    const float* Wa2  = (const float*)d_in[12];
    const float* ba2  = (const float*)d_in[13];
    float* out = (float*)d_out;

    void *deg_p, *colsum_p, *sumT_p;
    float *zf_p, *m2_p;
    cudaGetSymbolAddress(&deg_p,    g_deg);
    cudaGetSymbolAddress(&colsum_p, g_colsum);
    cudaGetSymbolAddress(&sumT_p,   g_sumT);
    cudaGetSymbolAddress((void**)&zf_p, g_zf);
    cudaGetSymbolAddress((void**)&m2_p, g_m2);

    const int zf_smem = (128*36*2 + 32*136*2) * 4;         // 71680 B
    const int s1atb_smem = S1ATB_SMEM_FLOATS * 4;          // 206336 B
    cudaFuncSetAttribute(k_gemm_zf, cudaFuncAttributeMaxDynamicSharedMemorySize, zf_smem);
    cudaFuncSetAttribute(k_s1atb,  cudaFuncAttributeMaxDynamicSharedMemorySize, s1atb_smem);

    cudaStream_t side = g_sr.s;

    // ---- fork: side stream does dense prep (independent of the graph) ----
    cudaEventRecord(g_sr.fork, 0);
    cudaStreamWaitEvent(side, g_sr.fork, 0);
    cudaMemsetAsync(colsum_p, 0, CC1*sizeof(float), side);
    cudaMemsetAsync(sumT_p,   0, DD*sizeof(float), side);
    k_gemm_zf<<<(NN+127)/128, 256, zf_smem, side>>>(feature, Wf, bf, zf_p);
    k_fold<<<129, 256, 0, side>>>(We1, be1, Wa1, ba1, attW1);
    cudaEventRecord(g_sr.join, side);

    // ---- main stream: graph build ----
    cudaMemsetAsync(deg_p, 0, NN*sizeof(int));
    k_count<<<(EE + 255)/256, 256>>>(dst);
    k_scanall<<<SCANB, 1024>>>();
    k_fill<<<(EE + 255)/256, 256>>>(src, dst);

    // ---- join, then serial chain ----
    cudaStreamWaitEvent(0, g_sr.join, 0);

    // embed3 = x = normalize(segmean(zf))  (written straight to d_out)
    k_segmean<true,false><<<(NN+31)/32, 256>>>(zf_p, out + OFF_E3);
    // m2 = segmean(x) + fused a_src/a_dst  (reads embed3 from d_out)
    k_segmean<false,true><<<(NN+31)/32, 256>>>(out + OFF_E3, m2_p);
    // GAT aggregation on 128-wide m2
    k_gatagg<<<(NN+31)/32, 256>>>(attb1);
    // FUSED: s1 softmax GEMM + T partials (148 blocks, 1/SM)
    k_s1atb<<<SCHUNKS, 512, s1atb_smem>>>(out + OFF_S1);
    // x1 = T@We1 + colsum (x) be1 (+ sumT accumulation)
    k_x1<<<128, 256>>>(We1, be1, out);
    // analytic coarse level
    k_tail<<<1, 256>>>(We1, be1, We2, be2, Wa2, ba2, out);
}